// round 1
// baseline (speedup 1.0000x reference)
#include <cuda_runtime.h>
#include <cuda_bf16.h>

// ---------------------------------------------------------------------------
// GSPN block, fp32 baseline. B=4, T=1024, D=768, HW=32, DS=48, CHUNK=8.
// ---------------------------------------------------------------------------

#define Bsz   4
#define Dch   768
#define Tlen  1024
#define DS    48
#define NPIX  1024           // 32*32
#define C4    (4*Dch)        // 3072
#define MGATE (6*C4)         // 18432 rows: [Gl;Gm;Gr;L;U;D]
#define BTD   (Bsz*Tlen*Dch) // 3145728

// ------------------------- static scratch (no allocs) ----------------------
__device__ float g_xln [Bsz*Dch*NPIX];
__device__ float g_x1  [Bsz*Dch*NPIX];
__device__ float g_x2  [Bsz*Dch*NPIX];
__device__ float g_x2t [Bsz*Dch*NPIX];
__device__ float g_xp  [Bsz*DS*NPIX];
__device__ float g_xpt [Bsz*DS*NPIX];
__device__ float g_gate[(size_t)Bsz*MGATE*NPIX];   // 302 MB
__device__ float g_s4  [Bsz*C4*NPIX];
__device__ float g_mrg [Bsz*Dch*NPIX];
__device__ float g_oc  [Bsz*Dch*NPIX];
__device__ float g_act [Bsz*Dch*NPIX];

// ------------------------------ helpers ------------------------------------
__device__ __forceinline__ float fast_exp(float x) {
    // e^x, FMA-only (no MUFU). Clamp for safety.
    x = fminf(fmaxf(x, -20.f), 20.f);
    float t = x * 1.4426950408889634f;          // log2(e)
    float r = t + 12582912.f;                   // 1.5*2^23, round-to-nearest
    int   i = __float_as_int(r) - 0x4B400000;   // integer part
    float f = t - (r - 12582912.f);             // frac in [-0.5,0.5]
    const float c1=0.69314718056f, c2=0.2402265069f, c3=0.0555041087f,
                c4=0.00961812911f, c5=0.00133335581f;
    float p = fmaf(c5, f, c4);
    p = fmaf(p, f, c3); p = fmaf(p, f, c2); p = fmaf(p, f, c1); p = fmaf(p, f, 1.f);
    return __int_as_float(__float_as_int(p) + (i << 23));
}

__device__ __forceinline__ float fast_rcp(float x) {
    // 1/x for positive normal x, FMA-only Newton.
    float y = __int_as_float(0x7EF311C3 - __float_as_int(x));
    y = y * (2.0f - x * y);
    y = y * (2.0f - x * y);
    y = y * (2.0f - x * y);
    return y;
}

// ------------------------------ LayerNorm + transpose ----------------------
// in: (B*T, 768) row-major. out: (B, 768, 1024) channel-major (h-major pixels).
__global__ void ln_kernel(const float* __restrict__ xin,
                          const float* __restrict__ w,
                          const float* __restrict__ bsh,
                          float* __restrict__ out) {
    __shared__ float mu_s[32], rs_s[32];
    __shared__ float tile[32][33];
    int block_t0 = blockIdx.x * 32;      // global row base (within B*T=4096)
    int lane = threadIdx.x, wy = threadIdx.y;
    const float* row = xin + (size_t)(block_t0 + wy) * Dch;
    float s = 0.f, s2 = 0.f;
    for (int d = lane; d < Dch; d += 32) { float v = row[d]; s += v; s2 += v*v; }
    #pragma unroll
    for (int o = 16; o; o >>= 1) {
        s  += __shfl_xor_sync(0xFFFFFFFFu, s,  o);
        s2 += __shfl_xor_sync(0xFFFFFFFFu, s2, o);
    }
    float mu  = s * (1.f/Dch);
    float var = s2 * (1.f/Dch) - mu*mu;
    float rs  = rsqrtf(var + 1e-5f);
    if (lane == 0) { mu_s[wy] = mu; rs_s[wy] = rs; }
    __syncthreads();
    int b  = block_t0 >> 10;
    int t0 = block_t0 & 1023;
    for (int d0 = 0; d0 < Dch; d0 += 32) {
        float v = xin[(size_t)(block_t0 + wy)*Dch + d0 + lane];
        v = (v - mu_s[wy]) * rs_s[wy] * w[d0+lane] + bsh[d0+lane];
        tile[lane][wy] = v;
        __syncthreads();
        out[((size_t)b*Dch + d0 + wy)*NPIX + t0 + lane] = tile[wy][lane];
        __syncthreads();
    }
}

// ------------------------------ SGEMM --------------------------------------
// C[b] = W(MxK) @ X[b](KxN).  BM=128, BN=64, TK=8, 256 threads, 8x4 micro.
// TRANSC=1 stores C transposed: Ct[n*M+m].
template<int TRANSC>
__global__ __launch_bounds__(256)
void sgemm_kernel(const float* __restrict__ W, const float* __restrict__ X,
                  float* __restrict__ C, int M, int N, int K,
                  size_t strideX, size_t strideC) {
    __shared__ float As[8][128];
    __shared__ float Bs[8][64];
    const float* Xb = X + (size_t)blockIdx.z * strideX;
    float*       Cb = C + (size_t)blockIdx.z * strideC;
    int bm = blockIdx.y * 128, bn = blockIdx.x * 64;
    int tid = threadIdx.x;
    int arow = tid >> 1;            // 0..127
    int acol = (tid & 1) * 4;       // 0 or 4
    int brow = tid >> 5;            // 0..7
    int bcol = tid & 31;            // 0..31
    int tm = (tid >> 4) * 8;        // row micro-offset
    int tn = (tid & 15) * 4;        // col micro-offset
    float acc[8][4];
    #pragma unroll
    for (int i = 0; i < 8; i++)
        #pragma unroll
        for (int j = 0; j < 4; j++) acc[i][j] = 0.f;

    for (int k0 = 0; k0 < K; k0 += 8) {
        float4 av = make_float4(0.f,0.f,0.f,0.f);
        if (bm + arow < M)
            av = *(const float4*)(W + (size_t)(bm + arow)*K + k0 + acol);
        As[acol+0][arow] = av.x; As[acol+1][arow] = av.y;
        As[acol+2][arow] = av.z; As[acol+3][arow] = av.w;
        Bs[brow][bcol]      = Xb[(size_t)(k0+brow)*N + bn + bcol];
        Bs[brow][bcol+32]   = Xb[(size_t)(k0+brow)*N + bn + bcol + 32];
        __syncthreads();
        #pragma unroll
        for (int kk = 0; kk < 8; kk++) {
            float a[8], bb[4];
            *(float4*)(a)   = *(const float4*)&As[kk][tm];
            *(float4*)(a+4) = *(const float4*)&As[kk][tm+4];
            *(float4*)(bb)  = *(const float4*)&Bs[kk][tn];
            #pragma unroll
            for (int i = 0; i < 8; i++)
                #pragma unroll
                for (int j = 0; j < 4; j++)
                    acc[i][j] = fmaf(a[i], bb[j], acc[i][j]);
        }
        __syncthreads();
    }
    if (!TRANSC) {
        #pragma unroll
        for (int i = 0; i < 8; i++) {
            int row = bm + tm + i;
            if (row < M) {
                float4 v = make_float4(acc[i][0], acc[i][1], acc[i][2], acc[i][3]);
                *(float4*)(Cb + (size_t)row*N + bn + tn) = v;
            }
        }
    } else {
        #pragma unroll
        for (int j = 0; j < 4; j++) {
            int col = bn + tn + j;
            float4 v0 = make_float4(acc[0][j], acc[1][j], acc[2][j], acc[3][j]);
            float4 v1 = make_float4(acc[4][j], acc[5][j], acc[6][j], acc[7][j]);
            *(float4*)(Cb + (size_t)col*M + bm + tm)     = v0;
            *(float4*)(Cb + (size_t)col*M + bm + tm + 4) = v1;
        }
    }
}

// ------------------------------ depthwise convs -----------------------------
__global__ void dw7_kernel(const float* __restrict__ in, const float* __restrict__ wt,
                           const float* __restrict__ bias, float* __restrict__ out) {
    int d = blockIdx.x, b = blockIdx.y;
    __shared__ float sm[38][38];
    __shared__ float wsm[49];
    const float* plane = in + ((size_t)b*Dch + d)*NPIX;
    int tid = threadIdx.x;
    if (tid < 49) wsm[tid] = wt[d*49 + tid];
    for (int i = tid; i < 38*38; i += 256) {
        int y = i/38 - 3, x = i%38 - 3;
        sm[i/38][i%38] = (y>=0 && y<32 && x>=0 && x<32) ? plane[y*32+x] : 0.f;
    }
    __syncthreads();
    float bv = bias[d];
    for (int p = tid; p < 1024; p += 256) {
        int y = p >> 5, x = p & 31;
        float acc = bv;
        #pragma unroll
        for (int ky = 0; ky < 7; ky++)
            #pragma unroll
            for (int kx = 0; kx < 7; kx++)
                acc = fmaf(sm[y+ky][x+kx], wsm[ky*7+kx], acc);
        out[((size_t)b*Dch + d)*NPIX + p] = acc;
    }
}

// 3x3 dw, no bias, fused y*relu(y)
__global__ void dw3act_kernel(const float* __restrict__ in, const float* __restrict__ wt,
                              float* __restrict__ out) {
    int d = blockIdx.x, b = blockIdx.y;
    __shared__ float sm[34][34];
    __shared__ float wsm[9];
    const float* plane = in + ((size_t)b*Dch + d)*NPIX;
    int tid = threadIdx.x;
    if (tid < 9) wsm[tid] = wt[d*9 + tid];
    for (int i = tid; i < 34*34; i += 256) {
        int y = i/34 - 1, x = i%34 - 1;
        sm[i/34][i%34] = (y>=0 && y<32 && x>=0 && x<32) ? plane[y*32+x] : 0.f;
    }
    __syncthreads();
    for (int p = tid; p < 1024; p += 256) {
        int y = p >> 5, x = p & 31;
        float acc = 0.f;
        #pragma unroll
        for (int ky = 0; ky < 3; ky++)
            #pragma unroll
            for (int kx = 0; kx < 3; kx++)
                acc = fmaf(sm[y+ky][x+kx], wsm[ky*3+kx], acc);
        float z = (acc > 0.f) ? acc*acc : 0.f;
        out[((size_t)b*Dch + d)*NPIX + p] = z;
    }
}

// ------------------------------ 32x32 per-plane transpose ------------------
// out[w*32+h] = in[h*32+w]; plane = blockIdx.x
__global__ void transpose32_kernel(const float* __restrict__ in, float* __restrict__ out) {
    __shared__ float sm[32][33];
    size_t base = (size_t)blockIdx.x * NPIX;
    int tx = threadIdx.x, ty = threadIdx.y;
    sm[ty][tx] = in[base + ty*32 + tx];
    __syncthreads();
    out[base + ty*32 + tx] = sm[tx][ty];
}

// ------------------------------ scan ---------------------------------------
// grid (C4, B), block 128 (4 warps = 4 chunks; lane = h).
// gate planes are w-major (q = w*32+h). Writes s4 (w-major), m_w[k] folded in.
__global__ void scan_kernel(const float* __restrict__ gate,
                            const float* __restrict__ x2,
                            const float* __restrict__ x2t,
                            const float* __restrict__ mw,
                            float* __restrict__ s4) {
    int c4 = blockIdx.x, b = blockIdx.y;
    int k = c4 / Dch, d = c4 - k*Dch;
    int tid = threadIdx.x;
    int chunk = tid >> 5, h = tid & 31;
    size_t gb = ((size_t)b*MGATE + c4) * NPIX;
    const float* Gl = gate + gb;
    const float* Gm = Gl + (size_t)1*C4*NPIX;
    const float* Gr = Gl + (size_t)2*C4*NPIX;
    const float* Lp = Gl + (size_t)3*C4*NPIX;
    const float* Up = Gl + (size_t)4*C4*NPIX;
    const float* Dp = Gl + (size_t)5*C4*NPIX;
    const float* xsrc = ((k & 1) ? x2 : x2t) + ((size_t)b*Dch + d)*NPIX;
    float mk = mw[k];
    float* outp = s4 + ((size_t)b*C4 + c4)*NPIX;
    float hs = 0.f;
    const unsigned mask = 0xFFFFFFFFu;
    #pragma unroll
    for (int pos = 0; pos < 8; pos++) {
        int w  = chunk*8 + pos;
        int q  = w*32 + h;
        int wq = (k >= 2) ? (31 - w) : w;
        float xv = xsrc[wq*32 + h];
        float a  = Gl[q], bb = Gm[q], cc = Gr[q], l = Lp[q];
        float ea = fast_exp(a), eb = fast_exp(bb), ec = fast_exp(cc);
        float qa = 1.f + ea, qb = 1.f + eb, qc = 1.f + ec;
        float pl = ea*qb*qc, pm = eb*qa*qc, pr = ec*qa*qb;
        float den = pl + pm + pr;
        if (h == 0)  den = pm + pr;
        if (h == 31) den = pl + pm;
        float rd = fast_rcp(den);
        float gl = pl*rd, gm = pm*rd, gr = pr*rd;
        float up = __shfl_up_sync(mask, hs, 1);
        float dn = __shfl_down_sync(mask, hs, 1);
        if (h == 0)  up = 0.f;
        if (h == 31) dn = 0.f;
        hs = fmaf(l, xv, fmaf(gl, up, fmaf(gm, hs, gr*dn)));
        float Uv = Up[q], Dv = Dp[q];
        outp[q] = mk * fmaf(hs, Uv, xv*Dv);
    }
}

// ------------------------------ merge (sum 4 dirs, w-major -> h-major) -----
__global__ void merge_kernel(const float* __restrict__ s4, float* __restrict__ out) {
    __shared__ float sm[32][33];
    int d = blockIdx.x, b = blockIdx.y;
    int tx = threadIdx.x, ty = threadIdx.y;
    int q = ty*32 + tx;                         // w=ty, h=tx
    float v = 0.f;
    #pragma unroll
    for (int k = 0; k < 4; k++)
        v += s4[((size_t)b*C4 + k*Dch + d)*NPIX + q];
    sm[ty][tx] = v;                             // sm[w][h]
    __syncthreads();
    out[((size_t)b*Dch + d)*NPIX + ty*32 + tx] = sm[tx][ty];  // h=ty, w=tx
}

// ------------------------------ launch -------------------------------------
extern "C" void kernel_launch(void* const* d_in, const int* in_sizes, int n_in,
                              void* d_out, int out_size) {
    const float* hidden   = (const float*)d_in[0];
    const float* norm_w   = (const float*)d_in[1];
    const float* norm_b   = (const float*)d_in[2];
    const float* in_proj  = (const float*)d_in[3];
    const float* conv7_w  = (const float*)d_in[4];
    const float* conv7_b  = (const float*)d_in[5];
    const float* xdown_w  = (const float*)d_in[6];
    const float* wup_w    = (const float*)d_in[7];
    const float* lup_w    = (const float*)d_in[8];
    const float* uup_w    = (const float*)d_in[9];
    const float* dcoef_w  = (const float*)d_in[10];
    const float* m_w      = (const float*)d_in[11];
    const float* outconv_w  = (const float*)d_in[12];
    const float* outdconv_w = (const float*)d_in[13];
    const float* outproj_w  = (const float*)d_in[14];
    float* outp = (float*)d_out;

    float *xln, *x1, *x2, *x2t, *xp, *xpt, *gatep, *s4, *mrg, *oc, *act;
    cudaGetSymbolAddress((void**)&xln,  g_xln);
    cudaGetSymbolAddress((void**)&x1,   g_x1);
    cudaGetSymbolAddress((void**)&x2,   g_x2);
    cudaGetSymbolAddress((void**)&x2t,  g_x2t);
    cudaGetSymbolAddress((void**)&xp,   g_xp);
    cudaGetSymbolAddress((void**)&xpt,  g_xpt);
    cudaGetSymbolAddress((void**)&gatep,g_gate);
    cudaGetSymbolAddress((void**)&s4,   g_s4);
    cudaGetSymbolAddress((void**)&mrg,  g_mrg);
    cudaGetSymbolAddress((void**)&oc,   g_oc);
    cudaGetSymbolAddress((void**)&act,  g_act);

    dim3 b3232(32, 32);

    // 1) LayerNorm + transpose -> (B,768,1024)
    ln_kernel<<<Bsz*Tlen/32, b3232>>>(hidden, norm_w, norm_b, xln);

    // 2) in_proj: x1 = W(768x768) @ xln
    sgemm_kernel<0><<<dim3(NPIX/64, Dch/128, Bsz), 256>>>(
        in_proj, xln, x1, Dch, NPIX, Dch, (size_t)Dch*NPIX, (size_t)Dch*NPIX);

    // 3) depthwise 7x7 + bias -> x2
    dw7_kernel<<<dim3(Dch, Bsz), 256>>>(x1, conv7_w, conv7_b, x2);

    // 4) transposed copy of x2 (w-major pixels)
    transpose32_kernel<<<Bsz*Dch, b3232>>>(x2, x2t);

    // 5) xdown: xp = W(48x768) @ x2
    sgemm_kernel<0><<<dim3(NPIX/64, 1, Bsz), 256>>>(
        xdown_w, x2, xp, DS, NPIX, Dch, (size_t)Dch*NPIX, (size_t)DS*NPIX);

    // 6) xp -> w-major pixel order
    transpose32_kernel<<<Bsz*DS, b3232>>>(xp, xpt);

    // 7) gate/L/U/D projections, K=48, N w-major. Row sections of g_gate:
    //    [0:9216)=wup(Gl,Gm,Gr), [9216:12288)=L, [12288:15360)=U, [15360:18432)=D
    sgemm_kernel<0><<<dim3(NPIX/64, (3*C4)/128, Bsz), 256>>>(
        wup_w,   xpt, gatep,                       3*C4, NPIX, DS,
        (size_t)DS*NPIX, (size_t)MGATE*NPIX);
    sgemm_kernel<0><<<dim3(NPIX/64, C4/128, Bsz), 256>>>(
        lup_w,   xpt, gatep + (size_t)3*C4*NPIX,   C4,   NPIX, DS,
        (size_t)DS*NPIX, (size_t)MGATE*NPIX);
    sgemm_kernel<0><<<dim3(NPIX/64, C4/128, Bsz), 256>>>(
        uup_w,   xpt, gatep + (size_t)4*C4*NPIX,   C4,   NPIX, DS,
        (size_t)DS*NPIX, (size_t)MGATE*NPIX);
    sgemm_kernel<0><<<dim3(NPIX/64, C4/128, Bsz), 256>>>(
        dcoef_w, xpt, gatep + (size_t)5*C4*NPIX,   C4,   NPIX, DS,
        (size_t)DS*NPIX, (size_t)MGATE*NPIX);

    // 8) 4-direction chunked tridiagonal scan + U/D epilogue + m_w fold
    scan_kernel<<<dim3(C4, Bsz), 128>>>(gatep, x2, x2t, m_w, s4);

    // 9) merge directions, w-major -> h-major
    merge_kernel<<<dim3(Dch, Bsz), b3232>>>(s4, mrg);

    // 10) outconv (768x768)
    sgemm_kernel<0><<<dim3(NPIX/64, Dch/128, Bsz), 256>>>(
        outconv_w, mrg, oc, Dch, NPIX, Dch, (size_t)Dch*NPIX, (size_t)Dch*NPIX);

    // 11) depthwise 3x3 + y*relu(y)
    dw3act_kernel<<<dim3(Dch, Bsz), 256>>>(oc, outdconv_w, act);

    // 12) outproj with transposed store -> (B, T, D) directly into d_out
    sgemm_kernel<1><<<dim3(NPIX/64, Dch/128, Bsz), 256>>>(
        outproj_w, act, outp, Dch, NPIX, Dch, (size_t)Dch*NPIX, (size_t)Tlen*Dch);

    // 13) shortcut copy (second output)
    cudaMemcpyAsync(outp + BTD, hidden, (size_t)BTD*sizeof(float),
                    cudaMemcpyDeviceToDevice);
}

// round 3
// speedup vs baseline: 1.2868x; 1.2868x over previous
#include <cuda_runtime.h>
#include <cuda_bf16.h>
#include <cstdint>

// ---------------------------------------------------------------------------
// GSPN block. B=4, T=1024, D=768, HW=32, DS=48, CHUNK=8.
// Round 3: GEMMs on baseline-PTX HMMA (mma.sync bf16 hi/lo 3-pass, fp32 acc).
// ---------------------------------------------------------------------------

#define Bsz   4
#define Dch   768
#define Tlen  1024
#define DS    48
#define NPIX  1024
#define NTOT  4096            // Bsz*NPIX columns
#define C4    (4*Dch)         // 3072
#define MG    (6*C4)          // 18432 gate rows
#define BTD   (Bsz*Tlen*Dch)

// ------------------------- static scratch (no allocs) ----------------------
__device__ float g_x1 [(size_t)Dch*NTOT];
__device__ float g_x2 [(size_t)Dch*NTOT];
__device__ float g_x2t[(size_t)Dch*NTOT];
__device__ float g_xp [(size_t)DS*NTOT];
__device__ float g_gate[(size_t)MG*NTOT];       // 302 MB fp32
__device__ float g_s4 [(size_t)C4*NTOT];
__device__ float g_mrg[(size_t)Dch*NTOT];
__device__ float g_oc [(size_t)Dch*NTOT];
__device__ float g_act[(size_t)Dch*NTOT];

__device__ __align__(16) __nv_bfloat16 g_xlnh[(size_t)NTOT*Dch], g_xlnl[(size_t)NTOT*Dch];
__device__ __align__(16) __nv_bfloat16 g_wih [Dch*Dch], g_wil [Dch*Dch];
__device__ __align__(16) __nv_bfloat16 g_woh [Dch*Dch], g_wol [Dch*Dch];
__device__ __align__(16) __nv_bfloat16 g_wph [Dch*Dch], g_wpl [Dch*Dch];
__device__ __align__(16) __nv_bfloat16 g_gwh [(size_t)MG*64], g_gwl [(size_t)MG*64];
__device__ __align__(16) __nv_bfloat16 g_xpnh[(size_t)NTOT*64], g_xpnl[(size_t)NTOT*64];
__device__ __align__(16) __nv_bfloat16 g_mnh [(size_t)NTOT*Dch], g_mnl [(size_t)NTOT*Dch];
__device__ __align__(16) __nv_bfloat16 g_anh [(size_t)NTOT*Dch], g_anl [(size_t)NTOT*Dch];

// ------------------------------ helpers ------------------------------------
__device__ __forceinline__ uint32_t smem_u32(const void* p) {
    uint32_t r;
    asm("{ .reg .u64 t; cvta.to.shared.u64 t, %1; cvt.u32.u64 %0, t; }"
        : "=r"(r) : "l"(p));
    return r;
}
#define SW128(x) ((x) ^ (((x) >> 3) & 0x70))

__device__ __forceinline__ void cp16(uint32_t saddr, const void* gptr) {
    asm volatile("cp.async.cg.shared.global [%0], [%1], 16;"
        :: "r"(saddr), "l"(gptr));
}
__device__ __forceinline__ void cp_commit() {
    asm volatile("cp.async.commit_group;" ::: "memory");
}
template<int N>
__device__ __forceinline__ void cp_wait() {
    asm volatile("cp.async.wait_group %0;" :: "n"(N) : "memory");
}
__device__ __forceinline__ void ldm4(uint32_t& r0, uint32_t& r1, uint32_t& r2,
                                     uint32_t& r3, uint32_t addr) {
    asm volatile("ldmatrix.sync.aligned.m8n8.x4.shared.b16 {%0,%1,%2,%3}, [%4];"
        : "=r"(r0), "=r"(r1), "=r"(r2), "=r"(r3) : "r"(addr));
}
__device__ __forceinline__ void mma16816(float* c, const uint32_t* a,
                                         const uint32_t* b) {
    asm volatile("mma.sync.aligned.m16n8k16.row.col.f32.bf16.bf16.f32 "
        "{%0,%1,%2,%3}, {%4,%5,%6,%7}, {%8,%9}, {%0,%1,%2,%3};"
        : "+f"(c[0]), "+f"(c[1]), "+f"(c[2]), "+f"(c[3])
        : "r"(a[0]), "r"(a[1]), "r"(a[2]), "r"(a[3]), "r"(b[0]), "r"(b[1]));
}

__device__ __forceinline__ float fast_exp(float x) {
    x = fminf(fmaxf(x, -20.f), 20.f);
    float t = x * 1.4426950408889634f;
    float r = t + 12582912.f;
    int   i = __float_as_int(r) - 0x4B400000;
    float f = t - (r - 12582912.f);
    const float c1=0.69314718056f, c2=0.2402265069f, c3=0.0555041087f,
                c4=0.00961812911f, c5=0.00133335581f;
    float p = fmaf(c5, f, c4);
    p = fmaf(p, f, c3); p = fmaf(p, f, c2); p = fmaf(p, f, c1); p = fmaf(p, f, 1.f);
    return __int_as_float(__float_as_int(p) + (i << 23));
}
__device__ __forceinline__ float fast_rcp(float x) {
    float y = __int_as_float(0x7EF311C3 - __float_as_int(x));
    y = y * (2.0f - x * y);
    y = y * (2.0f - x * y);
    y = y * (2.0f - x * y);
    return y;
}

// ------------------------------ HMMA GEMM ----------------------------------
// C(MxN fp32, ld=ldc) = (Ahi+Alo)(MxKp) @ (Bhi+Blo)(NxKp)^T, bf16 K-major,
// 3-pass hi/lo. M,N multiples of 128; Kp multiple of 64.
// CTA: 128x128 tile, 256 thr (8 warps, 2m x 4n, warp tile 64x32). BK=64.
// SMEM stage: Ahi|Alo|Bhi|Blo, 16KB each, SW128-swizzled rows of 128B.
#define STAGE_BYTES 65536
__global__ __launch_bounds__(256, 1)
void mma_gemm(const __nv_bfloat16* __restrict__ Ahi, const __nv_bfloat16* __restrict__ Alo,
              const __nv_bfloat16* __restrict__ Bhi, const __nv_bfloat16* __restrict__ Blo,
              float* __restrict__ C, int Kp, int ldc) {
    extern __shared__ __align__(16) char dsm[];
    const int tid  = threadIdx.x;
    const int wid  = tid >> 5, lane = tid & 31;
    const int wm   = (wid >> 2) << 6;      // warp m offset (0,64)
    const int wn   = (wid & 3)  << 5;      // warp n offset (0,32,64,96)
    const int bm   = blockIdx.y << 7, bn = blockIdx.x << 7;
    const uint32_t sbase = smem_u32(dsm);
    const int NKB = Kp >> 6;

    // cp.async addressing: per plane, 1024 chunks of 16B; 4 chunks/thread.
    const int crow0 = tid >> 1;            // rows 0..127 (2 thr per row)
    const int cslot0 = (tid & 1) << 2;     // 16B slots 0..3 / 4..7

    auto load_stage = [&](int buf, int kb) {
        const int k0 = kb << 6;
        const __nv_bfloat16* srcs[4] = {Ahi, Alo, Bhi, Blo};
        const int rb[4] = {bm, bm, bn, bn};
        uint32_t sb = sbase + buf * STAGE_BYTES;
        #pragma unroll
        for (int pl = 0; pl < 4; pl++) {
            const __nv_bfloat16* src = srcs[pl] + (size_t)(rb[pl] + crow0) * Kp + k0;
            uint32_t pbase = sb + (pl << 14) + (crow0 << 7);
            #pragma unroll
            for (int s = 0; s < 4; s++) {
                uint32_t bo = (cslot0 + s) << 4;  // within-row byte offset
                cp16(pbase + (bo ^ ((crow0 & 7) << 4)), src + ((cslot0 + s) << 3));
            }
        }
        cp_commit();
    };

    float acc[4][4][4];
    #pragma unroll
    for (int i = 0; i < 4; i++)
        #pragma unroll
        for (int j = 0; j < 4; j++)
            #pragma unroll
            for (int q = 0; q < 4; q++) acc[i][j][q] = 0.f;

    // ldmatrix lane mapping (x4): mi = lane>>3, row = (lane&7) + ((mi&1)<<3),
    // kchunk = mi>>1 (16B units)
    const int lrow = (lane & 7) + (((lane >> 3) & 1) << 3);
    const int lkof = ((lane >> 4) & 1) << 4;   // byte offset of k-chunk

    load_stage(0, 0);

    for (int kb = 0; kb < NKB; kb++) {
        if (kb + 1 < NKB) load_stage((kb + 1) & 1, kb + 1);
        if (kb + 1 < NKB) cp_wait<1>(); else cp_wait<0>();
        __syncthreads();

        uint32_t sb = sbase + (kb & 1) * STAGE_BYTES;
        uint32_t aHb = sb,            aLb = sb + 16384;
        uint32_t bHb = sb + 32768,    bLb = sb + 49152;

        #pragma unroll
        for (int ks = 0; ks < 4; ks++) {
            uint32_t aH[4][4], aL[4][4], bH[4][2], bL[4][2];
            #pragma unroll
            for (int mt = 0; mt < 4; mt++) {
                int row = wm + (mt << 4) + lrow;
                uint32_t co = (uint32_t)(((ks << 5) + lkof) ^ ((row & 7) << 4));
                uint32_t off = ((uint32_t)row << 7) + co;
                ldm4(aH[mt][0], aH[mt][1], aH[mt][2], aH[mt][3], aHb + off);
                ldm4(aL[mt][0], aL[mt][1], aL[mt][2], aL[mt][3], aLb + off);
            }
            #pragma unroll
            for (int nt2 = 0; nt2 < 2; nt2++) {
                int row = wn + (nt2 << 4) + lrow;
                uint32_t co = (uint32_t)(((ks << 5) + lkof) ^ ((row & 7) << 4));
                uint32_t off = ((uint32_t)row << 7) + co;
                uint32_t r0, r1, r2, r3;
                ldm4(r0, r1, r2, r3, bHb + off);
                bH[2*nt2][0] = r0; bH[2*nt2][1] = r2;
                bH[2*nt2+1][0] = r1; bH[2*nt2+1][1] = r3;
                ldm4(r0, r1, r2, r3, bLb + off);
                bL[2*nt2][0] = r0; bL[2*nt2][1] = r2;
                bL[2*nt2+1][0] = r1; bL[2*nt2+1][1] = r3;
            }
            #pragma unroll
            for (int mt = 0; mt < 4; mt++)
                #pragma unroll
                for (int nt = 0; nt < 4; nt++) {
                    mma16816(acc[mt][nt], aH[mt], bH[nt]);
                    mma16816(acc[mt][nt], aH[mt], bL[nt]);
                    mma16816(acc[mt][nt], aL[mt], bH[nt]);
                }
        }
        __syncthreads();
    }

    // epilogue: c0,c1 -> (row, col..col+1); c2,c3 -> (row+8, col..col+1)
    const int erow = lane >> 2, ecol = (lane & 3) << 1;
    #pragma unroll
    for (int mt = 0; mt < 4; mt++) {
        int r0 = bm + wm + (mt << 4) + erow;
        #pragma unroll
        for (int nt = 0; nt < 4; nt++) {
            int c0 = bn + wn + (nt << 3) + ecol;
            *(float2*)(C + (size_t)r0 * ldc + c0) =
                make_float2(acc[mt][nt][0], acc[mt][nt][1]);
            *(float2*)(C + (size_t)(r0 + 8) * ldc + c0) =
                make_float2(acc[mt][nt][2], acc[mt][nt][3]);
        }
    }
}

// ------------------------------ LayerNorm + bf16 split ---------------------
__global__ void ln_split_kernel(const float* __restrict__ xin, const float* __restrict__ w,
                                const float* __restrict__ bsh,
                                __nv_bfloat16* __restrict__ oh, __nv_bfloat16* __restrict__ ol) {
    int row = blockIdx.x * 8 + (threadIdx.x >> 5);
    int lane = threadIdx.x & 31;
    const float* r = xin + (size_t)row * Dch;
    float v[24];
    float s = 0.f, s2 = 0.f;
    #pragma unroll
    for (int j = 0; j < 24; j++) { float t = r[lane + j*32]; v[j] = t; s += t; s2 += t*t; }
    #pragma unroll
    for (int o = 16; o; o >>= 1) {
        s  += __shfl_xor_sync(0xFFFFFFFFu, s,  o);
        s2 += __shfl_xor_sync(0xFFFFFFFFu, s2, o);
    }
    float mu = s * (1.f/Dch);
    float rs = rsqrtf(s2 * (1.f/Dch) - mu*mu + 1e-5f);
    #pragma unroll
    for (int j = 0; j < 24; j++) {
        int c = lane + j*32;
        float y = (v[j] - mu) * rs * w[c] + bsh[c];
        __nv_bfloat16 h = __float2bfloat16(y);
        oh[(size_t)row*Dch + c] = h;
        ol[(size_t)row*Dch + c] = __float2bfloat16(y - __bfloat162float(h));
    }
}

// ------------------------------ weight hi/lo split (K pad) -----------------
__global__ void wsplit_kernel(const float* __restrict__ src, int M, int K, int Kp,
                              __nv_bfloat16* __restrict__ dh, __nv_bfloat16* __restrict__ dl) {
    int total = M * Kp;
    for (int idx = blockIdx.x * 256 + threadIdx.x; idx < total; idx += gridDim.x * 256) {
        int m = idx / Kp, k = idx - m * Kp;
        float v = (k < K) ? src[(size_t)m * K + k] : 0.f;
        __nv_bfloat16 h = __float2bfloat16(v);
        dh[idx] = h;
        dl[idx] = __float2bfloat16(v - __bfloat162float(h));
    }
}

// ------------------------------ transpose + split --------------------------
// src fp32 (K x 4096) -> dst hi/lo (4096 x Kp) bf16. REMAP: h-major -> w-major.
template<int REMAP>
__global__ void tconv_kernel(const float* __restrict__ src, int K, int Kp,
                             __nv_bfloat16* __restrict__ dh, __nv_bfloat16* __restrict__ dl) {
    __shared__ float sm[32][33];
    int n0 = blockIdx.x << 5, k0 = blockIdx.y << 5;
    int tx = threadIdx.x, ty = threadIdx.y;
    float v = 0.f;
    if (k0 + ty < K) {
        int n = n0 + tx, col;
        if (REMAP) { int q = n & 1023; col = (n & ~1023) + ((q & 31) << 5) + (q >> 5); }
        else col = n;
        v = src[(size_t)(k0 + ty) * NTOT + col];
    }
    sm[ty][tx] = v;
    __syncthreads();
    float y = sm[tx][ty];
    __nv_bfloat16 h = __float2bfloat16(y);
    size_t o = (size_t)(n0 + ty) * Kp + k0 + tx;
    dh[o] = h;
    dl[o] = __float2bfloat16(y - __bfloat162float(h));
}

// ------------------------------ fp32 SGEMM (xdown only) --------------------
__global__ __launch_bounds__(256)
void sgemm_kernel(const float* __restrict__ W, const float* __restrict__ X,
                  float* __restrict__ C, int M, int N, int K) {
    __shared__ float As[8][128];
    __shared__ float Bs[8][64];
    int bm = blockIdx.y * 128, bn = blockIdx.x * 64;
    int tid = threadIdx.x;
    int arow = tid >> 1, acol = (tid & 1) * 4;
    int brow = tid >> 5, bcol = tid & 31;
    int tm = (tid >> 4) * 8, tn = (tid & 15) * 4;
    float acc[8][4];
    #pragma unroll
    for (int i = 0; i < 8; i++)
        #pragma unroll
        for (int j = 0; j < 4; j++) acc[i][j] = 0.f;
    for (int k0 = 0; k0 < K; k0 += 8) {
        float4 av = make_float4(0.f,0.f,0.f,0.f);
        if (bm + arow < M)
            av = *(const float4*)(W + (size_t)(bm + arow)*K + k0 + acol);
        As[acol+0][arow] = av.x; As[acol+1][arow] = av.y;
        As[acol+2][arow] = av.z; As[acol+3][arow] = av.w;
        Bs[brow][bcol]    = X[(size_t)(k0+brow)*N + bn + bcol];
        Bs[brow][bcol+32] = X[(size_t)(k0+brow)*N + bn + bcol + 32];
        __syncthreads();
        #pragma unroll
        for (int kk = 0; kk < 8; kk++) {
            float a[8], bb[4];
            *(float4*)(a)   = *(const float4*)&As[kk][tm];
            *(float4*)(a+4) = *(const float4*)&As[kk][tm+4];
            *(float4*)(bb)  = *(const float4*)&Bs[kk][tn];
            #pragma unroll
            for (int i = 0; i < 8; i++)
                #pragma unroll
                for (int j = 0; j < 4; j++)
                    acc[i][j] = fmaf(a[i], bb[j], acc[i][j]);
        }
        __syncthreads();
    }
    #pragma unroll
    for (int i = 0; i < 8; i++) {
        int row = bm + tm + i;
        if (row < M)
            *(float4*)(C + (size_t)row*N + bn + tn) =
                make_float4(acc[i][0], acc[i][1], acc[i][2], acc[i][3]);
    }
}

// ------------------------------ depthwise convs ----------------------------
__global__ void dw7_kernel(const float* __restrict__ in, const float* __restrict__ wt,
                           const float* __restrict__ bias, float* __restrict__ out) {
    int d = blockIdx.x, b = blockIdx.y;
    __shared__ float sm[38][38];
    __shared__ float wsm[49];
    const float* plane = in + (size_t)d*NTOT + b*NPIX;
    int tid = threadIdx.x;
    if (tid < 49) wsm[tid] = wt[d*49 + tid];
    for (int i = tid; i < 38*38; i += 256) {
        int y = i/38 - 3, x = i%38 - 3;
        sm[i/38][i%38] = (y>=0 && y<32 && x>=0 && x<32) ? plane[y*32+x] : 0.f;
    }
    __syncthreads();
    float bv = bias[d];
    for (int p = tid; p < 1024; p += 256) {
        int y = p >> 5, x = p & 31;
        float acc = bv;
        #pragma unroll
        for (int ky = 0; ky < 7; ky++)
            #pragma unroll
            for (int kx = 0; kx < 7; kx++)
                acc = fmaf(sm[y+ky][x+kx], wsm[ky*7+kx], acc);
        out[(size_t)d*NTOT + b*NPIX + p] = acc;
    }
}

__global__ void dw3act_kernel(const float* __restrict__ in, const float* __restrict__ wt,
                              float* __restrict__ out) {
    int d = blockIdx.x, b = blockIdx.y;
    __shared__ float sm[34][34];
    __shared__ float wsm[9];
    const float* plane = in + (size_t)d*NTOT + b*NPIX;
    int tid = threadIdx.x;
    if (tid < 9) wsm[tid] = wt[d*9 + tid];
    for (int i = tid; i < 34*34; i += 256) {
        int y = i/34 - 1, x = i%34 - 1;
        sm[i/34][i%34] = (y>=0 && y<32 && x>=0 && x<32) ? plane[y*32+x] : 0.f;
    }
    __syncthreads();
    for (int p = tid; p < 1024; p += 256) {
        int y = p >> 5, x = p & 31;
        float acc = 0.f;
        #pragma unroll
        for (int ky = 0; ky < 3; ky++)
            #pragma unroll
            for (int kx = 0; kx < 3; kx++)
                acc = fmaf(sm[y+ky][x+kx], wsm[ky*3+kx], acc);
        float z = (acc > 0.f) ? acc*acc : 0.f;
        out[(size_t)d*NTOT + b*NPIX + p] = z;
    }
}

// ------------------------------ 32x32 per-plane transpose ------------------
__global__ void transpose32_kernel(const float* __restrict__ in, float* __restrict__ out) {
    __shared__ float sm[32][33];
    int d = blockIdx.x, b = blockIdx.y;
    size_t base = (size_t)d*NTOT + b*NPIX;
    int tx = threadIdx.x, ty = threadIdx.y;
    sm[ty][tx] = in[base + ty*32 + tx];
    __syncthreads();
    out[base + ty*32 + tx] = sm[tx][ty];
}

// ------------------------------ scan ---------------------------------------
__global__ void scan_kernel(const float* __restrict__ gate,
                            const float* __restrict__ x2,
                            const float* __restrict__ x2t,
                            const float* __restrict__ mw,
                            float* __restrict__ s4) {
    int c4 = blockIdx.x, b = blockIdx.y;
    int k = c4 / Dch, d = c4 - k*Dch;
    int tid = threadIdx.x;
    int chunk = tid >> 5, h = tid & 31;
    const size_t PS = (size_t)C4 * NTOT;
    const float* Gl = gate + (size_t)c4*NTOT + b*NPIX;
    const float* Gm = Gl + PS;
    const float* Gr = Gl + 2*PS;
    const float* Lp = Gl + 3*PS;
    const float* Up = Gl + 4*PS;
    const float* Dp = Gl + 5*PS;
    const float* xsrc = ((k & 1) ? x2 : x2t) + (size_t)d*NTOT + b*NPIX;
    float mk = mw[k];
    float* outp = s4 + (size_t)c4*NTOT + b*NPIX;
    float hs = 0.f;
    const unsigned mask = 0xFFFFFFFFu;
    #pragma unroll
    for (int pos = 0; pos < 8; pos++) {
        int w  = chunk*8 + pos;
        int q  = w*32 + h;
        int wq = (k >= 2) ? (31 - w) : w;
        float xv = xsrc[wq*32 + h];
        float a  = Gl[q], bb = Gm[q], cc = Gr[q], l = Lp[q];
        float ea = fast_exp(a), eb = fast_exp(bb), ec = fast_exp(cc);
        float qa = 1.f + ea, qb = 1.f + eb, qc = 1.f + ec;
        float pl = ea*qb*qc, pm = eb*qa*qc, pr = ec*qa*qb;
        float den = pl + pm + pr;
        if (h == 0)  den = pm + pr;
        if (h == 31) den = pl + pm;
        float rd = fast_rcp(den);
        float gl = pl*rd, gm = pm*rd, gr = pr*rd;
        float up = __shfl_up_sync(mask, hs, 1);
        float dn = __shfl_down_sync(mask, hs, 1);
        if (h == 0)  up = 0.f;
        if (h == 31) dn = 0.f;
        hs = fmaf(l, xv, fmaf(gl, up, fmaf(gm, hs, gr*dn)));
        outp[q] = mk * fmaf(hs, Up[q], xv*Dp[q]);
    }
}

// ------------------------------ merge (w-major -> h-major) -----------------
__global__ void merge_kernel(const float* __restrict__ s4, float* __restrict__ out) {
    __shared__ float sm[32][33];
    int d = blockIdx.x, b = blockIdx.y;
    int tx = threadIdx.x, ty = threadIdx.y;
    int q = ty*32 + tx;
    float v = 0.f;
    #pragma unroll
    for (int k = 0; k < 4; k++)
        v += s4[(size_t)(k*Dch + d)*NTOT + b*NPIX + q];
    sm[ty][tx] = v;
    __syncthreads();
    out[(size_t)d*NTOT + b*NPIX + ty*32 + tx] = sm[tx][ty];
}

// ------------------------------ launch -------------------------------------
extern "C" void kernel_launch(void* const* d_in, const int* in_sizes, int n_in,
                              void* d_out, int out_size) {
    const float* hidden   = (const float*)d_in[0];
    const float* norm_w   = (const float*)d_in[1];
    const float* norm_b   = (const float*)d_in[2];
    const float* in_proj  = (const float*)d_in[3];
    const float* conv7_w  = (const float*)d_in[4];
    const float* conv7_b  = (const float*)d_in[5];
    const float* xdown_w  = (const float*)d_in[6];
    const float* wup_w    = (const float*)d_in[7];
    const float* lup_w    = (const float*)d_in[8];
    const float* uup_w    = (const float*)d_in[9];
    const float* dcoef_w  = (const float*)d_in[10];
    const float* m_w      = (const float*)d_in[11];
    const float* outconv_w  = (const float*)d_in[12];
    const float* outdconv_w = (const float*)d_in[13];
    const float* outproj_w  = (const float*)d_in[14];
    float* outp = (float*)d_out;

    float *x1,*x2,*x2t,*xp,*gate,*s4,*mrg,*oc,*act;
    __nv_bfloat16 *xlnh,*xlnl,*wih,*wil,*woh,*wol,*wph,*wpl,*gwh,*gwl,*xpnh,*xpnl,*mnh,*mnl,*anh,*anl;
    cudaGetSymbolAddress((void**)&x1, g_x1);   cudaGetSymbolAddress((void**)&x2, g_x2);
    cudaGetSymbolAddress((void**)&x2t,g_x2t);  cudaGetSymbolAddress((void**)&xp, g_xp);
    cudaGetSymbolAddress((void**)&gate,g_gate);cudaGetSymbolAddress((void**)&s4, g_s4);
    cudaGetSymbolAddress((void**)&mrg,g_mrg);  cudaGetSymbolAddress((void**)&oc, g_oc);
    cudaGetSymbolAddress((void**)&act,g_act);
    cudaGetSymbolAddress((void**)&xlnh,g_xlnh);cudaGetSymbolAddress((void**)&xlnl,g_xlnl);
    cudaGetSymbolAddress((void**)&wih,g_wih);  cudaGetSymbolAddress((void**)&wil,g_wil);
    cudaGetSymbolAddress((void**)&woh,g_woh);  cudaGetSymbolAddress((void**)&wol,g_wol);
    cudaGetSymbolAddress((void**)&wph,g_wph);  cudaGetSymbolAddress((void**)&wpl,g_wpl);
    cudaGetSymbolAddress((void**)&gwh,g_gwh);  cudaGetSymbolAddress((void**)&gwl,g_gwl);
    cudaGetSymbolAddress((void**)&xpnh,g_xpnh);cudaGetSymbolAddress((void**)&xpnl,g_xpnl);
    cudaGetSymbolAddress((void**)&mnh,g_mnh);  cudaGetSymbolAddress((void**)&mnl,g_mnl);
    cudaGetSymbolAddress((void**)&anh,g_anh);  cudaGetSymbolAddress((void**)&anl,g_anl);

    const int MMA_SMEM = 2 * STAGE_BYTES;
    cudaFuncSetAttribute(mma_gemm, cudaFuncAttributeMaxDynamicSharedMemorySize, MMA_SMEM);
    dim3 b3232(32, 32);

    // 1) LN -> bf16 hi/lo (4096x768) token-major
    ln_split_kernel<<<NTOT/8, 256>>>(hidden, norm_w, norm_b, xlnh, xlnl);

    // 2) weight splits
    wsplit_kernel<<<2304, 256>>>(in_proj,   Dch, Dch, Dch, wih, wil);
    wsplit_kernel<<<2304, 256>>>(outconv_w, Dch, Dch, Dch, woh, wol);
    wsplit_kernel<<<2304, 256>>>(outproj_w, Dch, Dch, Dch, wph, wpl);
    wsplit_kernel<<<2304, 256>>>(wup_w,   3*C4, DS, 64, gwh,              gwl);
    wsplit_kernel<<<768,  256>>>(lup_w,      C4, DS, 64, gwh + (size_t)3*C4*64, gwl + (size_t)3*C4*64);
    wsplit_kernel<<<768,  256>>>(uup_w,      C4, DS, 64, gwh + (size_t)4*C4*64, gwl + (size_t)4*C4*64);
    wsplit_kernel<<<768,  256>>>(dcoef_w,    C4, DS, 64, gwh + (size_t)5*C4*64, gwl + (size_t)5*C4*64);

    // 3) in_proj: x1(768x4096) = Wi @ xln^T
    mma_gemm<<<dim3(NTOT/128, Dch/128), 256, MMA_SMEM>>>(wih, wil, xlnh, xlnl, x1, Dch, NTOT);

    // 4) depthwise 7x7 + bias
    dw7_kernel<<<dim3(Dch, Bsz), 256>>>(x1, conv7_w, conv7_b, x2);

    // 5) w-major copy for scan
    transpose32_kernel<<<dim3(Dch, Bsz), b3232>>>(x2, x2t);

    // 6) xdown (fp32): xp(48x4096) = Wd @ x2
    sgemm_kernel<<<dim3(NTOT/64, 1), 256>>>(xdown_w, x2, xp, DS, NTOT, Dch);

    // 7) xp -> (4096x64) hi/lo, w-major pixel remap, K pad 48->64
    tconv_kernel<1><<<dim3(NTOT/32, 2), b3232>>>(xp, DS, 64, xpnh, xpnl);

    // 8) gates: gate(18432x4096) = Gw @ xp_nk^T
    mma_gemm<<<dim3(NTOT/128, MG/128), 256, MMA_SMEM>>>(gwh, gwl, xpnh, xpnl, gate, 64, NTOT);

    // 9) scan
    scan_kernel<<<dim3(C4, Bsz), 128>>>(gate, x2, x2t, m_w, s4);

    // 10) merge -> mrg (h-major)
    merge_kernel<<<dim3(Dch, Bsz), b3232>>>(s4, mrg);

    // 11) mrg -> (4096x768) hi/lo
    tconv_kernel<0><<<dim3(NTOT/32, Dch/32), b3232>>>(mrg, Dch, Dch, mnh, mnl);

    // 12) outconv: oc(768x4096) = Wo @ mrg_nk^T
    mma_gemm<<<dim3(NTOT/128, Dch/128), 256, MMA_SMEM>>>(woh, wol, mnh, mnl, oc, Dch, NTOT);

    // 13) dw 3x3 + y*relu(y)
    dw3act_kernel<<<dim3(Dch, Bsz), 256>>>(oc, outdconv_w, act);

    // 14) act -> (4096x768) hi/lo
    tconv_kernel<0><<<dim3(NTOT/32, Dch/32), b3232>>>(act, Dch, Dch, anh, anl);

    // 15) outproj: out(4096x768) = act_nk @ Wp^T
    mma_gemm<<<dim3(Dch/128, NTOT/128), 256, MMA_SMEM>>>(anh, anl, wph, wpl, outp, Dch, Dch);

    // 16) shortcut
    cudaMemcpyAsync(outp + BTD, hidden, (size_t)BTD*sizeof(float),
                    cudaMemcpyDeviceToDevice);
}

// round 4
// speedup vs baseline: 1.3489x; 1.0483x over previous
#include <cuda_runtime.h>
#include <cuda_bf16.h>
#include <cstdint>

// ---------------------------------------------------------------------------
// GSPN block. B=4, T=1024, D=768, HW=32, DS=48, CHUNK=8.
// Round 4: 3-stage HMMA pipeline; gate GEMM split (sig: 1-pass bf16 out,
// LUD: 3-pass fp32); merge+split fusion.
// ---------------------------------------------------------------------------

#define Bsz   4
#define Dch   768
#define Tlen  1024
#define DS    48
#define NPIX  1024
#define NTOT  4096
#define C4    (4*Dch)         // 3072
#define MG    (6*C4)          // 18432
#define BTD   (Bsz*Tlen*Dch)

// ------------------------- static scratch ----------------------------------
__device__ float g_x1 [(size_t)Dch*NTOT];
__device__ float g_x2 [(size_t)Dch*NTOT];
__device__ float g_x2t[(size_t)Dch*NTOT];
__device__ float g_xp [(size_t)DS*NTOT];
__device__ __nv_bfloat16 g_gsig[(size_t)3*C4*NTOT];   // Gl|Gm|Gr bf16 (75.5MB)
__device__ float g_glud[(size_t)3*C4*NTOT];           // L|U|D fp32 (151MB)
__device__ float g_s4 [(size_t)C4*NTOT];
__device__ float g_oc [(size_t)Dch*NTOT];
__device__ float g_act[(size_t)Dch*NTOT];

__device__ __align__(16) __nv_bfloat16 g_xlnh[(size_t)NTOT*Dch], g_xlnl[(size_t)NTOT*Dch];
__device__ __align__(16) __nv_bfloat16 g_wih [Dch*Dch], g_wil [Dch*Dch];
__device__ __align__(16) __nv_bfloat16 g_woh [Dch*Dch], g_wol [Dch*Dch];
__device__ __align__(16) __nv_bfloat16 g_wph [Dch*Dch], g_wpl [Dch*Dch];
__device__ __align__(16) __nv_bfloat16 g_gwh [(size_t)MG*64], g_gwl [(size_t)MG*64];
__device__ __align__(16) __nv_bfloat16 g_xpnh[(size_t)NTOT*64], g_xpnl[(size_t)NTOT*64];
__device__ __align__(16) __nv_bfloat16 g_mnh [(size_t)NTOT*Dch], g_mnl [(size_t)NTOT*Dch];
__device__ __align__(16) __nv_bfloat16 g_anh [(size_t)NTOT*Dch], g_anl [(size_t)NTOT*Dch];

// ------------------------------ helpers ------------------------------------
__device__ __forceinline__ uint32_t smem_u32(const void* p) {
    uint32_t r;
    asm("{ .reg .u64 t; cvta.to.shared.u64 t, %1; cvt.u32.u64 %0, t; }"
        : "=r"(r) : "l"(p));
    return r;
}
__device__ __forceinline__ void cp16(uint32_t saddr, const void* gptr) {
    asm volatile("cp.async.cg.shared.global [%0], [%1], 16;"
        :: "r"(saddr), "l"(gptr));
}
__device__ __forceinline__ void cp_commit() {
    asm volatile("cp.async.commit_group;" ::: "memory");
}
template<int N>
__device__ __forceinline__ void cp_wait() {
    asm volatile("cp.async.wait_group %0;" :: "n"(N) : "memory");
}
__device__ __forceinline__ void ldm4(uint32_t& r0, uint32_t& r1, uint32_t& r2,
                                     uint32_t& r3, uint32_t addr) {
    asm volatile("ldmatrix.sync.aligned.m8n8.x4.shared.b16 {%0,%1,%2,%3}, [%4];"
        : "=r"(r0), "=r"(r1), "=r"(r2), "=r"(r3) : "r"(addr));
}
__device__ __forceinline__ void mma16816(float* c, const uint32_t* a,
                                         const uint32_t* b) {
    asm volatile("mma.sync.aligned.m16n8k16.row.col.f32.bf16.bf16.f32 "
        "{%0,%1,%2,%3}, {%4,%5,%6,%7}, {%8,%9}, {%0,%1,%2,%3};"
        : "+f"(c[0]), "+f"(c[1]), "+f"(c[2]), "+f"(c[3])
        : "r"(a[0]), "r"(a[1]), "r"(a[2]), "r"(a[3]), "r"(b[0]), "r"(b[1]));
}

__device__ __forceinline__ float fast_exp(float x) {
    x = fminf(fmaxf(x, -20.f), 20.f);
    float t = x * 1.4426950408889634f;
    float r = t + 12582912.f;
    int   i = __float_as_int(r) - 0x4B400000;
    float f = t - (r - 12582912.f);
    const float c1=0.69314718056f, c2=0.2402265069f, c3=0.0555041087f,
                c4=0.00961812911f, c5=0.00133335581f;
    float p = fmaf(c5, f, c4);
    p = fmaf(p, f, c3); p = fmaf(p, f, c2); p = fmaf(p, f, c1); p = fmaf(p, f, 1.f);
    return __int_as_float(__float_as_int(p) + (i << 23));
}
__device__ __forceinline__ float fast_rcp(float x) {
    float y = __int_as_float(0x7EF311C3 - __float_as_int(x));
    y = y * (2.0f - x * y);
    y = y * (2.0f - x * y);
    y = y * (2.0f - x * y);
    return y;
}

// ------------------------------ HMMA GEMM ----------------------------------
// C(MxN) = sum of hi/lo passes of A(MxKp) @ B(NxKp)^T (bf16 K-major).
// PASSES=3: Ahi*Bhi + Ahi*Blo + Alo*Bhi, PASSES=1: Ahi*Bhi.
// OUTBF16=1 -> write Cb (bf16), else Cf (fp32). 3-stage cp.async pipeline.
template<int PASSES, int OUTBF16>
__global__ __launch_bounds__(256, 1)
void mma_gemm(const __nv_bfloat16* __restrict__ Ahi, const __nv_bfloat16* __restrict__ Alo,
              const __nv_bfloat16* __restrict__ Bhi, const __nv_bfloat16* __restrict__ Blo,
              float* __restrict__ Cf, __nv_bfloat16* __restrict__ Cb,
              int Kp, int ldc) {
    extern __shared__ __align__(16) char dsm[];
    const int SSTAGE = (PASSES == 3) ? 65536 : 32768;
    const int tid  = threadIdx.x;
    const int wid  = tid >> 5, lane = tid & 31;
    const int wm   = (wid >> 2) << 6;
    const int wn   = (wid & 3)  << 5;
    const int bm   = blockIdx.y << 7, bn = blockIdx.x << 7;
    const uint32_t sbase = smem_u32(dsm);
    const int NKB = Kp >> 6;

    const int crow0  = tid >> 1;
    const int cslot0 = (tid & 1) << 2;

    auto load_stage = [&](int buf, int kb) {
        const int k0 = kb << 6;
        uint32_t sb = sbase + buf * SSTAGE;
        const int NPL = (PASSES == 3) ? 4 : 2;
        const __nv_bfloat16* srcs3[4] = {Ahi, Alo, Bhi, Blo};
        const __nv_bfloat16* srcs1[2] = {Ahi, Bhi};
        const int rb3[4] = {bm, bm, bn, bn};
        const int rb1[2] = {bm, bn};
        #pragma unroll
        for (int pl = 0; pl < NPL; pl++) {
            const __nv_bfloat16* src =
                ((PASSES == 3) ? srcs3[pl] : srcs1[pl])
                + (size_t)(((PASSES == 3) ? rb3[pl] : rb1[pl]) + crow0) * Kp + k0;
            uint32_t pbase = sb + (pl << 14) + (crow0 << 7);
            #pragma unroll
            for (int s = 0; s < 4; s++) {
                uint32_t bo = (cslot0 + s) << 4;
                cp16(pbase + (bo ^ ((crow0 & 7) << 4)), src + ((cslot0 + s) << 3));
            }
        }
        cp_commit();
    };

    float acc[4][4][4];
    #pragma unroll
    for (int i = 0; i < 4; i++)
        #pragma unroll
        for (int j = 0; j < 4; j++)
            #pragma unroll
            for (int q = 0; q < 4; q++) acc[i][j][q] = 0.f;

    const int lrow = (lane & 7) + (((lane >> 3) & 1) << 3);
    const int lkof = ((lane >> 4) & 1) << 4;

    load_stage(0, 0);
    if (NKB > 1) load_stage(1, 1);

    for (int kb = 0; kb < NKB; kb++) {
        if (kb < NKB - 1) cp_wait<1>(); else cp_wait<0>();
        __syncthreads();
        if (kb + 2 < NKB) {
            int dst = kb + 2;
            load_stage(dst - (dst / 3) * 3, dst);
        }

        uint32_t sb = sbase + (kb - (kb / 3) * 3) * SSTAGE;
        uint32_t aHb = sb;
        uint32_t aLb = sb + 16384;                    // PASSES==3 only
        uint32_t bHb = (PASSES == 3) ? sb + 32768 : sb + 16384;
        uint32_t bLb = sb + 49152;                    // PASSES==3 only

        #pragma unroll
        for (int ks = 0; ks < 4; ks++) {
            uint32_t aH[4][4], aL[4][4], bH[4][2], bL[4][2];
            #pragma unroll
            for (int mt = 0; mt < 4; mt++) {
                int row = wm + (mt << 4) + lrow;
                uint32_t co = (uint32_t)(((ks << 5) + lkof) ^ ((row & 7) << 4));
                uint32_t off = ((uint32_t)row << 7) + co;
                ldm4(aH[mt][0], aH[mt][1], aH[mt][2], aH[mt][3], aHb + off);
                if (PASSES == 3)
                    ldm4(aL[mt][0], aL[mt][1], aL[mt][2], aL[mt][3], aLb + off);
            }
            #pragma unroll
            for (int nt2 = 0; nt2 < 2; nt2++) {
                int row = wn + (nt2 << 4) + lrow;
                uint32_t co = (uint32_t)(((ks << 5) + lkof) ^ ((row & 7) << 4));
                uint32_t off = ((uint32_t)row << 7) + co;
                uint32_t r0, r1, r2, r3;
                ldm4(r0, r1, r2, r3, bHb + off);
                bH[2*nt2][0] = r0; bH[2*nt2][1] = r2;
                bH[2*nt2+1][0] = r1; bH[2*nt2+1][1] = r3;
                if (PASSES == 3) {
                    ldm4(r0, r1, r2, r3, bLb + off);
                    bL[2*nt2][0] = r0; bL[2*nt2][1] = r2;
                    bL[2*nt2+1][0] = r1; bL[2*nt2+1][1] = r3;
                }
            }
            #pragma unroll
            for (int mt = 0; mt < 4; mt++)
                #pragma unroll
                for (int nt = 0; nt < 4; nt++) {
                    mma16816(acc[mt][nt], aH[mt], bH[nt]);
                    if (PASSES == 3) {
                        mma16816(acc[mt][nt], aH[mt], bL[nt]);
                        mma16816(acc[mt][nt], aL[mt], bH[nt]);
                    }
                }
        }
    }

    const int erow = lane >> 2, ecol = (lane & 3) << 1;
    #pragma unroll
    for (int mt = 0; mt < 4; mt++) {
        int r0 = bm + wm + (mt << 4) + erow;
        #pragma unroll
        for (int nt = 0; nt < 4; nt++) {
            int c0 = bn + wn + (nt << 3) + ecol;
            if (OUTBF16) {
                __nv_bfloat162 v0, v1;
                v0.x = __float2bfloat16(acc[mt][nt][0]);
                v0.y = __float2bfloat16(acc[mt][nt][1]);
                v1.x = __float2bfloat16(acc[mt][nt][2]);
                v1.y = __float2bfloat16(acc[mt][nt][3]);
                *(__nv_bfloat162*)(Cb + (size_t)r0 * ldc + c0) = v0;
                *(__nv_bfloat162*)(Cb + (size_t)(r0 + 8) * ldc + c0) = v1;
            } else {
                *(float2*)(Cf + (size_t)r0 * ldc + c0) =
                    make_float2(acc[mt][nt][0], acc[mt][nt][1]);
                *(float2*)(Cf + (size_t)(r0 + 8) * ldc + c0) =
                    make_float2(acc[mt][nt][2], acc[mt][nt][3]);
            }
        }
    }
}

// ------------------------------ LayerNorm + bf16 split ---------------------
__global__ void ln_split_kernel(const float* __restrict__ xin, const float* __restrict__ w,
                                const float* __restrict__ bsh,
                                __nv_bfloat16* __restrict__ oh, __nv_bfloat16* __restrict__ ol) {
    int row = blockIdx.x * 8 + (threadIdx.x >> 5);
    int lane = threadIdx.x & 31;
    const float* r = xin + (size_t)row * Dch;
    float v[24];
    float s = 0.f, s2 = 0.f;
    #pragma unroll
    for (int j = 0; j < 24; j++) { float t = r[lane + j*32]; v[j] = t; s += t; s2 += t*t; }
    #pragma unroll
    for (int o = 16; o; o >>= 1) {
        s  += __shfl_xor_sync(0xFFFFFFFFu, s,  o);
        s2 += __shfl_xor_sync(0xFFFFFFFFu, s2, o);
    }
    float mu = s * (1.f/Dch);
    float rs = rsqrtf(s2 * (1.f/Dch) - mu*mu + 1e-5f);
    #pragma unroll
    for (int j = 0; j < 24; j++) {
        int c = lane + j*32;
        float y = (v[j] - mu) * rs * w[c] + bsh[c];
        __nv_bfloat16 h = __float2bfloat16(y);
        oh[(size_t)row*Dch + c] = h;
        ol[(size_t)row*Dch + c] = __float2bfloat16(y - __bfloat162float(h));
    }
}

// ------------------------------ weight hi/lo split --------------------------
__global__ void wsplit_kernel(const float* __restrict__ src, int M, int K, int Kp,
                              __nv_bfloat16* __restrict__ dh, __nv_bfloat16* __restrict__ dl) {
    int total = M * Kp;
    for (int idx = blockIdx.x * 256 + threadIdx.x; idx < total; idx += gridDim.x * 256) {
        int m = idx / Kp, k = idx - m * Kp;
        float v = (k < K) ? src[(size_t)m * K + k] : 0.f;
        __nv_bfloat16 h = __float2bfloat16(v);
        dh[idx] = h;
        dl[idx] = __float2bfloat16(v - __bfloat162float(h));
    }
}

// ------------------------------ transpose + split ---------------------------
template<int REMAP>
__global__ void tconv_kernel(const float* __restrict__ src, int K, int Kp,
                             __nv_bfloat16* __restrict__ dh, __nv_bfloat16* __restrict__ dl) {
    __shared__ float sm[32][33];
    int n0 = blockIdx.x << 5, k0 = blockIdx.y << 5;
    int tx = threadIdx.x, ty = threadIdx.y;
    float v = 0.f;
    if (k0 + ty < K) {
        int n = n0 + tx, col;
        if (REMAP) { int q = n & 1023; col = (n & ~1023) + ((q & 31) << 5) + (q >> 5); }
        else col = n;
        v = src[(size_t)(k0 + ty) * NTOT + col];
    }
    sm[ty][tx] = v;
    __syncthreads();
    float y = sm[tx][ty];
    __nv_bfloat16 h = __float2bfloat16(y);
    size_t o = (size_t)(n0 + ty) * Kp + k0 + tx;
    dh[o] = h;
    dl[o] = __float2bfloat16(y - __bfloat162float(h));
}

// ------------------------------ fp32 SGEMM (xdown only) --------------------
__global__ __launch_bounds__(256)
void sgemm_kernel(const float* __restrict__ W, const float* __restrict__ X,
                  float* __restrict__ C, int M, int N, int K) {
    __shared__ float As[8][128];
    __shared__ float Bs[8][64];
    int bm = blockIdx.y * 128, bn = blockIdx.x * 64;
    int tid = threadIdx.x;
    int arow = tid >> 1, acol = (tid & 1) * 4;
    int brow = tid >> 5, bcol = tid & 31;
    int tm = (tid >> 4) * 8, tn = (tid & 15) * 4;
    float acc[8][4];
    #pragma unroll
    for (int i = 0; i < 8; i++)
        #pragma unroll
        for (int j = 0; j < 4; j++) acc[i][j] = 0.f;
    for (int k0 = 0; k0 < K; k0 += 8) {
        float4 av = make_float4(0.f,0.f,0.f,0.f);
        if (bm + arow < M)
            av = *(const float4*)(W + (size_t)(bm + arow)*K + k0 + acol);
        As[acol+0][arow] = av.x; As[acol+1][arow] = av.y;
        As[acol+2][arow] = av.z; As[acol+3][arow] = av.w;
        Bs[brow][bcol]    = X[(size_t)(k0+brow)*N + bn + bcol];
        Bs[brow][bcol+32] = X[(size_t)(k0+brow)*N + bn + bcol + 32];
        __syncthreads();
        #pragma unroll
        for (int kk = 0; kk < 8; kk++) {
            float a[8], bb[4];
            *(float4*)(a)   = *(const float4*)&As[kk][tm];
            *(float4*)(a+4) = *(const float4*)&As[kk][tm+4];
            *(float4*)(bb)  = *(const float4*)&Bs[kk][tn];
            #pragma unroll
            for (int i = 0; i < 8; i++)
                #pragma unroll
                for (int j = 0; j < 4; j++)
                    acc[i][j] = fmaf(a[i], bb[j], acc[i][j]);
        }
        __syncthreads();
    }
    #pragma unroll
    for (int i = 0; i < 8; i++) {
        int row = bm + tm + i;
        if (row < M)
            *(float4*)(C + (size_t)row*N + bn + tn) =
                make_float4(acc[i][0], acc[i][1], acc[i][2], acc[i][3]);
    }
}

// ------------------------------ depthwise convs ----------------------------
__global__ void dw7_kernel(const float* __restrict__ in, const float* __restrict__ wt,
                           const float* __restrict__ bias, float* __restrict__ out) {
    int d = blockIdx.x, b = blockIdx.y;
    __shared__ float sm[38][38];
    __shared__ float wsm[49];
    const float* plane = in + (size_t)d*NTOT + b*NPIX;
    int tid = threadIdx.x;
    if (tid < 49) wsm[tid] = wt[d*49 + tid];
    for (int i = tid; i < 38*38; i += 256) {
        int y = i/38 - 3, x = i%38 - 3;
        sm[i/38][i%38] = (y>=0 && y<32 && x>=0 && x<32) ? plane[y*32+x] : 0.f;
    }
    __syncthreads();
    float bv = bias[d];
    for (int p = tid; p < 1024; p += 256) {
        int y = p >> 5, x = p & 31;
        float acc = bv;
        #pragma unroll
        for (int ky = 0; ky < 7; ky++)
            #pragma unroll
            for (int kx = 0; kx < 7; kx++)
                acc = fmaf(sm[y+ky][x+kx], wsm[ky*7+kx], acc);
        out[(size_t)d*NTOT + b*NPIX + p] = acc;
    }
}

__global__ void dw3act_kernel(const float* __restrict__ in, const float* __restrict__ wt,
                              float* __restrict__ out) {
    int d = blockIdx.x, b = blockIdx.y;
    __shared__ float sm[34][34];
    __shared__ float wsm[9];
    const float* plane = in + (size_t)d*NTOT + b*NPIX;
    int tid = threadIdx.x;
    if (tid < 9) wsm[tid] = wt[d*9 + tid];
    for (int i = tid; i < 34*34; i += 256) {
        int y = i/34 - 1, x = i%34 - 1;
        sm[i/34][i%34] = (y>=0 && y<32 && x>=0 && x<32) ? plane[y*32+x] : 0.f;
    }
    __syncthreads();
    for (int p = tid; p < 1024; p += 256) {
        int y = p >> 5, x = p & 31;
        float acc = 0.f;
        #pragma unroll
        for (int ky = 0; ky < 3; ky++)
            #pragma unroll
            for (int kx = 0; kx < 3; kx++)
                acc = fmaf(sm[y+ky][x+kx], wsm[ky*3+kx], acc);
        float z = (acc > 0.f) ? acc*acc : 0.f;
        out[(size_t)d*NTOT + b*NPIX + p] = z;
    }
}

// ------------------------------ 32x32 transpose -----------------------------
__global__ void transpose32_kernel(const float* __restrict__ in, float* __restrict__ out) {
    __shared__ float sm[32][33];
    int d = blockIdx.x, b = blockIdx.y;
    size_t base = (size_t)d*NTOT + b*NPIX;
    int tx = threadIdx.x, ty = threadIdx.y;
    sm[ty][tx] = in[base + ty*32 + tx];
    __syncthreads();
    out[base + ty*32 + tx] = sm[tx][ty];
}

// ------------------------------ scan ---------------------------------------
// sig gates (bf16, rows Gl|Gm|Gr) + LUD (fp32, rows L|U|D). cols w-major.
__global__ void scan_kernel(const __nv_bfloat16* __restrict__ gsig,
                            const float* __restrict__ glud,
                            const float* __restrict__ x2,
                            const float* __restrict__ x2t,
                            const float* __restrict__ mw,
                            float* __restrict__ s4) {
    int c4 = blockIdx.x, b = blockIdx.y;
    int k = c4 / Dch, d = c4 - k*Dch;
    int tid = threadIdx.x;
    int chunk = tid >> 5, h = tid & 31;
    const size_t PS = (size_t)C4 * NTOT;
    const __nv_bfloat16* Gl = gsig + (size_t)c4*NTOT + (size_t)b*NPIX;
    const __nv_bfloat16* Gm = Gl + PS;
    const __nv_bfloat16* Gr = Gl + 2*PS;
    const float* Lp = glud + (size_t)c4*NTOT + (size_t)b*NPIX;
    const float* Up = Lp + PS;
    const float* Dp = Lp + 2*PS;
    const float* xsrc = ((k & 1) ? x2 : x2t) + (size_t)d*NTOT + b*NPIX;
    float mk = mw[k];
    float* outp = s4 + (size_t)c4*NTOT + b*NPIX;
    float hs = 0.f;
    const unsigned mask = 0xFFFFFFFFu;
    #pragma unroll
    for (int pos = 0; pos < 8; pos++) {
        int w  = chunk*8 + pos;
        int q  = w*32 + h;
        int wq = (k >= 2) ? (31 - w) : w;
        float xv = xsrc[wq*32 + h];
        float a  = __bfloat162float(Gl[q]);
        float bb = __bfloat162float(Gm[q]);
        float cc = __bfloat162float(Gr[q]);
        float l  = Lp[q];
        float ea = fast_exp(a), eb = fast_exp(bb), ec = fast_exp(cc);
        float qa = 1.f + ea, qb = 1.f + eb, qc = 1.f + ec;
        float pl = ea*qb*qc, pm = eb*qa*qc, pr = ec*qa*qb;
        float den = pl + pm + pr;
        if (h == 0)  den = pm + pr;
        if (h == 31) den = pl + pm;
        float rd = fast_rcp(den);
        float gl = pl*rd, gm = pm*rd, gr = pr*rd;
        float up = __shfl_up_sync(mask, hs, 1);
        float dn = __shfl_down_sync(mask, hs, 1);
        if (h == 0)  up = 0.f;
        if (h == 31) dn = 0.f;
        hs = fmaf(l, xv, fmaf(gl, up, fmaf(gm, hs, gr*dn)));
        outp[q] = mk * fmaf(hs, Up[q], xv*Dp[q]);
    }
}

// ------------------------------ merge + transpose + bf16 split -------------
// s4 (C4 x NTOT, w-major cols) -> mn (NTOT tokens x 768) hi/lo bf16.
// grid (24, Bsz, 4), block (32,32). token t = h*32 + w.
__global__ void merge_split_kernel(const float* __restrict__ s4,
                                   __nv_bfloat16* __restrict__ dh,
                                   __nv_bfloat16* __restrict__ dl) {
    __shared__ float sm[32][33];
    int d0 = blockIdx.x << 5, b = blockIdx.y;
    int tx = threadIdx.x, ty = threadIdx.y;
    for (int pg = blockIdx.z * 8; pg < blockIdx.z * 8 + 8; pg++) {
        int q = (pg << 5) + tx;              // w = pg, h = tx
        float v = 0.f;
        #pragma unroll
        for (int k = 0; k < 4; k++)
            v += s4[(size_t)(k*Dch + d0 + ty)*NTOT + b*NPIX + q];
        sm[ty][tx] = v;                      // sm[d_local][h]
        __syncthreads();
        float y = sm[tx][ty];                // d_local = tx, h = ty
        __nv_bfloat16 hh = __float2bfloat16(y);
        size_t o = (size_t)(b*NPIX + (ty << 5) + pg) * Dch + d0 + tx;
        dh[o] = hh;
        dl[o] = __float2bfloat16(y - __bfloat162float(hh));
        __syncthreads();
    }
}

// ------------------------------ launch -------------------------------------
extern "C" void kernel_launch(void* const* d_in, const int* in_sizes, int n_in,
                              void* d_out, int out_size) {
    const float* hidden   = (const float*)d_in[0];
    const float* norm_w   = (const float*)d_in[1];
    const float* norm_b   = (const float*)d_in[2];
    const float* in_proj  = (const float*)d_in[3];
    const float* conv7_w  = (const float*)d_in[4];
    const float* conv7_b  = (const float*)d_in[5];
    const float* xdown_w  = (const float*)d_in[6];
    const float* wup_w    = (const float*)d_in[7];
    const float* lup_w    = (const float*)d_in[8];
    const float* uup_w    = (const float*)d_in[9];
    const float* dcoef_w  = (const float*)d_in[10];
    const float* m_w      = (const float*)d_in[11];
    const float* outconv_w  = (const float*)d_in[12];
    const float* outdconv_w = (const float*)d_in[13];
    const float* outproj_w  = (const float*)d_in[14];
    float* outp = (float*)d_out;

    float *x1,*x2,*x2t,*xp,*glud,*s4,*oc,*act;
    __nv_bfloat16 *gsig,*xlnh,*xlnl,*wih,*wil,*woh,*wol,*wph,*wpl,*gwh,*gwl,
                  *xpnh,*xpnl,*mnh,*mnl,*anh,*anl;
    cudaGetSymbolAddress((void**)&x1, g_x1);   cudaGetSymbolAddress((void**)&x2, g_x2);
    cudaGetSymbolAddress((void**)&x2t,g_x2t);  cudaGetSymbolAddress((void**)&xp, g_xp);
    cudaGetSymbolAddress((void**)&gsig,g_gsig);cudaGetSymbolAddress((void**)&glud,g_glud);
    cudaGetSymbolAddress((void**)&s4, g_s4);   cudaGetSymbolAddress((void**)&oc, g_oc);
    cudaGetSymbolAddress((void**)&act,g_act);
    cudaGetSymbolAddress((void**)&xlnh,g_xlnh);cudaGetSymbolAddress((void**)&xlnl,g_xlnl);
    cudaGetSymbolAddress((void**)&wih,g_wih);  cudaGetSymbolAddress((void**)&wil,g_wil);
    cudaGetSymbolAddress((void**)&woh,g_woh);  cudaGetSymbolAddress((void**)&wol,g_wol);
    cudaGetSymbolAddress((void**)&wph,g_wph);  cudaGetSymbolAddress((void**)&wpl,g_wpl);
    cudaGetSymbolAddress((void**)&gwh,g_gwh);  cudaGetSymbolAddress((void**)&gwl,g_gwl);
    cudaGetSymbolAddress((void**)&xpnh,g_xpnh);cudaGetSymbolAddress((void**)&xpnl,g_xpnl);
    cudaGetSymbolAddress((void**)&mnh,g_mnh);  cudaGetSymbolAddress((void**)&mnl,g_mnl);
    cudaGetSymbolAddress((void**)&anh,g_anh);  cudaGetSymbolAddress((void**)&anl,g_anl);

    const int SMEM3 = 3 * 65536;
    const int SMEM1 = 3 * 32768;
    cudaFuncSetAttribute(mma_gemm<3,0>, cudaFuncAttributeMaxDynamicSharedMemorySize, SMEM3);
    cudaFuncSetAttribute(mma_gemm<1,1>, cudaFuncAttributeMaxDynamicSharedMemorySize, SMEM1);
    dim3 b3232(32, 32);

    // 1) LN -> bf16 hi/lo
    ln_split_kernel<<<NTOT/8, 256>>>(hidden, norm_w, norm_b, xlnh, xlnl);

    // 2) weight splits
    wsplit_kernel<<<2304, 256>>>(in_proj,   Dch, Dch, Dch, wih, wil);
    wsplit_kernel<<<2304, 256>>>(outconv_w, Dch, Dch, Dch, woh, wol);
    wsplit_kernel<<<2304, 256>>>(outproj_w, Dch, Dch, Dch, wph, wpl);
    wsplit_kernel<<<2304, 256>>>(wup_w,   3*C4, DS, 64, gwh,              gwl);
    wsplit_kernel<<<768,  256>>>(lup_w,      C4, DS, 64, gwh + (size_t)3*C4*64, gwl + (size_t)3*C4*64);
    wsplit_kernel<<<768,  256>>>(uup_w,      C4, DS, 64, gwh + (size_t)4*C4*64, gwl + (size_t)4*C4*64);
    wsplit_kernel<<<768,  256>>>(dcoef_w,    C4, DS, 64, gwh + (size_t)5*C4*64, gwl + (size_t)5*C4*64);

    // 3) in_proj
    mma_gemm<3,0><<<dim3(NTOT/128, Dch/128), 256, SMEM3>>>(
        wih, wil, xlnh, xlnl, x1, nullptr, Dch, NTOT);

    // 4) dw 7x7
    dw7_kernel<<<dim3(Dch, Bsz), 256>>>(x1, conv7_w, conv7_b, x2);

    // 5) w-major copy
    transpose32_kernel<<<dim3(Dch, Bsz), b3232>>>(x2, x2t);

    // 6) xdown (fp32)
    sgemm_kernel<<<dim3(NTOT/64, 1), 256>>>(xdown_w, x2, xp, DS, NTOT, Dch);

    // 7) xp -> (4096x64) hi/lo, w-major remap
    tconv_kernel<1><<<dim3(NTOT/32, 2), b3232>>>(xp, DS, 64, xpnh, xpnl);

    // 8a) sigmoid gates: 1-pass bf16 out
    mma_gemm<1,1><<<dim3(NTOT/128, (3*C4)/128), 256, SMEM1>>>(
        gwh, nullptr, xpnh, nullptr, nullptr, gsig, 64, NTOT);
    // 8b) L|U|D: 3-pass fp32 out
    mma_gemm<3,0><<<dim3(NTOT/128, (3*C4)/128), 256, SMEM3>>>(
        gwh + (size_t)3*C4*64, gwl + (size_t)3*C4*64, xpnh, xpnl,
        glud, nullptr, 64, NTOT);

    // 9) scan
    scan_kernel<<<dim3(C4, Bsz), 128>>>(gsig, glud, x2, x2t, m_w, s4);

    // 10) merge + transpose + split -> mn hi/lo
    merge_split_kernel<<<dim3(Dch/32, Bsz, 4), b3232>>>(s4, mnh, mnl);

    // 11) outconv
    mma_gemm<3,0><<<dim3(NTOT/128, Dch/128), 256, SMEM3>>>(
        woh, wol, mnh, mnl, oc, nullptr, Dch, NTOT);

    // 12) dw 3x3 + y*relu(y)
    dw3act_kernel<<<dim3(Dch, Bsz), 256>>>(oc, outdconv_w, act);

    // 13) act -> (4096x768) hi/lo
    tconv_kernel<0><<<dim3(NTOT/32, Dch/32), b3232>>>(act, Dch, Dch, anh, anl);

    // 14) outproj -> d_out
    mma_gemm<3,0><<<dim3(Dch/128, NTOT/128), 256, SMEM3>>>(
        anh, anl, wph, wpl, outp, nullptr, Dch, Dch);

    // 15) shortcut
    cudaMemcpyAsync(outp + BTD, hidden, (size_t)BTD*sizeof(float),
                    cudaMemcpyDeviceToDevice);
}

// round 5
// speedup vs baseline: 1.3755x; 1.0197x over previous
#include <cuda_runtime.h>
#include <cuda_bf16.h>
#include <cstdint>

// ---------------------------------------------------------------------------
// GSPN block. B=4, T=1024, D=768, HW=32, DS=48, CHUNK=8.
// Round 5: batched weight split; dw7+transpose fusion; xdown epilogue fusion;
// launch order gives ncu visibility into the sig-gate GEMM.
// ---------------------------------------------------------------------------

#define Bsz   4
#define Dch   768
#define Tlen  1024
#define DS    48
#define NPIX  1024
#define NTOT  4096
#define C4    (4*Dch)         // 3072
#define MG    (6*C4)          // 18432
#define BTD   (Bsz*Tlen*Dch)

// ------------------------- static scratch ----------------------------------
__device__ float g_x1 [(size_t)Dch*NTOT];
__device__ float g_x2 [(size_t)Dch*NTOT];
__device__ float g_x2t[(size_t)Dch*NTOT];
__device__ __nv_bfloat16 g_gsig[(size_t)3*C4*NTOT];   // Gl|Gm|Gr bf16
__device__ float g_glud[(size_t)3*C4*NTOT];           // L|U|D fp32
__device__ float g_s4 [(size_t)C4*NTOT];
__device__ float g_oc [(size_t)Dch*NTOT];
__device__ float g_act[(size_t)Dch*NTOT];

__device__ __align__(16) __nv_bfloat16 g_xlnh[(size_t)NTOT*Dch], g_xlnl[(size_t)NTOT*Dch];
__device__ __align__(16) __nv_bfloat16 g_wih [Dch*Dch], g_wil [Dch*Dch];
__device__ __align__(16) __nv_bfloat16 g_woh [Dch*Dch], g_wol [Dch*Dch];
__device__ __align__(16) __nv_bfloat16 g_wph [Dch*Dch], g_wpl [Dch*Dch];
__device__ __align__(16) __nv_bfloat16 g_gwh [(size_t)MG*64], g_gwl [(size_t)MG*64];
__device__ __align__(16) __nv_bfloat16 g_xpnh[(size_t)NTOT*64], g_xpnl[(size_t)NTOT*64];
__device__ __align__(16) __nv_bfloat16 g_mnh [(size_t)NTOT*Dch], g_mnl [(size_t)NTOT*Dch];
__device__ __align__(16) __nv_bfloat16 g_anh [(size_t)NTOT*Dch], g_anl [(size_t)NTOT*Dch];

// ------------------------------ helpers ------------------------------------
__device__ __forceinline__ uint32_t smem_u32(const void* p) {
    uint32_t r;
    asm("{ .reg .u64 t; cvta.to.shared.u64 t, %1; cvt.u32.u64 %0, t; }"
        : "=r"(r) : "l"(p));
    return r;
}
__device__ __forceinline__ void cp16(uint32_t saddr, const void* gptr) {
    asm volatile("cp.async.cg.shared.global [%0], [%1], 16;"
        :: "r"(saddr), "l"(gptr));
}
__device__ __forceinline__ void cp_commit() {
    asm volatile("cp.async.commit_group;" ::: "memory");
}
template<int N>
__device__ __forceinline__ void cp_wait() {
    asm volatile("cp.async.wait_group %0;" :: "n"(N) : "memory");
}
__device__ __forceinline__ void ldm4(uint32_t& r0, uint32_t& r1, uint32_t& r2,
                                     uint32_t& r3, uint32_t addr) {
    asm volatile("ldmatrix.sync.aligned.m8n8.x4.shared.b16 {%0,%1,%2,%3}, [%4];"
        : "=r"(r0), "=r"(r1), "=r"(r2), "=r"(r3) : "r"(addr));
}
__device__ __forceinline__ void mma16816(float* c, const uint32_t* a,
                                         const uint32_t* b) {
    asm volatile("mma.sync.aligned.m16n8k16.row.col.f32.bf16.bf16.f32 "
        "{%0,%1,%2,%3}, {%4,%5,%6,%7}, {%8,%9}, {%0,%1,%2,%3};"
        : "+f"(c[0]), "+f"(c[1]), "+f"(c[2]), "+f"(c[3])
        : "r"(a[0]), "r"(a[1]), "r"(a[2]), "r"(a[3]), "r"(b[0]), "r"(b[1]));
}

__device__ __forceinline__ float fast_exp(float x) {
    x = fminf(fmaxf(x, -20.f), 20.f);
    float t = x * 1.4426950408889634f;
    float r = t + 12582912.f;
    int   i = __float_as_int(r) - 0x4B400000;
    float f = t - (r - 12582912.f);
    const float c1=0.69314718056f, c2=0.2402265069f, c3=0.0555041087f,
                c4=0.00961812911f, c5=0.00133335581f;
    float p = fmaf(c5, f, c4);
    p = fmaf(p, f, c3); p = fmaf(p, f, c2); p = fmaf(p, f, c1); p = fmaf(p, f, 1.f);
    return __int_as_float(__float_as_int(p) + (i << 23));
}
__device__ __forceinline__ float fast_rcp(float x) {
    float y = __int_as_float(0x7EF311C3 - __float_as_int(x));
    y = y * (2.0f - x * y);
    y = y * (2.0f - x * y);
    y = y * (2.0f - x * y);
    return y;
}

// ------------------------------ HMMA GEMM ----------------------------------
template<int PASSES, int OUTBF16>
__global__ __launch_bounds__(256, 1)
void mma_gemm(const __nv_bfloat16* __restrict__ Ahi, const __nv_bfloat16* __restrict__ Alo,
              const __nv_bfloat16* __restrict__ Bhi, const __nv_bfloat16* __restrict__ Blo,
              float* __restrict__ Cf, __nv_bfloat16* __restrict__ Cb,
              int Kp, int ldc) {
    extern __shared__ __align__(16) char dsm[];
    const int SSTAGE = (PASSES == 3) ? 65536 : 32768;
    const int tid  = threadIdx.x;
    const int wid  = tid >> 5, lane = tid & 31;
    const int wm   = (wid >> 2) << 6;
    const int wn   = (wid & 3)  << 5;
    const int bm   = blockIdx.y << 7, bn = blockIdx.x << 7;
    const uint32_t sbase = smem_u32(dsm);
    const int NKB = Kp >> 6;

    const int crow0  = tid >> 1;
    const int cslot0 = (tid & 1) << 2;

    auto load_stage = [&](int buf, int kb) {
        const int k0 = kb << 6;
        uint32_t sb = sbase + buf * SSTAGE;
        const int NPL = (PASSES == 3) ? 4 : 2;
        const __nv_bfloat16* srcs3[4] = {Ahi, Alo, Bhi, Blo};
        const __nv_bfloat16* srcs1[2] = {Ahi, Bhi};
        const int rb3[4] = {bm, bm, bn, bn};
        const int rb1[2] = {bm, bn};
        #pragma unroll
        for (int pl = 0; pl < NPL; pl++) {
            const __nv_bfloat16* src =
                ((PASSES == 3) ? srcs3[pl] : srcs1[pl])
                + (size_t)(((PASSES == 3) ? rb3[pl] : rb1[pl]) + crow0) * Kp + k0;
            uint32_t pbase = sb + (pl << 14) + (crow0 << 7);
            #pragma unroll
            for (int s = 0; s < 4; s++) {
                uint32_t bo = (cslot0 + s) << 4;
                cp16(pbase + (bo ^ ((crow0 & 7) << 4)), src + ((cslot0 + s) << 3));
            }
        }
        cp_commit();
    };

    float acc[4][4][4];
    #pragma unroll
    for (int i = 0; i < 4; i++)
        #pragma unroll
        for (int j = 0; j < 4; j++)
            #pragma unroll
            for (int q = 0; q < 4; q++) acc[i][j][q] = 0.f;

    const int lrow = (lane & 7) + (((lane >> 3) & 1) << 3);
    const int lkof = ((lane >> 4) & 1) << 4;

    load_stage(0, 0);
    if (NKB > 1) load_stage(1, 1);

    for (int kb = 0; kb < NKB; kb++) {
        if (kb < NKB - 1) cp_wait<1>(); else cp_wait<0>();
        __syncthreads();
        if (kb + 2 < NKB) {
            int dst = kb + 2;
            load_stage(dst - (dst / 3) * 3, dst);
        }

        uint32_t sb = sbase + (kb - (kb / 3) * 3) * SSTAGE;
        uint32_t aHb = sb;
        uint32_t aLb = sb + 16384;
        uint32_t bHb = (PASSES == 3) ? sb + 32768 : sb + 16384;
        uint32_t bLb = sb + 49152;

        #pragma unroll
        for (int ks = 0; ks < 4; ks++) {
            uint32_t aH[4][4], aL[4][4], bH[4][2], bL[4][2];
            #pragma unroll
            for (int mt = 0; mt < 4; mt++) {
                int row = wm + (mt << 4) + lrow;
                uint32_t co = (uint32_t)(((ks << 5) + lkof) ^ ((row & 7) << 4));
                uint32_t off = ((uint32_t)row << 7) + co;
                ldm4(aH[mt][0], aH[mt][1], aH[mt][2], aH[mt][3], aHb + off);
                if (PASSES == 3)
                    ldm4(aL[mt][0], aL[mt][1], aL[mt][2], aL[mt][3], aLb + off);
            }
            #pragma unroll
            for (int nt2 = 0; nt2 < 2; nt2++) {
                int row = wn + (nt2 << 4) + lrow;
                uint32_t co = (uint32_t)(((ks << 5) + lkof) ^ ((row & 7) << 4));
                uint32_t off = ((uint32_t)row << 7) + co;
                uint32_t r0, r1, r2, r3;
                ldm4(r0, r1, r2, r3, bHb + off);
                bH[2*nt2][0] = r0; bH[2*nt2][1] = r2;
                bH[2*nt2+1][0] = r1; bH[2*nt2+1][1] = r3;
                if (PASSES == 3) {
                    ldm4(r0, r1, r2, r3, bLb + off);
                    bL[2*nt2][0] = r0; bL[2*nt2][1] = r2;
                    bL[2*nt2+1][0] = r1; bL[2*nt2+1][1] = r3;
                }
            }
            #pragma unroll
            for (int mt = 0; mt < 4; mt++)
                #pragma unroll
                for (int nt = 0; nt < 4; nt++) {
                    mma16816(acc[mt][nt], aH[mt], bH[nt]);
                    if (PASSES == 3) {
                        mma16816(acc[mt][nt], aH[mt], bL[nt]);
                        mma16816(acc[mt][nt], aL[mt], bH[nt]);
                    }
                }
        }
    }

    const int erow = lane >> 2, ecol = (lane & 3) << 1;
    #pragma unroll
    for (int mt = 0; mt < 4; mt++) {
        int r0 = bm + wm + (mt << 4) + erow;
        #pragma unroll
        for (int nt = 0; nt < 4; nt++) {
            int c0 = bn + wn + (nt << 3) + ecol;
            if (OUTBF16) {
                __nv_bfloat162 v0, v1;
                v0.x = __float2bfloat16(acc[mt][nt][0]);
                v0.y = __float2bfloat16(acc[mt][nt][1]);
                v1.x = __float2bfloat16(acc[mt][nt][2]);
                v1.y = __float2bfloat16(acc[mt][nt][3]);
                *(__nv_bfloat162*)(Cb + (size_t)r0 * ldc + c0) = v0;
                *(__nv_bfloat162*)(Cb + (size_t)(r0 + 8) * ldc + c0) = v1;
            } else {
                *(float2*)(Cf + (size_t)r0 * ldc + c0) =
                    make_float2(acc[mt][nt][0], acc[mt][nt][1]);
                *(float2*)(Cf + (size_t)(r0 + 8) * ldc + c0) =
                    make_float2(acc[mt][nt][2], acc[mt][nt][3]);
            }
        }
    }
}

// ------------------------------ LayerNorm + bf16 split ---------------------
__global__ void ln_split_kernel(const float* __restrict__ xin, const float* __restrict__ w,
                                const float* __restrict__ bsh,
                                __nv_bfloat16* __restrict__ oh, __nv_bfloat16* __restrict__ ol) {
    int row = blockIdx.x * 8 + (threadIdx.x >> 5);
    int lane = threadIdx.x & 31;
    const float* r = xin + (size_t)row * Dch;
    float v[24];
    float s = 0.f, s2 = 0.f;
    #pragma unroll
    for (int j = 0; j < 24; j++) { float t = r[lane + j*32]; v[j] = t; s += t; s2 += t*t; }
    #pragma unroll
    for (int o = 16; o; o >>= 1) {
        s  += __shfl_xor_sync(0xFFFFFFFFu, s,  o);
        s2 += __shfl_xor_sync(0xFFFFFFFFu, s2, o);
    }
    float mu = s * (1.f/Dch);
    float rs = rsqrtf(s2 * (1.f/Dch) - mu*mu + 1e-5f);
    #pragma unroll
    for (int j = 0; j < 24; j++) {
        int c = lane + j*32;
        float y = (v[j] - mu) * rs * w[c] + bsh[c];
        __nv_bfloat16 h = __float2bfloat16(y);
        oh[(size_t)row*Dch + c] = h;
        ol[(size_t)row*Dch + c] = __float2bfloat16(y - __bfloat162float(h));
    }
}

// ------------------------------ batched weight hi/lo split -----------------
// All 7 weight tensors in one launch. Gate weights pad K 48->64.
#define WSEG_BIG   589824         // 768*768 and 9216*64
#define WSEG_SMALL 196608         // 3072*64
__global__ void wsplit_all_kernel(
    const float* __restrict__ in_proj, const float* __restrict__ outconv,
    const float* __restrict__ outproj, const float* __restrict__ wup,
    const float* __restrict__ lup, const float* __restrict__ uup,
    const float* __restrict__ dcoef,
    __nv_bfloat16* __restrict__ wih, __nv_bfloat16* __restrict__ wil,
    __nv_bfloat16* __restrict__ woh, __nv_bfloat16* __restrict__ wol,
    __nv_bfloat16* __restrict__ wph, __nv_bfloat16* __restrict__ wpl,
    __nv_bfloat16* __restrict__ gwh, __nv_bfloat16* __restrict__ gwl) {
    int idx = blockIdx.x * 256 + threadIdx.x;   // 0 .. 4*WSEG_BIG+3*WSEG_SMALL
    const float* src; __nv_bfloat16 *dh, *dl; int K, Kp, li;
    if (idx < 3 * WSEG_BIG) {
        int seg = idx / WSEG_BIG; li = idx - seg * WSEG_BIG;
        src = (seg == 0) ? in_proj : (seg == 1) ? outconv : outproj;
        dh  = (seg == 0) ? wih : (seg == 1) ? woh : wph;
        dl  = (seg == 0) ? wil : (seg == 1) ? wol : wpl;
        K = Dch; Kp = Dch;
    } else {
        int r = idx - 3 * WSEG_BIG;
        if (r < WSEG_BIG) { src = wup; li = r; dh = gwh; dl = gwl; }
        else {
            r -= WSEG_BIG;
            int seg = r / WSEG_SMALL; li = r - seg * WSEG_SMALL;
            src = (seg == 0) ? lup : (seg == 1) ? uup : dcoef;
            size_t off = (size_t)(3 + seg) * C4 * 64;
            dh = gwh + off; dl = gwl + off;
        }
        K = DS; Kp = 64;
    }
    int m = li / Kp, k = li - m * Kp;
    float v = (k < K) ? src[(size_t)m * K + k] : 0.f;
    __nv_bfloat16 h = __float2bfloat16(v);
    dh[li] = h;
    dl[li] = __float2bfloat16(v - __bfloat162float(h));
}

// ------------------------------ transpose + split (act only) ---------------
__global__ void tconv_kernel(const float* __restrict__ src,
                             __nv_bfloat16* __restrict__ dh, __nv_bfloat16* __restrict__ dl) {
    __shared__ float sm[32][33];
    int n0 = blockIdx.x << 5, k0 = blockIdx.y << 5;
    int tx = threadIdx.x, ty = threadIdx.y;
    float v = src[(size_t)(k0 + ty) * NTOT + n0 + tx];
    sm[ty][tx] = v;
    __syncthreads();
    float y = sm[tx][ty];
    __nv_bfloat16 h = __float2bfloat16(y);
    size_t o = (size_t)(n0 + ty) * Dch + k0 + tx;
    dh[o] = h;
    dl[o] = __float2bfloat16(y - __bfloat162float(h));
}

// ------------------------------ xdown SGEMM + fused remap/split epilogue ---
// xp(48x4096) = Wd(48x768) @ x2(768x4096); writes xpn hi/lo (4096x64),
// token order w-major, rows 48..63 zero-padded.
__global__ __launch_bounds__(256)
void xdown_kernel(const float* __restrict__ W, const float* __restrict__ X,
                  __nv_bfloat16* __restrict__ dh, __nv_bfloat16* __restrict__ dl) {
    __shared__ float As[8][128];
    __shared__ float Bs[8][64];
    const int M = DS, N = NTOT, K = Dch;
    int bn = blockIdx.x * 64;
    int tid = threadIdx.x;
    int arow = tid >> 1, acol = (tid & 1) * 4;
    int brow = tid >> 5, bcol = tid & 31;
    int tm = (tid >> 4) * 8, tn = (tid & 15) * 4;
    float acc[8][4];
    #pragma unroll
    for (int i = 0; i < 8; i++)
        #pragma unroll
        for (int j = 0; j < 4; j++) acc[i][j] = 0.f;
    for (int k0 = 0; k0 < K; k0 += 8) {
        float4 av = make_float4(0.f,0.f,0.f,0.f);
        if (arow < M)
            av = *(const float4*)(W + (size_t)arow*K + k0 + acol);
        As[acol+0][arow] = av.x; As[acol+1][arow] = av.y;
        As[acol+2][arow] = av.z; As[acol+3][arow] = av.w;
        Bs[brow][bcol]    = X[(size_t)(k0+brow)*N + bn + bcol];
        Bs[brow][bcol+32] = X[(size_t)(k0+brow)*N + bn + bcol + 32];
        __syncthreads();
        #pragma unroll
        for (int kk = 0; kk < 8; kk++) {
            float a[8], bb[4];
            *(float4*)(a)   = *(const float4*)&As[kk][tm];
            *(float4*)(a+4) = *(const float4*)&As[kk][tm+4];
            *(float4*)(bb)  = *(const float4*)&Bs[kk][tn];
            #pragma unroll
            for (int i = 0; i < 8; i++)
                #pragma unroll
                for (int j = 0; j < 4; j++)
                    acc[i][j] = fmaf(a[i], bb[j], acc[i][j]);
        }
        __syncthreads();
    }
    // epilogue: rows = K-dim of xpn (0..63; >=48 are zero since A was zero),
    // cols = h-major pixels -> w-major tokens.
    if (tm < 64) {
        #pragma unroll
        for (int i = 0; i < 8; i++) {
            int row = tm + i;
            #pragma unroll
            for (int j = 0; j < 4; j++) {
                int n = bn + tn + j;
                int q = n & 1023;
                int tok = (n & ~1023) + ((q & 31) << 5) + (q >> 5);
                float y = acc[i][j];
                __nv_bfloat16 h = __float2bfloat16(y);
                dh[(size_t)tok*64 + row] = h;
                dl[(size_t)tok*64 + row] = __float2bfloat16(y - __bfloat162float(h));
            }
        }
    }
}

// ------------------------------ dw7 + fused transpose ----------------------
__global__ void dw7_kernel(const float* __restrict__ in, const float* __restrict__ wt,
                           const float* __restrict__ bias,
                           float* __restrict__ out, float* __restrict__ outT) {
    int d = blockIdx.x, b = blockIdx.y;
    __shared__ float sm[38][38];
    __shared__ float wsm[49];
    __shared__ float zt[32][33];
    const float* plane = in + (size_t)d*NTOT + b*NPIX;
    int tid = threadIdx.x;
    if (tid < 49) wsm[tid] = wt[d*49 + tid];
    for (int i = tid; i < 38*38; i += 256) {
        int y = i/38 - 3, x = i%38 - 3;
        sm[i/38][i%38] = (y>=0 && y<32 && x>=0 && x<32) ? plane[y*32+x] : 0.f;
    }
    __syncthreads();
    float bv = bias[d];
    for (int p = tid; p < 1024; p += 256) {
        int y = p >> 5, x = p & 31;
        float acc = bv;
        #pragma unroll
        for (int ky = 0; ky < 7; ky++)
            #pragma unroll
            for (int kx = 0; kx < 7; kx++)
                acc = fmaf(sm[y+ky][x+kx], wsm[ky*7+kx], acc);
        zt[y][x] = acc;
    }
    __syncthreads();
    size_t base = (size_t)d*NTOT + b*NPIX;
    for (int p = tid; p < 1024; p += 256) {
        int y = p >> 5, x = p & 31;
        out [base + p] = zt[y][x];
        outT[base + p] = zt[x][y];
    }
}

__global__ void dw3act_kernel(const float* __restrict__ in, const float* __restrict__ wt,
                              float* __restrict__ out) {
    int d = blockIdx.x, b = blockIdx.y;
    __shared__ float sm[34][34];
    __shared__ float wsm[9];
    const float* plane = in + (size_t)d*NTOT + b*NPIX;
    int tid = threadIdx.x;
    if (tid < 9) wsm[tid] = wt[d*9 + tid];
    for (int i = tid; i < 34*34; i += 256) {
        int y = i/34 - 1, x = i%34 - 1;
        sm[i/34][i%34] = (y>=0 && y<32 && x>=0 && x<32) ? plane[y*32+x] : 0.f;
    }
    __syncthreads();
    for (int p = tid; p < 1024; p += 256) {
        int y = p >> 5, x = p & 31;
        float acc = 0.f;
        #pragma unroll
        for (int ky = 0; ky < 3; ky++)
            #pragma unroll
            for (int kx = 0; kx < 3; kx++)
                acc = fmaf(sm[y+ky][x+kx], wsm[ky*3+kx], acc);
        float z = (acc > 0.f) ? acc*acc : 0.f;
        out[(size_t)d*NTOT + b*NPIX + p] = z;
    }
}

// ------------------------------ scan ---------------------------------------
__global__ void scan_kernel(const __nv_bfloat16* __restrict__ gsig,
                            const float* __restrict__ glud,
                            const float* __restrict__ x2,
                            const float* __restrict__ x2t,
                            const float* __restrict__ mw,
                            float* __restrict__ s4) {
    int c4 = blockIdx.x, b = blockIdx.y;
    int k = c4 / Dch, d = c4 - k*Dch;
    int tid = threadIdx.x;
    int chunk = tid >> 5, h = tid & 31;
    const size_t PS = (size_t)C4 * NTOT;
    const __nv_bfloat16* Gl = gsig + (size_t)c4*NTOT + (size_t)b*NPIX;
    const __nv_bfloat16* Gm = Gl + PS;
    const __nv_bfloat16* Gr = Gl + 2*PS;
    const float* Lp = glud + (size_t)c4*NTOT + (size_t)b*NPIX;
    const float* Up = Lp + PS;
    const float* Dp = Lp + 2*PS;
    const float* xsrc = ((k & 1) ? x2 : x2t) + (size_t)d*NTOT + b*NPIX;
    float mk = mw[k];
    float* outp = s4 + (size_t)c4*NTOT + b*NPIX;
    float hs = 0.f;
    const unsigned mask = 0xFFFFFFFFu;
    #pragma unroll
    for (int pos = 0; pos < 8; pos++) {
        int w  = chunk*8 + pos;
        int q  = w*32 + h;
        int wq = (k >= 2) ? (31 - w) : w;
        float xv = xsrc[wq*32 + h];
        float a  = __bfloat162float(Gl[q]);
        float bb = __bfloat162float(Gm[q]);
        float cc = __bfloat162float(Gr[q]);
        float l  = Lp[q];
        float ea = fast_exp(a), eb = fast_exp(bb), ec = fast_exp(cc);
        float qa = 1.f + ea, qb = 1.f + eb, qc = 1.f + ec;
        float pl = ea*qb*qc, pm = eb*qa*qc, pr = ec*qa*qb;
        float den = pl + pm + pr;
        if (h == 0)  den = pm + pr;
        if (h == 31) den = pl + pm;
        float rd = fast_rcp(den);
        float gl = pl*rd, gm = pm*rd, gr = pr*rd;
        float up = __shfl_up_sync(mask, hs, 1);
        float dn = __shfl_down_sync(mask, hs, 1);
        if (h == 0)  up = 0.f;
        if (h == 31) dn = 0.f;
        hs = fmaf(l, xv, fmaf(gl, up, fmaf(gm, hs, gr*dn)));
        outp[q] = mk * fmaf(hs, Up[q], xv*Dp[q]);
    }
}

// ------------------------------ merge + transpose + bf16 split -------------
__global__ void merge_split_kernel(const float* __restrict__ s4,
                                   __nv_bfloat16* __restrict__ dh,
                                   __nv_bfloat16* __restrict__ dl) {
    __shared__ float sm[32][33];
    int d0 = blockIdx.x << 5, b = blockIdx.y;
    int tx = threadIdx.x, ty = threadIdx.y;
    for (int pg = blockIdx.z * 8; pg < blockIdx.z * 8 + 8; pg++) {
        int q = (pg << 5) + tx;
        float v = 0.f;
        #pragma unroll
        for (int k = 0; k < 4; k++)
            v += s4[(size_t)(k*Dch + d0 + ty)*NTOT + b*NPIX + q];
        sm[ty][tx] = v;
        __syncthreads();
        float y = sm[tx][ty];
        __nv_bfloat16 hh = __float2bfloat16(y);
        size_t o = (size_t)(b*NPIX + (ty << 5) + pg) * Dch + d0 + tx;
        dh[o] = hh;
        dl[o] = __float2bfloat16(y - __bfloat162float(hh));
        __syncthreads();
    }
}

// ------------------------------ launch -------------------------------------
extern "C" void kernel_launch(void* const* d_in, const int* in_sizes, int n_in,
                              void* d_out, int out_size) {
    const float* hidden   = (const float*)d_in[0];
    const float* norm_w   = (const float*)d_in[1];
    const float* norm_b   = (const float*)d_in[2];
    const float* in_proj  = (const float*)d_in[3];
    const float* conv7_w  = (const float*)d_in[4];
    const float* conv7_b  = (const float*)d_in[5];
    const float* xdown_w  = (const float*)d_in[6];
    const float* wup_w    = (const float*)d_in[7];
    const float* lup_w    = (const float*)d_in[8];
    const float* uup_w    = (const float*)d_in[9];
    const float* dcoef_w  = (const float*)d_in[10];
    const float* m_w      = (const float*)d_in[11];
    const float* outconv_w  = (const float*)d_in[12];
    const float* outdconv_w = (const float*)d_in[13];
    const float* outproj_w  = (const float*)d_in[14];
    float* outp = (float*)d_out;

    float *x1,*x2,*x2t,*glud,*s4,*oc,*act;
    __nv_bfloat16 *gsig,*xlnh,*xlnl,*wih,*wil,*woh,*wol,*wph,*wpl,*gwh,*gwl,
                  *xpnh,*xpnl,*mnh,*mnl,*anh,*anl;
    cudaGetSymbolAddress((void**)&x1, g_x1);   cudaGetSymbolAddress((void**)&x2, g_x2);
    cudaGetSymbolAddress((void**)&x2t,g_x2t);
    cudaGetSymbolAddress((void**)&gsig,g_gsig);cudaGetSymbolAddress((void**)&glud,g_glud);
    cudaGetSymbolAddress((void**)&s4, g_s4);   cudaGetSymbolAddress((void**)&oc, g_oc);
    cudaGetSymbolAddress((void**)&act,g_act);
    cudaGetSymbolAddress((void**)&xlnh,g_xlnh);cudaGetSymbolAddress((void**)&xlnl,g_xlnl);
    cudaGetSymbolAddress((void**)&wih,g_wih);  cudaGetSymbolAddress((void**)&wil,g_wil);
    cudaGetSymbolAddress((void**)&woh,g_woh);  cudaGetSymbolAddress((void**)&wol,g_wol);
    cudaGetSymbolAddress((void**)&wph,g_wph);  cudaGetSymbolAddress((void**)&wpl,g_wpl);
    cudaGetSymbolAddress((void**)&gwh,g_gwh);  cudaGetSymbolAddress((void**)&gwl,g_gwl);
    cudaGetSymbolAddress((void**)&xpnh,g_xpnh);cudaGetSymbolAddress((void**)&xpnl,g_xpnl);
    cudaGetSymbolAddress((void**)&mnh,g_mnh);  cudaGetSymbolAddress((void**)&mnl,g_mnl);
    cudaGetSymbolAddress((void**)&anh,g_anh);  cudaGetSymbolAddress((void**)&anl,g_anl);

    const int SMEM3 = 3 * 65536;
    const int SMEM1 = 3 * 32768;
    cudaFuncSetAttribute(mma_gemm<3,0>, cudaFuncAttributeMaxDynamicSharedMemorySize, SMEM3);
    cudaFuncSetAttribute(mma_gemm<1,1>, cudaFuncAttributeMaxDynamicSharedMemorySize, SMEM1);
    dim3 b3232(32, 32);

    // 1) batched weight splits (4*589824 + 3*196608 = 2949120 elems)
    wsplit_all_kernel<<<(4*WSEG_BIG + 3*WSEG_SMALL)/256, 256>>>(
        in_proj, outconv_w, outproj_w, wup_w, lup_w, uup_w, dcoef_w,
        wih, wil, woh, wol, wph, wpl, gwh, gwl);

    // 2) LN -> bf16 hi/lo
    ln_split_kernel<<<NTOT/8, 256>>>(hidden, norm_w, norm_b, xlnh, xlnl);

    // 3) in_proj
    mma_gemm<3,0><<<dim3(NTOT/128, Dch/128), 256, SMEM3>>>(
        wih, wil, xlnh, xlnl, x1, nullptr, Dch, NTOT);

    // 4) dw 7x7 (+ fused w-major transpose)
    dw7_kernel<<<dim3(Dch, Bsz), 256>>>(x1, conv7_w, conv7_b, x2, x2t);

    // 5) xdown + fused remap/split -> xpn hi/lo
    xdown_kernel<<<dim3(NTOT/64, 1), 256>>>(xdown_w, x2, xpnh, xpnl);

    // 6) sigmoid gates: 1-pass bf16 out   <-- profiled launch (ncu -s 5)
    mma_gemm<1,1><<<dim3(NTOT/128, (3*C4)/128), 256, SMEM1>>>(
        gwh, nullptr, xpnh, nullptr, nullptr, gsig, 64, NTOT);

    // 7) L|U|D: 3-pass fp32 out
    mma_gemm<3,0><<<dim3(NTOT/128, (3*C4)/128), 256, SMEM3>>>(
        gwh + (size_t)3*C4*64, gwl + (size_t)3*C4*64, xpnh, xpnl,
        glud, nullptr, 64, NTOT);

    // 8) scan
    scan_kernel<<<dim3(C4, Bsz), 128>>>(gsig, glud, x2, x2t, m_w, s4);

    // 9) merge + transpose + split -> mn hi/lo
    merge_split_kernel<<<dim3(Dch/32, Bsz, 4), b3232>>>(s4, mnh, mnl);

    // 10) outconv
    mma_gemm<3,0><<<dim3(NTOT/128, Dch/128), 256, SMEM3>>>(
        woh, wol, mnh, mnl, oc, nullptr, Dch, NTOT);

    // 11) dw 3x3 + y*relu(y)
    dw3act_kernel<<<dim3(Dch, Bsz), 256>>>(oc, outdconv_w, act);

    // 12) act -> (4096x768) hi/lo
    tconv_kernel<<<dim3(NTOT/32, Dch/32), b3232>>>(act, anh, anl);

    // 13) outproj -> d_out
    mma_gemm<3,0><<<dim3(Dch/128, NTOT/128), 256, SMEM3>>>(
        anh, anl, wph, wpl, outp, nullptr, Dch, Dch);

    // 14) shortcut
    cudaMemcpyAsync(outp + BTD, hidden, (size_t)BTD*sizeof(float),
                    cudaMemcpyDeviceToDevice);
}

// round 6
// speedup vs baseline: 1.4222x; 1.0339x over previous
#include <cuda_runtime.h>
#include <cuda_bf16.h>
#include <cstdint>

// ---------------------------------------------------------------------------
// GSPN block. B=4, T=1024, D=768, HW=32, DS=48, CHUNK=8.
// Round 6: dw-conv strip compute (2.8x fewer LDS); gate GEMMs 1-stage SMEM +
// occupancy bump on the 1-pass gate GEMM.
// ---------------------------------------------------------------------------

#define Bsz   4
#define Dch   768
#define Tlen  1024
#define DS    48
#define NPIX  1024
#define NTOT  4096
#define C4    (4*Dch)         // 3072
#define MG    (6*C4)          // 18432
#define BTD   (Bsz*Tlen*Dch)

// ------------------------- static scratch ----------------------------------
__device__ float g_x1 [(size_t)Dch*NTOT];
__device__ float g_x2 [(size_t)Dch*NTOT];
__device__ float g_x2t[(size_t)Dch*NTOT];
__device__ __nv_bfloat16 g_gsig[(size_t)3*C4*NTOT];
__device__ float g_glud[(size_t)3*C4*NTOT];
__device__ float g_s4 [(size_t)C4*NTOT];
__device__ float g_oc [(size_t)Dch*NTOT];
__device__ float g_act[(size_t)Dch*NTOT];

__device__ __align__(16) __nv_bfloat16 g_xlnh[(size_t)NTOT*Dch], g_xlnl[(size_t)NTOT*Dch];
__device__ __align__(16) __nv_bfloat16 g_wih [Dch*Dch], g_wil [Dch*Dch];
__device__ __align__(16) __nv_bfloat16 g_woh [Dch*Dch], g_wol [Dch*Dch];
__device__ __align__(16) __nv_bfloat16 g_wph [Dch*Dch], g_wpl [Dch*Dch];
__device__ __align__(16) __nv_bfloat16 g_gwh [(size_t)MG*64], g_gwl [(size_t)MG*64];
__device__ __align__(16) __nv_bfloat16 g_xpnh[(size_t)NTOT*64], g_xpnl[(size_t)NTOT*64];
__device__ __align__(16) __nv_bfloat16 g_mnh [(size_t)NTOT*Dch], g_mnl [(size_t)NTOT*Dch];
__device__ __align__(16) __nv_bfloat16 g_anh [(size_t)NTOT*Dch], g_anl [(size_t)NTOT*Dch];

// ------------------------------ helpers ------------------------------------
__device__ __forceinline__ uint32_t smem_u32(const void* p) {
    uint32_t r;
    asm("{ .reg .u64 t; cvta.to.shared.u64 t, %1; cvt.u32.u64 %0, t; }"
        : "=r"(r) : "l"(p));
    return r;
}
__device__ __forceinline__ void cp16(uint32_t saddr, const void* gptr) {
    asm volatile("cp.async.cg.shared.global [%0], [%1], 16;"
        :: "r"(saddr), "l"(gptr));
}
__device__ __forceinline__ void cp_commit() {
    asm volatile("cp.async.commit_group;" ::: "memory");
}
template<int N>
__device__ __forceinline__ void cp_wait() {
    asm volatile("cp.async.wait_group %0;" :: "n"(N) : "memory");
}
__device__ __forceinline__ void ldm4(uint32_t& r0, uint32_t& r1, uint32_t& r2,
                                     uint32_t& r3, uint32_t addr) {
    asm volatile("ldmatrix.sync.aligned.m8n8.x4.shared.b16 {%0,%1,%2,%3}, [%4];"
        : "=r"(r0), "=r"(r1), "=r"(r2), "=r"(r3) : "r"(addr));
}
__device__ __forceinline__ void mma16816(float* c, const uint32_t* a,
                                         const uint32_t* b) {
    asm volatile("mma.sync.aligned.m16n8k16.row.col.f32.bf16.bf16.f32 "
        "{%0,%1,%2,%3}, {%4,%5,%6,%7}, {%8,%9}, {%0,%1,%2,%3};"
        : "+f"(c[0]), "+f"(c[1]), "+f"(c[2]), "+f"(c[3])
        : "r"(a[0]), "r"(a[1]), "r"(a[2]), "r"(a[3]), "r"(b[0]), "r"(b[1]));
}

__device__ __forceinline__ float fast_exp(float x) {
    x = fminf(fmaxf(x, -20.f), 20.f);
    float t = x * 1.4426950408889634f;
    float r = t + 12582912.f;
    int   i = __float_as_int(r) - 0x4B400000;
    float f = t - (r - 12582912.f);
    const float c1=0.69314718056f, c2=0.2402265069f, c3=0.0555041087f,
                c4=0.00961812911f, c5=0.00133335581f;
    float p = fmaf(c5, f, c4);
    p = fmaf(p, f, c3); p = fmaf(p, f, c2); p = fmaf(p, f, c1); p = fmaf(p, f, 1.f);
    return __int_as_float(__float_as_int(p) + (i << 23));
}
__device__ __forceinline__ float fast_rcp(float x) {
    float y = __int_as_float(0x7EF311C3 - __float_as_int(x));
    y = y * (2.0f - x * y);
    y = y * (2.0f - x * y);
    y = y * (2.0f - x * y);
    return y;
}

// ------------------------------ HMMA GEMM ----------------------------------
template<int PASSES, int OUTBF16, int MINCTA>
__global__ __launch_bounds__(256, MINCTA)
void mma_gemm(const __nv_bfloat16* __restrict__ Ahi, const __nv_bfloat16* __restrict__ Alo,
              const __nv_bfloat16* __restrict__ Bhi, const __nv_bfloat16* __restrict__ Blo,
              float* __restrict__ Cf, __nv_bfloat16* __restrict__ Cb,
              int Kp, int ldc) {
    extern __shared__ __align__(16) char dsm[];
    const int SSTAGE = (PASSES == 3) ? 65536 : 32768;
    const int tid  = threadIdx.x;
    const int wid  = tid >> 5, lane = tid & 31;
    const int wm   = (wid >> 2) << 6;
    const int wn   = (wid & 3)  << 5;
    const int bm   = blockIdx.y << 7, bn = blockIdx.x << 7;
    const uint32_t sbase = smem_u32(dsm);
    const int NKB = Kp >> 6;

    const int crow0  = tid >> 1;
    const int cslot0 = (tid & 1) << 2;

    auto load_stage = [&](int buf, int kb) {
        const int k0 = kb << 6;
        uint32_t sb = sbase + buf * SSTAGE;
        const int NPL = (PASSES == 3) ? 4 : 2;
        const __nv_bfloat16* srcs3[4] = {Ahi, Alo, Bhi, Blo};
        const __nv_bfloat16* srcs1[2] = {Ahi, Bhi};
        const int rb3[4] = {bm, bm, bn, bn};
        const int rb1[2] = {bm, bn};
        #pragma unroll
        for (int pl = 0; pl < NPL; pl++) {
            const __nv_bfloat16* src =
                ((PASSES == 3) ? srcs3[pl] : srcs1[pl])
                + (size_t)(((PASSES == 3) ? rb3[pl] : rb1[pl]) + crow0) * Kp + k0;
            uint32_t pbase = sb + (pl << 14) + (crow0 << 7);
            #pragma unroll
            for (int s = 0; s < 4; s++) {
                uint32_t bo = (cslot0 + s) << 4;
                cp16(pbase + (bo ^ ((crow0 & 7) << 4)), src + ((cslot0 + s) << 3));
            }
        }
        cp_commit();
    };

    float acc[4][4][4];
    #pragma unroll
    for (int i = 0; i < 4; i++)
        #pragma unroll
        for (int j = 0; j < 4; j++)
            #pragma unroll
            for (int q = 0; q < 4; q++) acc[i][j][q] = 0.f;

    const int lrow = (lane & 7) + (((lane >> 3) & 1) << 3);
    const int lkof = ((lane >> 4) & 1) << 4;

    load_stage(0, 0);
    if (NKB > 1) load_stage(1, 1);

    for (int kb = 0; kb < NKB; kb++) {
        if (kb < NKB - 1) cp_wait<1>(); else cp_wait<0>();
        __syncthreads();
        if (kb + 2 < NKB) {
            int dst = kb + 2;
            load_stage(dst - (dst / 3) * 3, dst);
        }

        uint32_t sb = sbase + (kb - (kb / 3) * 3) * SSTAGE;
        uint32_t aHb = sb;
        uint32_t aLb = sb + 16384;
        uint32_t bHb = (PASSES == 3) ? sb + 32768 : sb + 16384;
        uint32_t bLb = sb + 49152;

        #pragma unroll
        for (int ks = 0; ks < 4; ks++) {
            uint32_t aH[4][4], aL[4][4], bH[4][2], bL[4][2];
            #pragma unroll
            for (int mt = 0; mt < 4; mt++) {
                int row = wm + (mt << 4) + lrow;
                uint32_t co = (uint32_t)(((ks << 5) + lkof) ^ ((row & 7) << 4));
                uint32_t off = ((uint32_t)row << 7) + co;
                ldm4(aH[mt][0], aH[mt][1], aH[mt][2], aH[mt][3], aHb + off);
                if (PASSES == 3)
                    ldm4(aL[mt][0], aL[mt][1], aL[mt][2], aL[mt][3], aLb + off);
            }
            #pragma unroll
            for (int nt2 = 0; nt2 < 2; nt2++) {
                int row = wn + (nt2 << 4) + lrow;
                uint32_t co = (uint32_t)(((ks << 5) + lkof) ^ ((row & 7) << 4));
                uint32_t off = ((uint32_t)row << 7) + co;
                uint32_t r0, r1, r2, r3;
                ldm4(r0, r1, r2, r3, bHb + off);
                bH[2*nt2][0] = r0; bH[2*nt2][1] = r2;
                bH[2*nt2+1][0] = r1; bH[2*nt2+1][1] = r3;
                if (PASSES == 3) {
                    ldm4(r0, r1, r2, r3, bLb + off);
                    bL[2*nt2][0] = r0; bL[2*nt2][1] = r2;
                    bL[2*nt2+1][0] = r1; bL[2*nt2+1][1] = r3;
                }
            }
            #pragma unroll
            for (int mt = 0; mt < 4; mt++)
                #pragma unroll
                for (int nt = 0; nt < 4; nt++) {
                    mma16816(acc[mt][nt], aH[mt], bH[nt]);
                    if (PASSES == 3) {
                        mma16816(acc[mt][nt], aH[mt], bL[nt]);
                        mma16816(acc[mt][nt], aL[mt], bH[nt]);
                    }
                }
        }
    }

    const int erow = lane >> 2, ecol = (lane & 3) << 1;
    #pragma unroll
    for (int mt = 0; mt < 4; mt++) {
        int r0 = bm + wm + (mt << 4) + erow;
        #pragma unroll
        for (int nt = 0; nt < 4; nt++) {
            int c0 = bn + wn + (nt << 3) + ecol;
            if (OUTBF16) {
                __nv_bfloat162 v0, v1;
                v0.x = __float2bfloat16(acc[mt][nt][0]);
                v0.y = __float2bfloat16(acc[mt][nt][1]);
                v1.x = __float2bfloat16(acc[mt][nt][2]);
                v1.y = __float2bfloat16(acc[mt][nt][3]);
                *(__nv_bfloat162*)(Cb + (size_t)r0 * ldc + c0) = v0;
                *(__nv_bfloat162*)(Cb + (size_t)(r0 + 8) * ldc + c0) = v1;
            } else {
                *(float2*)(Cf + (size_t)r0 * ldc + c0) =
                    make_float2(acc[mt][nt][0], acc[mt][nt][1]);
                *(float2*)(Cf + (size_t)(r0 + 8) * ldc + c0) =
                    make_float2(acc[mt][nt][2], acc[mt][nt][3]);
            }
        }
    }
}

// ------------------------------ LayerNorm + bf16 split ---------------------
__global__ void ln_split_kernel(const float* __restrict__ xin, const float* __restrict__ w,
                                const float* __restrict__ bsh,
                                __nv_bfloat16* __restrict__ oh, __nv_bfloat16* __restrict__ ol) {
    int row = blockIdx.x * 8 + (threadIdx.x >> 5);
    int lane = threadIdx.x & 31;
    const float* r = xin + (size_t)row * Dch;
    float v[24];
    float s = 0.f, s2 = 0.f;
    #pragma unroll
    for (int j = 0; j < 24; j++) { float t = r[lane + j*32]; v[j] = t; s += t; s2 += t*t; }
    #pragma unroll
    for (int o = 16; o; o >>= 1) {
        s  += __shfl_xor_sync(0xFFFFFFFFu, s,  o);
        s2 += __shfl_xor_sync(0xFFFFFFFFu, s2, o);
    }
    float mu = s * (1.f/Dch);
    float rs = rsqrtf(s2 * (1.f/Dch) - mu*mu + 1e-5f);
    #pragma unroll
    for (int j = 0; j < 24; j++) {
        int c = lane + j*32;
        float y = (v[j] - mu) * rs * w[c] + bsh[c];
        __nv_bfloat16 h = __float2bfloat16(y);
        oh[(size_t)row*Dch + c] = h;
        ol[(size_t)row*Dch + c] = __float2bfloat16(y - __bfloat162float(h));
    }
}

// ------------------------------ batched weight hi/lo split -----------------
#define WSEG_BIG   589824
#define WSEG_SMALL 196608
__global__ void wsplit_all_kernel(
    const float* __restrict__ in_proj, const float* __restrict__ outconv,
    const float* __restrict__ outproj, const float* __restrict__ wup,
    const float* __restrict__ lup, const float* __restrict__ uup,
    const float* __restrict__ dcoef,
    __nv_bfloat16* __restrict__ wih, __nv_bfloat16* __restrict__ wil,
    __nv_bfloat16* __restrict__ woh, __nv_bfloat16* __restrict__ wol,
    __nv_bfloat16* __restrict__ wph, __nv_bfloat16* __restrict__ wpl,
    __nv_bfloat16* __restrict__ gwh, __nv_bfloat16* __restrict__ gwl) {
    int idx = blockIdx.x * 256 + threadIdx.x;
    const float* src; __nv_bfloat16 *dh, *dl; int K, Kp, li;
    if (idx < 3 * WSEG_BIG) {
        int seg = idx / WSEG_BIG; li = idx - seg * WSEG_BIG;
        src = (seg == 0) ? in_proj : (seg == 1) ? outconv : outproj;
        dh  = (seg == 0) ? wih : (seg == 1) ? woh : wph;
        dl  = (seg == 0) ? wil : (seg == 1) ? wol : wpl;
        K = Dch; Kp = Dch;
    } else {
        int r = idx - 3 * WSEG_BIG;
        if (r < WSEG_BIG) { src = wup; li = r; dh = gwh; dl = gwl; }
        else {
            r -= WSEG_BIG;
            int seg = r / WSEG_SMALL; li = r - seg * WSEG_SMALL;
            src = (seg == 0) ? lup : (seg == 1) ? uup : dcoef;
            size_t off = (size_t)(3 + seg) * C4 * 64;
            dh = gwh + off; dl = gwl + off;
        }
        K = DS; Kp = 64;
    }
    int m = li / Kp, k = li - m * Kp;
    float v = (k < K) ? src[(size_t)m * K + k] : 0.f;
    __nv_bfloat16 h = __float2bfloat16(v);
    dh[li] = h;
    dl[li] = __float2bfloat16(v - __bfloat162float(h));
}

// ------------------------------ transpose + split (act) --------------------
__global__ void tconv_kernel(const float* __restrict__ src,
                             __nv_bfloat16* __restrict__ dh, __nv_bfloat16* __restrict__ dl) {
    __shared__ float sm[32][33];
    int n0 = blockIdx.x << 5, k0 = blockIdx.y << 5;
    int tx = threadIdx.x, ty = threadIdx.y;
    float v = src[(size_t)(k0 + ty) * NTOT + n0 + tx];
    sm[ty][tx] = v;
    __syncthreads();
    float y = sm[tx][ty];
    __nv_bfloat16 h = __float2bfloat16(y);
    size_t o = (size_t)(n0 + ty) * Dch + k0 + tx;
    dh[o] = h;
    dl[o] = __float2bfloat16(y - __bfloat162float(h));
}

// ------------------------------ xdown + fused remap/split ------------------
__global__ __launch_bounds__(256)
void xdown_kernel(const float* __restrict__ W, const float* __restrict__ X,
                  __nv_bfloat16* __restrict__ dh, __nv_bfloat16* __restrict__ dl) {
    __shared__ float As[8][128];
    __shared__ float Bs[8][64];
    const int M = DS, N = NTOT, K = Dch;
    int bn = blockIdx.x * 64;
    int tid = threadIdx.x;
    int arow = tid >> 1, acol = (tid & 1) * 4;
    int brow = tid >> 5, bcol = tid & 31;
    int tm = (tid >> 4) * 8, tn = (tid & 15) * 4;
    float acc[8][4];
    #pragma unroll
    for (int i = 0; i < 8; i++)
        #pragma unroll
        for (int j = 0; j < 4; j++) acc[i][j] = 0.f;
    for (int k0 = 0; k0 < K; k0 += 8) {
        float4 av = make_float4(0.f,0.f,0.f,0.f);
        if (arow < M)
            av = *(const float4*)(W + (size_t)arow*K + k0 + acol);
        As[acol+0][arow] = av.x; As[acol+1][arow] = av.y;
        As[acol+2][arow] = av.z; As[acol+3][arow] = av.w;
        Bs[brow][bcol]    = X[(size_t)(k0+brow)*N + bn + bcol];
        Bs[brow][bcol+32] = X[(size_t)(k0+brow)*N + bn + bcol + 32];
        __syncthreads();
        #pragma unroll
        for (int kk = 0; kk < 8; kk++) {
            float a[8], bb[4];
            *(float4*)(a)   = *(const float4*)&As[kk][tm];
            *(float4*)(a+4) = *(const float4*)&As[kk][tm+4];
            *(float4*)(bb)  = *(const float4*)&Bs[kk][tn];
            #pragma unroll
            for (int i = 0; i < 8; i++)
                #pragma unroll
                for (int j = 0; j < 4; j++)
                    acc[i][j] = fmaf(a[i], bb[j], acc[i][j]);
        }
        __syncthreads();
    }
    if (tm < 64) {
        #pragma unroll
        for (int i = 0; i < 8; i++) {
            int row = tm + i;
            #pragma unroll
            for (int j = 0; j < 4; j++) {
                int n = bn + tn + j;
                int q = n & 1023;
                int tok = (n & ~1023) + ((q & 31) << 5) + (q >> 5);
                float y = acc[i][j];
                __nv_bfloat16 h = __float2bfloat16(y);
                dh[(size_t)tok*64 + row] = h;
                dl[(size_t)tok*64 + row] = __float2bfloat16(y - __bfloat162float(h));
            }
        }
    }
}

// ------------------------------ dw7: 1x4 strips + fused transpose ----------
__global__ void dw7_kernel(const float* __restrict__ in, const float* __restrict__ wt,
                           const float* __restrict__ bias,
                           float* __restrict__ out, float* __restrict__ outT) {
    int d = blockIdx.x, b = blockIdx.y;
    __shared__ float sm[38][39];
    __shared__ float wsm[49];
    __shared__ float zt[32][33];
    const float* plane = in + (size_t)d*NTOT + b*NPIX;
    int tid = threadIdx.x;
    if (tid < 49) wsm[tid] = wt[d*49 + tid];
    for (int i = tid; i < 38*38; i += 256) {
        int y = i/38, x = i - y*38;
        int yy = y - 3, xx = x - 3;
        sm[y][x] = (yy>=0 && yy<32 && xx>=0 && xx<32) ? plane[yy*32+xx] : 0.f;
    }
    __syncthreads();
    float bv = bias[d];
    int y  = tid >> 3;
    int x0 = (tid & 7) << 2;
    float a0 = bv, a1 = bv, a2 = bv, a3 = bv;
    #pragma unroll
    for (int ky = 0; ky < 7; ky++) {
        float r[10];
        #pragma unroll
        for (int i = 0; i < 10; i++) r[i] = sm[y+ky][x0+i];
        #pragma unroll
        for (int kx = 0; kx < 7; kx++) {
            float wv = wsm[ky*7+kx];
            a0 = fmaf(r[kx],   wv, a0);
            a1 = fmaf(r[kx+1], wv, a1);
            a2 = fmaf(r[kx+2], wv, a2);
            a3 = fmaf(r[kx+3], wv, a3);
        }
    }
    zt[y][x0] = a0; zt[y][x0+1] = a1; zt[y][x0+2] = a2; zt[y][x0+3] = a3;
    __syncthreads();
    size_t base = (size_t)d*NTOT + b*NPIX;
    for (int p = tid; p < 1024; p += 256) {
        int yy = p >> 5, xx = p & 31;
        out [base + p] = zt[yy][xx];
        outT[base + p] = zt[xx][yy];
    }
}

// ------------------------------ dw3 + y*relu(y): 1x4 strips ----------------
__global__ void dw3act_kernel(const float* __restrict__ in, const float* __restrict__ wt,
                              float* __restrict__ out) {
    int d = blockIdx.x, b = blockIdx.y;
    __shared__ float sm[34][35];
    __shared__ float wsm[9];
    const float* plane = in + (size_t)d*NTOT + b*NPIX;
    int tid = threadIdx.x;
    if (tid < 9) wsm[tid] = wt[d*9 + tid];
    for (int i = tid; i < 34*34; i += 256) {
        int y = i/34, x = i - y*34;
        int yy = y - 1, xx = x - 1;
        sm[y][x] = (yy>=0 && yy<32 && xx>=0 && xx<32) ? plane[yy*32+xx] : 0.f;
    }
    __syncthreads();
    int y  = tid >> 3;
    int x0 = (tid & 7) << 2;
    float a0 = 0.f, a1 = 0.f, a2 = 0.f, a3 = 0.f;
    #pragma unroll
    for (int ky = 0; ky < 3; ky++) {
        float r[6];
        #pragma unroll
        for (int i = 0; i < 6; i++) r[i] = sm[y+ky][x0+i];
        #pragma unroll
        for (int kx = 0; kx < 3; kx++) {
            float wv = wsm[ky*3+kx];
            a0 = fmaf(r[kx],   wv, a0);
            a1 = fmaf(r[kx+1], wv, a1);
            a2 = fmaf(r[kx+2], wv, a2);
            a3 = fmaf(r[kx+3], wv, a3);
        }
    }
    float z0 = (a0 > 0.f) ? a0*a0 : 0.f;
    float z1 = (a1 > 0.f) ? a1*a1 : 0.f;
    float z2 = (a2 > 0.f) ? a2*a2 : 0.f;
    float z3 = (a3 > 0.f) ? a3*a3 : 0.f;
    float* o = out + (size_t)d*NTOT + b*NPIX + (y << 5) + x0;
    o[0] = z0; o[1] = z1; o[2] = z2; o[3] = z3;
}

// ------------------------------ scan ---------------------------------------
__global__ void scan_kernel(const __nv_bfloat16* __restrict__ gsig,
                            const float* __restrict__ glud,
                            const float* __restrict__ x2,
                            const float* __restrict__ x2t,
                            const float* __restrict__ mw,
                            float* __restrict__ s4) {
    int c4 = blockIdx.x, b = blockIdx.y;
    int k = c4 / Dch, d = c4 - k*Dch;
    int tid = threadIdx.x;
    int chunk = tid >> 5, h = tid & 31;
    const size_t PS = (size_t)C4 * NTOT;
    const __nv_bfloat16* Gl = gsig + (size_t)c4*NTOT + (size_t)b*NPIX;
    const __nv_bfloat16* Gm = Gl + PS;
    const __nv_bfloat16* Gr = Gl + 2*PS;
    const float* Lp = glud + (size_t)c4*NTOT + (size_t)b*NPIX;
    const float* Up = Lp + PS;
    const float* Dp = Lp + 2*PS;
    const float* xsrc = ((k & 1) ? x2 : x2t) + (size_t)d*NTOT + b*NPIX;
    float mk = mw[k];
    float* outp = s4 + (size_t)c4*NTOT + b*NPIX;
    float hs = 0.f;
    const unsigned mask = 0xFFFFFFFFu;
    #pragma unroll
    for (int pos = 0; pos < 8; pos++) {
        int w  = chunk*8 + pos;
        int q  = w*32 + h;
        int wq = (k >= 2) ? (31 - w) : w;
        float xv = xsrc[wq*32 + h];
        float a  = __bfloat162float(Gl[q]);
        float bb = __bfloat162float(Gm[q]);
        float cc = __bfloat162float(Gr[q]);
        float l  = Lp[q];
        float ea = fast_exp(a), eb = fast_exp(bb), ec = fast_exp(cc);
        float qa = 1.f + ea, qb = 1.f + eb, qc = 1.f + ec;
        float pl = ea*qb*qc, pm = eb*qa*qc, pr = ec*qa*qb;
        float den = pl + pm + pr;
        if (h == 0)  den = pm + pr;
        if (h == 31) den = pl + pm;
        float rd = fast_rcp(den);
        float gl = pl*rd, gm = pm*rd, gr = pr*rd;
        float up = __shfl_up_sync(mask, hs, 1);
        float dn = __shfl_down_sync(mask, hs, 1);
        if (h == 0)  up = 0.f;
        if (h == 31) dn = 0.f;
        hs = fmaf(l, xv, fmaf(gl, up, fmaf(gm, hs, gr*dn)));
        outp[q] = mk * fmaf(hs, Up[q], xv*Dp[q]);
    }
}

// ------------------------------ merge + transpose + bf16 split -------------
__global__ void merge_split_kernel(const float* __restrict__ s4,
                                   __nv_bfloat16* __restrict__ dh,
                                   __nv_bfloat16* __restrict__ dl) {
    __shared__ float sm[32][33];
    int d0 = blockIdx.x << 5, b = blockIdx.y;
    int tx = threadIdx.x, ty = threadIdx.y;
    for (int pg = blockIdx.z * 8; pg < blockIdx.z * 8 + 8; pg++) {
        int q = (pg << 5) + tx;
        float v = 0.f;
        #pragma unroll
        for (int k = 0; k < 4; k++)
            v += s4[(size_t)(k*Dch + d0 + ty)*NTOT + b*NPIX + q];
        sm[ty][tx] = v;
        __syncthreads();
        float y = sm[tx][ty];
        __nv_bfloat16 hh = __float2bfloat16(y);
        size_t o = (size_t)(b*NPIX + (ty << 5) + pg) * Dch + d0 + tx;
        dh[o] = hh;
        dl[o] = __float2bfloat16(y - __bfloat162float(hh));
        __syncthreads();
    }
}

// ------------------------------ launch -------------------------------------
extern "C" void kernel_launch(void* const* d_in, const int* in_sizes, int n_in,
                              void* d_out, int out_size) {
    const float* hidden   = (const float*)d_in[0];
    const float* norm_w   = (const float*)d_in[1];
    const float* norm_b   = (const float*)d_in[2];
    const float* in_proj  = (const float*)d_in[3];
    const float* conv7_w  = (const float*)d_in[4];
    const float* conv7_b  = (const float*)d_in[5];
    const float* xdown_w  = (const float*)d_in[6];
    const float* wup_w    = (const float*)d_in[7];
    const float* lup_w    = (const float*)d_in[8];
    const float* uup_w    = (const float*)d_in[9];
    const float* dcoef_w  = (const float*)d_in[10];
    const float* m_w      = (const float*)d_in[11];
    const float* outconv_w  = (const float*)d_in[12];
    const float* outdconv_w = (const float*)d_in[13];
    const float* outproj_w  = (const float*)d_in[14];
    float* outp = (float*)d_out;

    float *x1,*x2,*x2t,*glud,*s4,*oc,*act;
    __nv_bfloat16 *gsig,*xlnh,*xlnl,*wih,*wil,*woh,*wol,*wph,*wpl,*gwh,*gwl,
                  *xpnh,*xpnl,*mnh,*mnl,*anh,*anl;
    cudaGetSymbolAddress((void**)&x1, g_x1);   cudaGetSymbolAddress((void**)&x2, g_x2);
    cudaGetSymbolAddress((void**)&x2t,g_x2t);
    cudaGetSymbolAddress((void**)&gsig,g_gsig);cudaGetSymbolAddress((void**)&glud,g_glud);
    cudaGetSymbolAddress((void**)&s4, g_s4);   cudaGetSymbolAddress((void**)&oc, g_oc);
    cudaGetSymbolAddress((void**)&act,g_act);
    cudaGetSymbolAddress((void**)&xlnh,g_xlnh);cudaGetSymbolAddress((void**)&xlnl,g_xlnl);
    cudaGetSymbolAddress((void**)&wih,g_wih);  cudaGetSymbolAddress((void**)&wil,g_wil);
    cudaGetSymbolAddress((void**)&woh,g_woh);  cudaGetSymbolAddress((void**)&wol,g_wol);
    cudaGetSymbolAddress((void**)&wph,g_wph);  cudaGetSymbolAddress((void**)&wpl,g_wpl);
    cudaGetSymbolAddress((void**)&gwh,g_gwh);  cudaGetSymbolAddress((void**)&gwl,g_gwl);
    cudaGetSymbolAddress((void**)&xpnh,g_xpnh);cudaGetSymbolAddress((void**)&xpnl,g_xpnl);
    cudaGetSymbolAddress((void**)&mnh,g_mnh);  cudaGetSymbolAddress((void**)&mnl,g_mnl);
    cudaGetSymbolAddress((void**)&anh,g_anh);  cudaGetSymbolAddress((void**)&anl,g_anl);

    const int SMEM3_PIPE = 3 * 65536;    // K>64: 3-stage
    const int SMEM3_ONE  = 1 * 65536;    // K=64: single stage
    const int SMEM1_ONE  = 1 * 32768;
    cudaFuncSetAttribute(mma_gemm<3,0,1>, cudaFuncAttributeMaxDynamicSharedMemorySize, SMEM3_PIPE);
    cudaFuncSetAttribute(mma_gemm<1,1,2>, cudaFuncAttributeMaxDynamicSharedMemorySize, SMEM1_ONE);
    dim3 b3232(32, 32);

    // 1) batched weight splits
    wsplit_all_kernel<<<(4*WSEG_BIG + 3*WSEG_SMALL)/256, 256>>>(
        in_proj, outconv_w, outproj_w, wup_w, lup_w, uup_w, dcoef_w,
        wih, wil, woh, wol, wph, wpl, gwh, gwl);

    // 2) LN -> bf16 hi/lo
    ln_split_kernel<<<NTOT/8, 256>>>(hidden, norm_w, norm_b, xlnh, xlnl);

    // 3) in_proj
    mma_gemm<3,0,1><<<dim3(NTOT/128, Dch/128), 256, SMEM3_PIPE>>>(
        wih, wil, xlnh, xlnl, x1, nullptr, Dch, NTOT);

    // 4) dw 7x7 (+ fused w-major transpose)
    dw7_kernel<<<dim3(Dch, Bsz), 256>>>(x1, conv7_w, conv7_b, x2, x2t);

    // 5) xdown + fused remap/split -> xpn hi/lo
    xdown_kernel<<<dim3(NTOT/64, 1), 256>>>(xdown_w, x2, xpnh, xpnl);

    // 6) sigmoid gates: 1-pass bf16 out, 1-stage smem, 2 CTA/SM
    mma_gemm<1,1,2><<<dim3(NTOT/128, (3*C4)/128), 256, SMEM1_ONE>>>(
        gwh, nullptr, xpnh, nullptr, nullptr, gsig, 64, NTOT);

    // 7) L|U|D: 3-pass fp32 out, 1-stage smem
    mma_gemm<3,0,1><<<dim3(NTOT/128, (3*C4)/128), 256, SMEM3_ONE>>>(
        gwh + (size_t)3*C4*64, gwl + (size_t)3*C4*64, xpnh, xpnl,
        glud, nullptr, 64, NTOT);

    // 8) scan
    scan_kernel<<<dim3(C4, Bsz), 128>>>(gsig, glud, x2, x2t, m_w, s4);

    // 9) merge + transpose + split -> mn hi/lo
    merge_split_kernel<<<dim3(Dch/32, Bsz, 4), b3232>>>(s4, mnh, mnl);

    // 10) outconv
    mma_gemm<3,0,1><<<dim3(NTOT/128, Dch/128), 256, SMEM3_PIPE>>>(
        woh, wol, mnh, mnl, oc, nullptr, Dch, NTOT);

    // 11) dw 3x3 + y*relu(y)
    dw3act_kernel<<<dim3(Dch, Bsz), 256>>>(oc, outdconv_w, act);

    // 12) act -> (4096x768) hi/lo
    tconv_kernel<<<dim3(NTOT/32, Dch/32), b3232>>>(act, anh, anl);

    // 13) outproj -> d_out
    mma_gemm<3,0,1><<<dim3(Dch/128, NTOT/128), 256, SMEM3_PIPE>>>(
        anh, anl, wph, wpl, outp, nullptr, Dch, Dch);

    // 14) shortcut
    cudaMemcpyAsync(outp + BTD, hidden, (size_t)BTD*sizeof(float),
                    cudaMemcpyDeviceToDevice);
}

// round 7
// speedup vs baseline: 1.5227x; 1.0707x over previous
#include <cuda_runtime.h>
#include <cuda_bf16.h>
#include <cstdint>

// ---------------------------------------------------------------------------
// GSPN block. B=4, T=1024, D=768, HW=32, DS=48, CHUNK=8.
// Round 7: BK=32 GEMM with 2 CTA/SM; vectorized dw epilogues; profile order.
// ---------------------------------------------------------------------------

#define Bsz   4
#define Dch   768
#define Tlen  1024
#define DS    48
#define NPIX  1024
#define NTOT  4096
#define C4    (4*Dch)         // 3072
#define MG    (6*C4)          // 18432
#define BTD   (Bsz*Tlen*Dch)

// ------------------------- static scratch ----------------------------------
__device__ float g_x1 [(size_t)Dch*NTOT];
__device__ float g_x2 [(size_t)Dch*NTOT];
__device__ float g_x2t[(size_t)Dch*NTOT];
__device__ __nv_bfloat16 g_gsig[(size_t)3*C4*NTOT];
__device__ float g_glud[(size_t)3*C4*NTOT];
__device__ float g_s4 [(size_t)C4*NTOT];
__device__ float g_oc [(size_t)Dch*NTOT];
__device__ float g_act[(size_t)Dch*NTOT];

__device__ __align__(16) __nv_bfloat16 g_xlnh[(size_t)NTOT*Dch], g_xlnl[(size_t)NTOT*Dch];
__device__ __align__(16) __nv_bfloat16 g_wih [Dch*Dch], g_wil [Dch*Dch];
__device__ __align__(16) __nv_bfloat16 g_woh [Dch*Dch], g_wol [Dch*Dch];
__device__ __align__(16) __nv_bfloat16 g_wph [Dch*Dch], g_wpl [Dch*Dch];
__device__ __align__(16) __nv_bfloat16 g_gwh [(size_t)MG*64], g_gwl [(size_t)MG*64];
__device__ __align__(16) __nv_bfloat16 g_xpnh[(size_t)NTOT*64], g_xpnl[(size_t)NTOT*64];
__device__ __align__(16) __nv_bfloat16 g_mnh [(size_t)NTOT*Dch], g_mnl [(size_t)NTOT*Dch];
__device__ __align__(16) __nv_bfloat16 g_anh [(size_t)NTOT*Dch], g_anl [(size_t)NTOT*Dch];

// ------------------------------ helpers ------------------------------------
__device__ __forceinline__ uint32_t smem_u32(const void* p) {
    uint32_t r;
    asm("{ .reg .u64 t; cvta.to.shared.u64 t, %1; cvt.u32.u64 %0, t; }"
        : "=r"(r) : "l"(p));
    return r;
}
__device__ __forceinline__ void cp16(uint32_t saddr, const void* gptr) {
    asm volatile("cp.async.cg.shared.global [%0], [%1], 16;"
        :: "r"(saddr), "l"(gptr));
}
__device__ __forceinline__ void cp_commit() {
    asm volatile("cp.async.commit_group;" ::: "memory");
}
template<int N>
__device__ __forceinline__ void cp_wait() {
    asm volatile("cp.async.wait_group %0;" :: "n"(N) : "memory");
}
__device__ __forceinline__ void ldm4(uint32_t& r0, uint32_t& r1, uint32_t& r2,
                                     uint32_t& r3, uint32_t addr) {
    asm volatile("ldmatrix.sync.aligned.m8n8.x4.shared.b16 {%0,%1,%2,%3}, [%4];"
        : "=r"(r0), "=r"(r1), "=r"(r2), "=r"(r3) : "r"(addr));
}
__device__ __forceinline__ void mma16816(float* c, const uint32_t* a,
                                         const uint32_t* b) {
    asm volatile("mma.sync.aligned.m16n8k16.row.col.f32.bf16.bf16.f32 "
        "{%0,%1,%2,%3}, {%4,%5,%6,%7}, {%8,%9}, {%0,%1,%2,%3};"
        : "+f"(c[0]), "+f"(c[1]), "+f"(c[2]), "+f"(c[3])
        : "r"(a[0]), "r"(a[1]), "r"(a[2]), "r"(a[3]), "r"(b[0]), "r"(b[1]));
}

__device__ __forceinline__ float fast_exp(float x) {
    x = fminf(fmaxf(x, -20.f), 20.f);
    float t = x * 1.4426950408889634f;
    float r = t + 12582912.f;
    int   i = __float_as_int(r) - 0x4B400000;
    float f = t - (r - 12582912.f);
    const float c1=0.69314718056f, c2=0.2402265069f, c3=0.0555041087f,
                c4=0.00961812911f, c5=0.00133335581f;
    float p = fmaf(c5, f, c4);
    p = fmaf(p, f, c3); p = fmaf(p, f, c2); p = fmaf(p, f, c1); p = fmaf(p, f, 1.f);
    return __int_as_float(__float_as_int(p) + (i << 23));
}
__device__ __forceinline__ float fast_rcp(float x) {
    float y = __int_as_float(0x7EF311C3 - __float_as_int(x));
    y = y * (2.0f - x * y);
    y = y * (2.0f - x * y);
    y = y * (2.0f - x * y);
    return y;
}

// ------------------------------ HMMA GEMM (BK=32, 2 CTA/SM) ----------------
// C(MxN) = hi/lo passes of A(MxKp) @ B(NxKp)^T, bf16 K-major. M,N mult of 128,
// Kp mult of 32. Stage: PLANES x 8KB (128 rows x 64B), swizzle c ^= (r>>1)&3.
template<int PASSES, int OUTBF16>
__global__ __launch_bounds__(256, 2)
void mma_gemm(const __nv_bfloat16* __restrict__ Ahi, const __nv_bfloat16* __restrict__ Alo,
              const __nv_bfloat16* __restrict__ Bhi, const __nv_bfloat16* __restrict__ Blo,
              float* __restrict__ Cf, __nv_bfloat16* __restrict__ Cb,
              int Kp, int ldc) {
    extern __shared__ __align__(16) char dsm[];
    const int PLANES = (PASSES == 3) ? 4 : 2;
    const int SSTAGE = PLANES * 8192;
    const int tid  = threadIdx.x;
    const int wid  = tid >> 5, lane = tid & 31;
    const int wm   = (wid >> 2) << 6;
    const int wn   = (wid & 3)  << 5;
    const int bm   = blockIdx.y << 7, bn = blockIdx.x << 7;
    const uint32_t sbase = smem_u32(dsm);
    const int NKB = Kp >> 5;

    const int lrow_ = tid >> 1;           // loader row 0..127
    const int lc0   = (tid & 1) << 1;     // loader chunk base 0/2
    const uint32_t lswz = (lrow_ >> 1) & 3;

    auto load_stage = [&](int buf, int kb) {
        const int k0 = kb << 5;
        uint32_t sb = sbase + buf * SSTAGE;
        const __nv_bfloat16* srcs3[4] = {Ahi, Alo, Bhi, Blo};
        const __nv_bfloat16* srcs1[2] = {Ahi, Bhi};
        const int rb3[4] = {bm, bm, bn, bn};
        const int rb1[2] = {bm, bn};
        #pragma unroll
        for (int pl = 0; pl < PLANES; pl++) {
            const __nv_bfloat16* src =
                ((PASSES == 3) ? srcs3[pl] : srcs1[pl])
                + (size_t)(((PASSES == 3) ? rb3[pl] : rb1[pl]) + lrow_) * Kp + k0;
            uint32_t pbase = sb + (pl << 13) + (lrow_ << 6);
            #pragma unroll
            for (int s = 0; s < 2; s++) {
                uint32_t c = lc0 + s;
                cp16(pbase + ((c ^ lswz) << 4), src + (c << 3));
            }
        }
        cp_commit();
    };

    float acc[4][4][4];
    #pragma unroll
    for (int i = 0; i < 4; i++)
        #pragma unroll
        for (int j = 0; j < 4; j++)
            #pragma unroll
            for (int q = 0; q < 4; q++) acc[i][j][q] = 0.f;

    const int lrow = (lane & 7) + (((lane >> 3) & 1) << 3);
    const int lchunk = (lane >> 4) & 1;

    load_stage(0, 0);
    if (NKB > 1) load_stage(1, 1);

    for (int kb = 0; kb < NKB; kb++) {
        if (kb < NKB - 1) cp_wait<1>(); else cp_wait<0>();
        __syncthreads();
        if (kb + 2 < NKB) {
            int dst = kb + 2;
            load_stage(dst - (dst / 3) * 3, dst);
        }

        uint32_t sb = sbase + (kb - (kb / 3) * 3) * SSTAGE;
        uint32_t aHb = sb;
        uint32_t aLb = sb + 8192;
        uint32_t bHb = (PASSES == 3) ? sb + 16384 : sb + 8192;
        uint32_t bLb = sb + 24576;

        #pragma unroll
        for (int ks = 0; ks < 2; ks++) {
            uint32_t bH[4][2], bL[4][2];
            #pragma unroll
            for (int nt2 = 0; nt2 < 2; nt2++) {
                int r = wn + (nt2 << 4) + lrow;
                uint32_t c = (uint32_t)((ks << 1) + lchunk);
                uint32_t off = ((uint32_t)r << 6) + (((c ^ ((r >> 1) & 3)) << 4));
                uint32_t r0, r1, r2, r3;
                ldm4(r0, r1, r2, r3, bHb + off);
                bH[2*nt2][0] = r0; bH[2*nt2][1] = r2;
                bH[2*nt2+1][0] = r1; bH[2*nt2+1][1] = r3;
                if (PASSES == 3) {
                    ldm4(r0, r1, r2, r3, bLb + off);
                    bL[2*nt2][0] = r0; bL[2*nt2][1] = r2;
                    bL[2*nt2+1][0] = r1; bL[2*nt2+1][1] = r3;
                }
            }
            #pragma unroll
            for (int mt = 0; mt < 4; mt++) {
                int r = wm + (mt << 4) + lrow;
                uint32_t c = (uint32_t)((ks << 1) + lchunk);
                uint32_t off = ((uint32_t)r << 6) + (((c ^ ((r >> 1) & 3)) << 4));
                uint32_t aH[4], aL[4];
                ldm4(aH[0], aH[1], aH[2], aH[3], aHb + off);
                if (PASSES == 3)
                    ldm4(aL[0], aL[1], aL[2], aL[3], aLb + off);
                #pragma unroll
                for (int nt = 0; nt < 4; nt++) {
                    mma16816(acc[mt][nt], aH, bH[nt]);
                    if (PASSES == 3) {
                        mma16816(acc[mt][nt], aH, bL[nt]);
                        mma16816(acc[mt][nt], aL, bH[nt]);
                    }
                }
            }
        }
    }

    const int erow = lane >> 2, ecol = (lane & 3) << 1;
    #pragma unroll
    for (int mt = 0; mt < 4; mt++) {
        int r0 = bm + wm + (mt << 4) + erow;
        #pragma unroll
        for (int nt = 0; nt < 4; nt++) {
            int c0 = bn + wn + (nt << 3) + ecol;
            if (OUTBF16) {
                __nv_bfloat162 v0, v1;
                v0.x = __float2bfloat16(acc[mt][nt][0]);
                v0.y = __float2bfloat16(acc[mt][nt][1]);
                v1.x = __float2bfloat16(acc[mt][nt][2]);
                v1.y = __float2bfloat16(acc[mt][nt][3]);
                *(__nv_bfloat162*)(Cb + (size_t)r0 * ldc + c0) = v0;
                *(__nv_bfloat162*)(Cb + (size_t)(r0 + 8) * ldc + c0) = v1;
            } else {
                *(float2*)(Cf + (size_t)r0 * ldc + c0) =
                    make_float2(acc[mt][nt][0], acc[mt][nt][1]);
                *(float2*)(Cf + (size_t)(r0 + 8) * ldc + c0) =
                    make_float2(acc[mt][nt][2], acc[mt][nt][3]);
            }
        }
    }
}

// ------------------------------ shortcut copy -------------------------------
__global__ void copy_kernel(const float4* __restrict__ s, float4* __restrict__ d) {
    int i = blockIdx.x * 256 + threadIdx.x;
    d[i] = s[i];
}

// ------------------------------ LayerNorm + bf16 split ---------------------
__global__ void ln_split_kernel(const float* __restrict__ xin, const float* __restrict__ w,
                                const float* __restrict__ bsh,
                                __nv_bfloat16* __restrict__ oh, __nv_bfloat16* __restrict__ ol) {
    int row = blockIdx.x * 8 + (threadIdx.x >> 5);
    int lane = threadIdx.x & 31;
    const float* r = xin + (size_t)row * Dch;
    float v[24];
    float s = 0.f, s2 = 0.f;
    #pragma unroll
    for (int j = 0; j < 24; j++) { float t = r[lane + j*32]; v[j] = t; s += t; s2 += t*t; }
    #pragma unroll
    for (int o = 16; o; o >>= 1) {
        s  += __shfl_xor_sync(0xFFFFFFFFu, s,  o);
        s2 += __shfl_xor_sync(0xFFFFFFFFu, s2, o);
    }
    float mu = s * (1.f/Dch);
    float rs = rsqrtf(s2 * (1.f/Dch) - mu*mu + 1e-5f);
    #pragma unroll
    for (int j = 0; j < 24; j++) {
        int c = lane + j*32;
        float y = (v[j] - mu) * rs * w[c] + bsh[c];
        __nv_bfloat16 h = __float2bfloat16(y);
        oh[(size_t)row*Dch + c] = h;
        ol[(size_t)row*Dch + c] = __float2bfloat16(y - __bfloat162float(h));
    }
}

// ------------------------------ batched weight hi/lo split -----------------
#define WSEG_BIG   589824
#define WSEG_SMALL 196608
__global__ void wsplit_all_kernel(
    const float* __restrict__ in_proj, const float* __restrict__ outconv,
    const float* __restrict__ outproj, const float* __restrict__ wup,
    const float* __restrict__ lup, const float* __restrict__ uup,
    const float* __restrict__ dcoef,
    __nv_bfloat16* __restrict__ wih, __nv_bfloat16* __restrict__ wil,
    __nv_bfloat16* __restrict__ woh, __nv_bfloat16* __restrict__ wol,
    __nv_bfloat16* __restrict__ wph, __nv_bfloat16* __restrict__ wpl,
    __nv_bfloat16* __restrict__ gwh, __nv_bfloat16* __restrict__ gwl) {
    int idx = blockIdx.x * 256 + threadIdx.x;
    const float* src; __nv_bfloat16 *dh, *dl; int K, Kp, li;
    if (idx < 3 * WSEG_BIG) {
        int seg = idx / WSEG_BIG; li = idx - seg * WSEG_BIG;
        src = (seg == 0) ? in_proj : (seg == 1) ? outconv : outproj;
        dh  = (seg == 0) ? wih : (seg == 1) ? woh : wph;
        dl  = (seg == 0) ? wil : (seg == 1) ? wol : wpl;
        K = Dch; Kp = Dch;
    } else {
        int r = idx - 3 * WSEG_BIG;
        if (r < WSEG_BIG) { src = wup; li = r; dh = gwh; dl = gwl; }
        else {
            r -= WSEG_BIG;
            int seg = r / WSEG_SMALL; li = r - seg * WSEG_SMALL;
            src = (seg == 0) ? lup : (seg == 1) ? uup : dcoef;
            size_t off = (size_t)(3 + seg) * C4 * 64;
            dh = gwh + off; dl = gwl + off;
        }
        K = DS; Kp = 64;
    }
    int m = li / Kp, k = li - m * Kp;
    float v = (k < K) ? src[(size_t)m * K + k] : 0.f;
    __nv_bfloat16 h = __float2bfloat16(v);
    dh[li] = h;
    dl[li] = __float2bfloat16(v - __bfloat162float(h));
}

// ------------------------------ transpose + split (act) --------------------
__global__ void tconv_kernel(const float* __restrict__ src,
                             __nv_bfloat16* __restrict__ dh, __nv_bfloat16* __restrict__ dl) {
    __shared__ float sm[32][33];
    int n0 = blockIdx.x << 5, k0 = blockIdx.y << 5;
    int tx = threadIdx.x, ty = threadIdx.y;
    float v = src[(size_t)(k0 + ty) * NTOT + n0 + tx];
    sm[ty][tx] = v;
    __syncthreads();
    float y = sm[tx][ty];
    __nv_bfloat16 h = __float2bfloat16(y);
    size_t o = (size_t)(n0 + ty) * Dch + k0 + tx;
    dh[o] = h;
    dl[o] = __float2bfloat16(y - __bfloat162float(h));
}

// ------------------------------ xdown + fused remap/split ------------------
__global__ __launch_bounds__(256)
void xdown_kernel(const float* __restrict__ W, const float* __restrict__ X,
                  __nv_bfloat16* __restrict__ dh, __nv_bfloat16* __restrict__ dl) {
    __shared__ float As[8][128];
    __shared__ float Bs[8][64];
    const int M = DS, N = NTOT, K = Dch;
    int bn = blockIdx.x * 64;
    int tid = threadIdx.x;
    int arow = tid >> 1, acol = (tid & 1) * 4;
    int brow = tid >> 5, bcol = tid & 31;
    int tm = (tid >> 4) * 8, tn = (tid & 15) * 4;
    float acc[8][4];
    #pragma unroll
    for (int i = 0; i < 8; i++)
        #pragma unroll
        for (int j = 0; j < 4; j++) acc[i][j] = 0.f;
    for (int k0 = 0; k0 < K; k0 += 8) {
        float4 av = make_float4(0.f,0.f,0.f,0.f);
        if (arow < M)
            av = *(const float4*)(W + (size_t)arow*K + k0 + acol);
        As[acol+0][arow] = av.x; As[acol+1][arow] = av.y;
        As[acol+2][arow] = av.z; As[acol+3][arow] = av.w;
        Bs[brow][bcol]    = X[(size_t)(k0+brow)*N + bn + bcol];
        Bs[brow][bcol+32] = X[(size_t)(k0+brow)*N + bn + bcol + 32];
        __syncthreads();
        #pragma unroll
        for (int kk = 0; kk < 8; kk++) {
            float a[8], bb[4];
            *(float4*)(a)   = *(const float4*)&As[kk][tm];
            *(float4*)(a+4) = *(const float4*)&As[kk][tm+4];
            *(float4*)(bb)  = *(const float4*)&Bs[kk][tn];
            #pragma unroll
            for (int i = 0; i < 8; i++)
                #pragma unroll
                for (int j = 0; j < 4; j++)
                    acc[i][j] = fmaf(a[i], bb[j], acc[i][j]);
        }
        __syncthreads();
    }
    if (tm < 64) {
        #pragma unroll
        for (int i = 0; i < 8; i++) {
            int row = tm + i;
            #pragma unroll
            for (int j = 0; j < 4; j++) {
                int n = bn + tn + j;
                int q = n & 1023;
                int tok = (n & ~1023) + ((q & 31) << 5) + (q >> 5);
                float y = acc[i][j];
                __nv_bfloat16 h = __float2bfloat16(y);
                dh[(size_t)tok*64 + row] = h;
                dl[(size_t)tok*64 + row] = __float2bfloat16(y - __bfloat162float(h));
            }
        }
    }
}

// ------------------------------ dw7: 1x4 strips + fused transpose ----------
__global__ void dw7_kernel(const float* __restrict__ in, const float* __restrict__ wt,
                           const float* __restrict__ bias,
                           float* __restrict__ out, float* __restrict__ outT) {
    int d = blockIdx.x, b = blockIdx.y;
    __shared__ float sm[38][39];
    __shared__ float wsm[49];
    __shared__ float zt[32][33];
    const float* plane = in + (size_t)d*NTOT + b*NPIX;
    int tid = threadIdx.x;
    if (tid < 49) wsm[tid] = wt[d*49 + tid];
    for (int i = tid; i < 38*38; i += 256) {
        int y = i/38, x = i - y*38;
        int yy = y - 3, xx = x - 3;
        sm[y][x] = (yy>=0 && yy<32 && xx>=0 && xx<32) ? plane[yy*32+xx] : 0.f;
    }
    __syncthreads();
    float bv = bias[d];
    int y  = tid >> 3;
    int x0 = (tid & 7) << 2;
    float a0 = bv, a1 = bv, a2 = bv, a3 = bv;
    #pragma unroll
    for (int ky = 0; ky < 7; ky++) {
        float r[10];
        #pragma unroll
        for (int i = 0; i < 10; i++) r[i] = sm[y+ky][x0+i];
        #pragma unroll
        for (int kx = 0; kx < 7; kx++) {
            float wv = wsm[ky*7+kx];
            a0 = fmaf(r[kx],   wv, a0);
            a1 = fmaf(r[kx+1], wv, a1);
            a2 = fmaf(r[kx+2], wv, a2);
            a3 = fmaf(r[kx+3], wv, a3);
        }
    }
    size_t base = (size_t)d*NTOT + b*NPIX;
    *(float4*)(out + base + (y << 5) + x0) = make_float4(a0, a1, a2, a3);
    zt[y][x0] = a0; zt[y][x0+1] = a1; zt[y][x0+2] = a2; zt[y][x0+3] = a3;
    __syncthreads();
    float4 vt = make_float4(zt[x0][y], zt[x0+1][y], zt[x0+2][y], zt[x0+3][y]);
    *(float4*)(outT + base + (y << 5) + x0) = vt;
}

// ------------------------------ dw3 + y*relu(y): 1x4 strips ----------------
__global__ void dw3act_kernel(const float* __restrict__ in, const float* __restrict__ wt,
                              float* __restrict__ out) {
    int d = blockIdx.x, b = blockIdx.y;
    __shared__ float sm[34][35];
    __shared__ float wsm[9];
    const float* plane = in + (size_t)d*NTOT + b*NPIX;
    int tid = threadIdx.x;
    if (tid < 9) wsm[tid] = wt[d*9 + tid];
    for (int i = tid; i < 34*34; i += 256) {
        int y = i/34, x = i - y*34;
        int yy = y - 1, xx = x - 1;
        sm[y][x] = (yy>=0 && yy<32 && xx>=0 && xx<32) ? plane[yy*32+xx] : 0.f;
    }
    __syncthreads();
    int y  = tid >> 3;
    int x0 = (tid & 7) << 2;
    float a0 = 0.f, a1 = 0.f, a2 = 0.f, a3 = 0.f;
    #pragma unroll
    for (int ky = 0; ky < 3; ky++) {
        float r[6];
        #pragma unroll
        for (int i = 0; i < 6; i++) r[i] = sm[y+ky][x0+i];
        #pragma unroll
        for (int kx = 0; kx < 3; kx++) {
            float wv = wsm[ky*3+kx];
            a0 = fmaf(r[kx],   wv, a0);
            a1 = fmaf(r[kx+1], wv, a1);
            a2 = fmaf(r[kx+2], wv, a2);
            a3 = fmaf(r[kx+3], wv, a3);
        }
    }
    float z0 = (a0 > 0.f) ? a0*a0 : 0.f;
    float z1 = (a1 > 0.f) ? a1*a1 : 0.f;
    float z2 = (a2 > 0.f) ? a2*a2 : 0.f;
    float z3 = (a3 > 0.f) ? a3*a3 : 0.f;
    *(float4*)(out + (size_t)d*NTOT + b*NPIX + (y << 5) + x0) =
        make_float4(z0, z1, z2, z3);
}

// ------------------------------ scan ---------------------------------------
__global__ void scan_kernel(const __nv_bfloat16* __restrict__ gsig,
                            const float* __restrict__ glud,
                            const float* __restrict__ x2,
                            const float* __restrict__ x2t,
                            const float* __restrict__ mw,
                            float* __restrict__ s4) {
    int c4 = blockIdx.x, b = blockIdx.y;
    int k = c4 / Dch, d = c4 - k*Dch;
    int tid = threadIdx.x;
    int chunk = tid >> 5, h = tid & 31;
    const size_t PS = (size_t)C4 * NTOT;
    const __nv_bfloat16* Gl = gsig + (size_t)c4*NTOT + (size_t)b*NPIX;
    const __nv_bfloat16* Gm = Gl + PS;
    const __nv_bfloat16* Gr = Gl + 2*PS;
    const float* Lp = glud + (size_t)c4*NTOT + (size_t)b*NPIX;
    const float* Up = Lp + PS;
    const float* Dp = Lp + 2*PS;
    const float* xsrc = ((k & 1) ? x2 : x2t) + (size_t)d*NTOT + b*NPIX;
    float mk = mw[k];
    float* outp = s4 + (size_t)c4*NTOT + b*NPIX;
    float hs = 0.f;
    const unsigned mask = 0xFFFFFFFFu;
    #pragma unroll
    for (int pos = 0; pos < 8; pos++) {
        int w  = chunk*8 + pos;
        int q  = w*32 + h;
        int wq = (k >= 2) ? (31 - w) : w;
        float xv = xsrc[wq*32 + h];
        float a  = __bfloat162float(Gl[q]);
        float bb = __bfloat162float(Gm[q]);
        float cc = __bfloat162float(Gr[q]);
        float l  = Lp[q];
        float ea = fast_exp(a), eb = fast_exp(bb), ec = fast_exp(cc);
        float qa = 1.f + ea, qb = 1.f + eb, qc = 1.f + ec;
        float pl = ea*qb*qc, pm = eb*qa*qc, pr = ec*qa*qb;
        float den = pl + pm + pr;
        if (h == 0)  den = pm + pr;
        if (h == 31) den = pl + pm;
        float rd = fast_rcp(den);
        float gl = pl*rd, gm = pm*rd, gr = pr*rd;
        float up = __shfl_up_sync(mask, hs, 1);
        float dn = __shfl_down_sync(mask, hs, 1);
        if (h == 0)  up = 0.f;
        if (h == 31) dn = 0.f;
        hs = fmaf(l, xv, fmaf(gl, up, fmaf(gm, hs, gr*dn)));
        outp[q] = mk * fmaf(hs, Up[q], xv*Dp[q]);
    }
}

// ------------------------------ merge + transpose + bf16 split -------------
__global__ void merge_split_kernel(const float* __restrict__ s4,
                                   __nv_bfloat16* __restrict__ dh,
                                   __nv_bfloat16* __restrict__ dl) {
    __shared__ float sm[32][33];
    int d0 = blockIdx.x << 5, b = blockIdx.y;
    int tx = threadIdx.x, ty = threadIdx.y;
    for (int pg = blockIdx.z * 8; pg < blockIdx.z * 8 + 8; pg++) {
        int q = (pg << 5) + tx;
        float v = 0.f;
        #pragma unroll
        for (int k = 0; k < 4; k++)
            v += s4[(size_t)(k*Dch + d0 + ty)*NTOT + b*NPIX + q];
        sm[ty][tx] = v;
        __syncthreads();
        float y = sm[tx][ty];
        __nv_bfloat16 hh = __float2bfloat16(y);
        size_t o = (size_t)(b*NPIX + (ty << 5) + pg) * Dch + d0 + tx;
        dh[o] = hh;
        dl[o] = __float2bfloat16(y - __bfloat162float(hh));
        __syncthreads();
    }
}

// ------------------------------ launch -------------------------------------
extern "C" void kernel_launch(void* const* d_in, const int* in_sizes, int n_in,
                              void* d_out, int out_size) {
    const float* hidden   = (const float*)d_in[0];
    const float* norm_w   = (const float*)d_in[1];
    const float* norm_b   = (const float*)d_in[2];
    const float* in_proj  = (const float*)d_in[3];
    const float* conv7_w  = (const float*)d_in[4];
    const float* conv7_b  = (const float*)d_in[5];
    const float* xdown_w  = (const float*)d_in[6];
    const float* wup_w    = (const float*)d_in[7];
    const float* lup_w    = (const float*)d_in[8];
    const float* uup_w    = (const float*)d_in[9];
    const float* dcoef_w  = (const float*)d_in[10];
    const float* m_w      = (const float*)d_in[11];
    const float* outconv_w  = (const float*)d_in[12];
    const float* outdconv_w = (const float*)d_in[13];
    const float* outproj_w  = (const float*)d_in[14];
    float* outp = (float*)d_out;

    float *x1,*x2,*x2t,*glud,*s4,*oc,*act;
    __nv_bfloat16 *gsig,*xlnh,*xlnl,*wih,*wil,*woh,*wol,*wph,*wpl,*gwh,*gwl,
                  *xpnh,*xpnl,*mnh,*mnl,*anh,*anl;
    cudaGetSymbolAddress((void**)&x1, g_x1);   cudaGetSymbolAddress((void**)&x2, g_x2);
    cudaGetSymbolAddress((void**)&x2t,g_x2t);
    cudaGetSymbolAddress((void**)&gsig,g_gsig);cudaGetSymbolAddress((void**)&glud,g_glud);
    cudaGetSymbolAddress((void**)&s4, g_s4);   cudaGetSymbolAddress((void**)&oc, g_oc);
    cudaGetSymbolAddress((void**)&act,g_act);
    cudaGetSymbolAddress((void**)&xlnh,g_xlnh);cudaGetSymbolAddress((void**)&xlnl,g_xlnl);
    cudaGetSymbolAddress((void**)&wih,g_wih);  cudaGetSymbolAddress((void**)&wil,g_wil);
    cudaGetSymbolAddress((void**)&woh,g_woh);  cudaGetSymbolAddress((void**)&wol,g_wol);
    cudaGetSymbolAddress((void**)&wph,g_wph);  cudaGetSymbolAddress((void**)&wpl,g_wpl);
    cudaGetSymbolAddress((void**)&gwh,g_gwh);  cudaGetSymbolAddress((void**)&gwl,g_gwl);
    cudaGetSymbolAddress((void**)&xpnh,g_xpnh);cudaGetSymbolAddress((void**)&xpnl,g_xpnl);
    cudaGetSymbolAddress((void**)&mnh,g_mnh);  cudaGetSymbolAddress((void**)&mnl,g_mnl);
    cudaGetSymbolAddress((void**)&anh,g_anh);  cudaGetSymbolAddress((void**)&anl,g_anl);

    const int SMEM3 = 3 * 32768;   // 3-pass: 3 stages x 32KB
    const int SMEM1 = 3 * 16384;   // 1-pass: 3 stages x 16KB
    cudaFuncSetAttribute(mma_gemm<3,0>, cudaFuncAttributeMaxDynamicSharedMemorySize, SMEM3);
    cudaFuncSetAttribute(mma_gemm<1,1>, cudaFuncAttributeMaxDynamicSharedMemorySize, SMEM1);
    dim3 b3232(32, 32);

    // 1) batched weight splits
    wsplit_all_kernel<<<(4*WSEG_BIG + 3*WSEG_SMALL)/256, 256>>>(
        in_proj, outconv_w, outproj_w, wup_w, lup_w, uup_w, dcoef_w,
        wih, wil, woh, wol, wph, wpl, gwh, gwl);

    // 2) LN -> bf16 hi/lo
    ln_split_kernel<<<NTOT/8, 256>>>(hidden, norm_w, norm_b, xlnh, xlnl);

    // 3) shortcut copy (also makes in_proj launch #4 for the profiler)
    copy_kernel<<<BTD/1024, 256>>>((const float4*)hidden, (float4*)(outp + BTD));

    // 4) in_proj   <-- profiled launch
    mma_gemm<3,0><<<dim3(NTOT/128, Dch/128), 256, SMEM3>>>(
        wih, wil, xlnh, xlnl, x1, nullptr, Dch, NTOT);

    // 5) dw 7x7 (+ fused w-major transpose)
    dw7_kernel<<<dim3(Dch, Bsz), 256>>>(x1, conv7_w, conv7_b, x2, x2t);

    // 6) xdown + fused remap/split -> xpn hi/lo
    xdown_kernel<<<dim3(NTOT/64, 1), 256>>>(xdown_w, x2, xpnh, xpnl);

    // 7) sigmoid gates: 1-pass bf16 out
    mma_gemm<1,1><<<dim3(NTOT/128, (3*C4)/128), 256, SMEM1>>>(
        gwh, nullptr, xpnh, nullptr, nullptr, gsig, 64, NTOT);

    // 8) L|U|D: 3-pass fp32 out
    mma_gemm<3,0><<<dim3(NTOT/128, (3*C4)/128), 256, SMEM3>>>(
        gwh + (size_t)3*C4*64, gwl + (size_t)3*C4*64, xpnh, xpnl,
        glud, nullptr, 64, NTOT);

    // 9) scan
    scan_kernel<<<dim3(C4, Bsz), 128>>>(gsig, glud, x2, x2t, m_w, s4);

    // 10) merge + transpose + split -> mn hi/lo
    merge_split_kernel<<<dim3(Dch/32, Bsz, 4), b3232>>>(s4, mnh, mnl);

    // 11) outconv
    mma_gemm<3,0><<<dim3(NTOT/128, Dch/128), 256, SMEM3>>>(
        woh, wol, mnh, mnl, oc, nullptr, Dch, NTOT);

    // 12) dw 3x3 + y*relu(y)
    dw3act_kernel<<<dim3(Dch, Bsz), 256>>>(oc, outdconv_w, act);

    // 13) act -> (4096x768) hi/lo
    tconv_kernel<<<dim3(NTOT/32, Dch/32), b3232>>>(act, anh, anl);

    // 14) outproj -> d_out
    mma_gemm<3,0><<<dim3(Dch/128, NTOT/128), 256, SMEM3>>>(
        anh, anl, wph, wpl, outp, nullptr, Dch, Dch);
}

// round 8
// speedup vs baseline: 1.7181x; 1.1284x over previous
#include <cuda_runtime.h>
#include <cuda_bf16.h>
#include <cstdint>

// ---------------------------------------------------------------------------
// GSPN block. B=4, T=1024, D=768, HW=32, DS=48, CHUNK=8.
// Round 8: TM=64 GEMM tiles for the big-3 (grid 384, 3 CTA/SM) to kill the
// occupancy quantization seen in the round-7 profile (occ 15.5%, tensor 31%).
// ---------------------------------------------------------------------------

#define Bsz   4
#define Dch   768
#define Tlen  1024
#define DS    48
#define NPIX  1024
#define NTOT  4096
#define C4    (4*Dch)         // 3072
#define MG    (6*C4)          // 18432
#define BTD   (Bsz*Tlen*Dch)

// ------------------------- static scratch ----------------------------------
__device__ float g_x1 [(size_t)Dch*NTOT];
__device__ float g_x2 [(size_t)Dch*NTOT];
__device__ float g_x2t[(size_t)Dch*NTOT];
__device__ __nv_bfloat16 g_gsig[(size_t)3*C4*NTOT];
__device__ float g_glud[(size_t)3*C4*NTOT];
__device__ float g_s4 [(size_t)C4*NTOT];
__device__ float g_oc [(size_t)Dch*NTOT];
__device__ float g_act[(size_t)Dch*NTOT];

__device__ __align__(16) __nv_bfloat16 g_xlnh[(size_t)NTOT*Dch], g_xlnl[(size_t)NTOT*Dch];
__device__ __align__(16) __nv_bfloat16 g_wih [Dch*Dch], g_wil [Dch*Dch];
__device__ __align__(16) __nv_bfloat16 g_woh [Dch*Dch], g_wol [Dch*Dch];
__device__ __align__(16) __nv_bfloat16 g_wph [Dch*Dch], g_wpl [Dch*Dch];
__device__ __align__(16) __nv_bfloat16 g_gwh [(size_t)MG*64], g_gwl [(size_t)MG*64];
__device__ __align__(16) __nv_bfloat16 g_xpnh[(size_t)NTOT*64], g_xpnl[(size_t)NTOT*64];
__device__ __align__(16) __nv_bfloat16 g_mnh [(size_t)NTOT*Dch], g_mnl [(size_t)NTOT*Dch];
__device__ __align__(16) __nv_bfloat16 g_anh [(size_t)NTOT*Dch], g_anl [(size_t)NTOT*Dch];

// ------------------------------ helpers ------------------------------------
__device__ __forceinline__ uint32_t smem_u32(const void* p) {
    uint32_t r;
    asm("{ .reg .u64 t; cvta.to.shared.u64 t, %1; cvt.u32.u64 %0, t; }"
        : "=r"(r) : "l"(p));
    return r;
}
__device__ __forceinline__ void cp16(uint32_t saddr, const void* gptr) {
    asm volatile("cp.async.cg.shared.global [%0], [%1], 16;"
        :: "r"(saddr), "l"(gptr));
}
__device__ __forceinline__ void cp_commit() {
    asm volatile("cp.async.commit_group;" ::: "memory");
}
template<int N>
__device__ __forceinline__ void cp_wait() {
    asm volatile("cp.async.wait_group %0;" :: "n"(N) : "memory");
}
__device__ __forceinline__ void ldm4(uint32_t& r0, uint32_t& r1, uint32_t& r2,
                                     uint32_t& r3, uint32_t addr) {
    asm volatile("ldmatrix.sync.aligned.m8n8.x4.shared.b16 {%0,%1,%2,%3}, [%4];"
        : "=r"(r0), "=r"(r1), "=r"(r2), "=r"(r3) : "r"(addr));
}
__device__ __forceinline__ void mma16816(float* c, const uint32_t* a,
                                         const uint32_t* b) {
    asm volatile("mma.sync.aligned.m16n8k16.row.col.f32.bf16.bf16.f32 "
        "{%0,%1,%2,%3}, {%4,%5,%6,%7}, {%8,%9}, {%0,%1,%2,%3};"
        : "+f"(c[0]), "+f"(c[1]), "+f"(c[2]), "+f"(c[3])
        : "r"(a[0]), "r"(a[1]), "r"(a[2]), "r"(a[3]), "r"(b[0]), "r"(b[1]));
}

__device__ __forceinline__ float fast_exp(float x) {
    x = fminf(fmaxf(x, -20.f), 20.f);
    float t = x * 1.4426950408889634f;
    float r = t + 12582912.f;
    int   i = __float_as_int(r) - 0x4B400000;
    float f = t - (r - 12582912.f);
    const float c1=0.69314718056f, c2=0.2402265069f, c3=0.0555041087f,
                c4=0.00961812911f, c5=0.00133335581f;
    float p = fmaf(c5, f, c4);
    p = fmaf(p, f, c3); p = fmaf(p, f, c2); p = fmaf(p, f, c1); p = fmaf(p, f, 1.f);
    return __int_as_float(__float_as_int(p) + (i << 23));
}
__device__ __forceinline__ float fast_rcp(float x) {
    float y = __int_as_float(0x7EF311C3 - __float_as_int(x));
    y = y * (2.0f - x * y);
    y = y * (2.0f - x * y);
    y = y * (2.0f - x * y);
    return y;
}

// ------------------------------ HMMA GEMM ----------------------------------
// C(MxN) = hi/lo passes of A(MxKp) @ B(NxKp)^T, bf16 K-major.
// Tile: TM x 128, 8 warps (2 x 4), warp tile (TM/2) x 32. BK=32, 3 stages.
// Stage: A planes TM rows + B planes 128 rows, 64B/row, swizzle c ^= (r>>1)&3.
template<int PASSES, int OUTBF16, int TM, int MAXCTA>
__global__ __launch_bounds__(256, MAXCTA)
void mma_gemm(const __nv_bfloat16* __restrict__ Ahi, const __nv_bfloat16* __restrict__ Alo,
              const __nv_bfloat16* __restrict__ Bhi, const __nv_bfloat16* __restrict__ Blo,
              float* __restrict__ Cf, __nv_bfloat16* __restrict__ Cb,
              int Kp, int ldc) {
    extern __shared__ __align__(16) char dsm[];
    const int PA = (PASSES == 3) ? 2 : 1;          // A planes
    const int SA = TM * 64;                        // bytes per A plane
    const int SB = 8192;                           // bytes per B plane
    const int SSTAGE = PA * SA + PA * SB;
    const int MT = TM / 32;                        // m-tiles per warp (16-row)
    const int tid  = threadIdx.x;
    const int wid  = tid >> 5, lane = tid & 31;
    const int wm   = (wid >> 2) * (TM >> 1);
    const int wn   = (wid & 3)  << 5;
    const int bm   = blockIdx.y * TM, bn = blockIdx.x << 7;
    const uint32_t sbase = smem_u32(dsm);
    const int NKB = Kp >> 5;

    auto load_stage = [&](int buf, int kb) {
        const int k0 = kb << 5;
        uint32_t sb = sbase + buf * SSTAGE;
        #pragma unroll
        for (int pl = 0; pl < PA; pl++) {          // A planes
            const __nv_bfloat16* src = (pl == 0) ? Ahi : Alo;
            uint32_t pb = sb + pl * SA;
            #pragma unroll
            for (int i = tid; i < TM * 4; i += 256) {
                int r = i >> 2, c = i & 3;
                cp16(pb + (r << 6) + ((uint32_t)(c ^ ((r >> 1) & 3)) << 4),
                     src + (size_t)(bm + r) * Kp + k0 + (c << 3));
            }
        }
        #pragma unroll
        for (int pl = 0; pl < PA; pl++) {          // B planes
            const __nv_bfloat16* src = (pl == 0) ? Bhi : Blo;
            uint32_t pb = sb + PA * SA + pl * SB;
            #pragma unroll
            for (int i = tid; i < 512; i += 256) {
                int r = i >> 2, c = i & 3;
                cp16(pb + (r << 6) + ((uint32_t)(c ^ ((r >> 1) & 3)) << 4),
                     src + (size_t)(bn + r) * Kp + k0 + (c << 3));
            }
        }
        cp_commit();
    };

    float acc[MT][4][4];
    #pragma unroll
    for (int i = 0; i < MT; i++)
        #pragma unroll
        for (int j = 0; j < 4; j++)
            #pragma unroll
            for (int q = 0; q < 4; q++) acc[i][j][q] = 0.f;

    const int lrow = (lane & 7) + (((lane >> 3) & 1) << 3);
    const int lchunk = (lane >> 4) & 1;

    load_stage(0, 0);
    if (NKB > 1) load_stage(1, 1);

    for (int kb = 0; kb < NKB; kb++) {
        if (kb < NKB - 1) cp_wait<1>(); else cp_wait<0>();
        __syncthreads();
        if (kb + 2 < NKB) {
            int dst = kb + 2;
            load_stage(dst - (dst / 3) * 3, dst);
        }

        uint32_t sb = sbase + (kb - (kb / 3) * 3) * SSTAGE;
        uint32_t aHb = sb;
        uint32_t aLb = sb + SA;
        uint32_t bHb = sb + PA * SA;
        uint32_t bLb = bHb + SB;

        #pragma unroll
        for (int ks = 0; ks < 2; ks++) {
            uint32_t bH[4][2], bL[4][2];
            #pragma unroll
            for (int nt2 = 0; nt2 < 2; nt2++) {
                int r = wn + (nt2 << 4) + lrow;
                uint32_t c = (uint32_t)((ks << 1) + lchunk);
                uint32_t off = ((uint32_t)r << 6) + (((c ^ ((r >> 1) & 3)) << 4));
                uint32_t r0, r1, r2, r3;
                ldm4(r0, r1, r2, r3, bHb + off);
                bH[2*nt2][0] = r0; bH[2*nt2][1] = r2;
                bH[2*nt2+1][0] = r1; bH[2*nt2+1][1] = r3;
                if (PASSES == 3) {
                    ldm4(r0, r1, r2, r3, bLb + off);
                    bL[2*nt2][0] = r0; bL[2*nt2][1] = r2;
                    bL[2*nt2+1][0] = r1; bL[2*nt2+1][1] = r3;
                }
            }
            #pragma unroll
            for (int mt = 0; mt < MT; mt++) {
                int r = wm + (mt << 4) + lrow;
                uint32_t c = (uint32_t)((ks << 1) + lchunk);
                uint32_t off = ((uint32_t)r << 6) + (((c ^ ((r >> 1) & 3)) << 4));
                uint32_t aH[4], aL[4];
                ldm4(aH[0], aH[1], aH[2], aH[3], aHb + off);
                if (PASSES == 3)
                    ldm4(aL[0], aL[1], aL[2], aL[3], aLb + off);
                #pragma unroll
                for (int nt = 0; nt < 4; nt++) {
                    mma16816(acc[mt][nt], aH, bH[nt]);
                    if (PASSES == 3) {
                        mma16816(acc[mt][nt], aH, bL[nt]);
                        mma16816(acc[mt][nt], aL, bH[nt]);
                    }
                }
            }
        }
    }

    const int erow = lane >> 2, ecol = (lane & 3) << 1;
    #pragma unroll
    for (int mt = 0; mt < MT; mt++) {
        int r0 = bm + wm + (mt << 4) + erow;
        #pragma unroll
        for (int nt = 0; nt < 4; nt++) {
            int c0 = bn + wn + (nt << 3) + ecol;
            if (OUTBF16) {
                __nv_bfloat162 v0, v1;
                v0.x = __float2bfloat16(acc[mt][nt][0]);
                v0.y = __float2bfloat16(acc[mt][nt][1]);
                v1.x = __float2bfloat16(acc[mt][nt][2]);
                v1.y = __float2bfloat16(acc[mt][nt][3]);
                *(__nv_bfloat162*)(Cb + (size_t)r0 * ldc + c0) = v0;
                *(__nv_bfloat162*)(Cb + (size_t)(r0 + 8) * ldc + c0) = v1;
            } else {
                *(float2*)(Cf + (size_t)r0 * ldc + c0) =
                    make_float2(acc[mt][nt][0], acc[mt][nt][1]);
                *(float2*)(Cf + (size_t)(r0 + 8) * ldc + c0) =
                    make_float2(acc[mt][nt][2], acc[mt][nt][3]);
            }
        }
    }
}

// ------------------------------ shortcut copy -------------------------------
__global__ void copy_kernel(const float4* __restrict__ s, float4* __restrict__ d) {
    int i = blockIdx.x * 256 + threadIdx.x;
    d[i] = s[i];
}

// ------------------------------ LayerNorm + bf16 split ---------------------
__global__ void ln_split_kernel(const float* __restrict__ xin, const float* __restrict__ w,
                                const float* __restrict__ bsh,
                                __nv_bfloat16* __restrict__ oh, __nv_bfloat16* __restrict__ ol) {
    int row = blockIdx.x * 8 + (threadIdx.x >> 5);
    int lane = threadIdx.x & 31;
    const float* r = xin + (size_t)row * Dch;
    float v[24];
    float s = 0.f, s2 = 0.f;
    #pragma unroll
    for (int j = 0; j < 24; j++) { float t = r[lane + j*32]; v[j] = t; s += t; s2 += t*t; }
    #pragma unroll
    for (int o = 16; o; o >>= 1) {
        s  += __shfl_xor_sync(0xFFFFFFFFu, s,  o);
        s2 += __shfl_xor_sync(0xFFFFFFFFu, s2, o);
    }
    float mu = s * (1.f/Dch);
    float rs = rsqrtf(s2 * (1.f/Dch) - mu*mu + 1e-5f);
    #pragma unroll
    for (int j = 0; j < 24; j++) {
        int c = lane + j*32;
        float y = (v[j] - mu) * rs * w[c] + bsh[c];
        __nv_bfloat16 h = __float2bfloat16(y);
        oh[(size_t)row*Dch + c] = h;
        ol[(size_t)row*Dch + c] = __float2bfloat16(y - __bfloat162float(h));
    }
}

// ------------------------------ batched weight hi/lo split -----------------
#define WSEG_BIG   589824
#define WSEG_SMALL 196608
__global__ void wsplit_all_kernel(
    const float* __restrict__ in_proj, const float* __restrict__ outconv,
    const float* __restrict__ outproj, const float* __restrict__ wup,
    const float* __restrict__ lup, const float* __restrict__ uup,
    const float* __restrict__ dcoef,
    __nv_bfloat16* __restrict__ wih, __nv_bfloat16* __restrict__ wil,
    __nv_bfloat16* __restrict__ woh, __nv_bfloat16* __restrict__ wol,
    __nv_bfloat16* __restrict__ wph, __nv_bfloat16* __restrict__ wpl,
    __nv_bfloat16* __restrict__ gwh, __nv_bfloat16* __restrict__ gwl) {
    int idx = blockIdx.x * 256 + threadIdx.x;
    const float* src; __nv_bfloat16 *dh, *dl; int K, Kp, li;
    if (idx < 3 * WSEG_BIG) {
        int seg = idx / WSEG_BIG; li = idx - seg * WSEG_BIG;
        src = (seg == 0) ? in_proj : (seg == 1) ? outconv : outproj;
        dh  = (seg == 0) ? wih : (seg == 1) ? woh : wph;
        dl  = (seg == 0) ? wil : (seg == 1) ? wol : wpl;
        K = Dch; Kp = Dch;
    } else {
        int r = idx - 3 * WSEG_BIG;
        if (r < WSEG_BIG) { src = wup; li = r; dh = gwh; dl = gwl; }
        else {
            r -= WSEG_BIG;
            int seg = r / WSEG_SMALL; li = r - seg * WSEG_SMALL;
            src = (seg == 0) ? lup : (seg == 1) ? uup : dcoef;
            size_t off = (size_t)(3 + seg) * C4 * 64;
            dh = gwh + off; dl = gwl + off;
        }
        K = DS; Kp = 64;
    }
    int m = li / Kp, k = li - m * Kp;
    float v = (k < K) ? src[(size_t)m * K + k] : 0.f;
    __nv_bfloat16 h = __float2bfloat16(v);
    dh[li] = h;
    dl[li] = __float2bfloat16(v - __bfloat162float(h));
}

// ------------------------------ transpose + split (act) --------------------
__global__ void tconv_kernel(const float* __restrict__ src,
                             __nv_bfloat16* __restrict__ dh, __nv_bfloat16* __restrict__ dl) {
    __shared__ float sm[32][33];
    int n0 = blockIdx.x << 5, k0 = blockIdx.y << 5;
    int tx = threadIdx.x, ty = threadIdx.y;
    float v = src[(size_t)(k0 + ty) * NTOT + n0 + tx];
    sm[ty][tx] = v;
    __syncthreads();
    float y = sm[tx][ty];
    __nv_bfloat16 h = __float2bfloat16(y);
    size_t o = (size_t)(n0 + ty) * Dch + k0 + tx;
    dh[o] = h;
    dl[o] = __float2bfloat16(y - __bfloat162float(h));
}

// ------------------------------ xdown + fused remap/split ------------------
__global__ __launch_bounds__(256)
void xdown_kernel(const float* __restrict__ W, const float* __restrict__ X,
                  __nv_bfloat16* __restrict__ dh, __nv_bfloat16* __restrict__ dl) {
    __shared__ float As[8][128];
    __shared__ float Bs[8][64];
    const int M = DS, N = NTOT, K = Dch;
    int bn = blockIdx.x * 64;
    int tid = threadIdx.x;
    int arow = tid >> 1, acol = (tid & 1) * 4;
    int brow = tid >> 5, bcol = tid & 31;
    int tm = (tid >> 4) * 8, tn = (tid & 15) * 4;
    float acc[8][4];
    #pragma unroll
    for (int i = 0; i < 8; i++)
        #pragma unroll
        for (int j = 0; j < 4; j++) acc[i][j] = 0.f;
    for (int k0 = 0; k0 < K; k0 += 8) {
        float4 av = make_float4(0.f,0.f,0.f,0.f);
        if (arow < M)
            av = *(const float4*)(W + (size_t)arow*K + k0 + acol);
        As[acol+0][arow] = av.x; As[acol+1][arow] = av.y;
        As[acol+2][arow] = av.z; As[acol+3][arow] = av.w;
        Bs[brow][bcol]    = X[(size_t)(k0+brow)*N + bn + bcol];
        Bs[brow][bcol+32] = X[(size_t)(k0+brow)*N + bn + bcol + 32];
        __syncthreads();
        #pragma unroll
        for (int kk = 0; kk < 8; kk++) {
            float a[8], bb[4];
            *(float4*)(a)   = *(const float4*)&As[kk][tm];
            *(float4*)(a+4) = *(const float4*)&As[kk][tm+4];
            *(float4*)(bb)  = *(const float4*)&Bs[kk][tn];
            #pragma unroll
            for (int i = 0; i < 8; i++)
                #pragma unroll
                for (int j = 0; j < 4; j++)
                    acc[i][j] = fmaf(a[i], bb[j], acc[i][j]);
        }
        __syncthreads();
    }
    if (tm < 64) {
        #pragma unroll
        for (int i = 0; i < 8; i++) {
            int row = tm + i;
            #pragma unroll
            for (int j = 0; j < 4; j++) {
                int n = bn + tn + j;
                int q = n & 1023;
                int tok = (n & ~1023) + ((q & 31) << 5) + (q >> 5);
                float y = acc[i][j];
                __nv_bfloat16 h = __float2bfloat16(y);
                dh[(size_t)tok*64 + row] = h;
                dl[(size_t)tok*64 + row] = __float2bfloat16(y - __bfloat162float(h));
            }
        }
    }
}

// ------------------------------ dw7: 1x4 strips + fused transpose ----------
__global__ void dw7_kernel(const float* __restrict__ in, const float* __restrict__ wt,
                           const float* __restrict__ bias,
                           float* __restrict__ out, float* __restrict__ outT) {
    int d = blockIdx.x, b = blockIdx.y;
    __shared__ float sm[38][39];
    __shared__ float wsm[49];
    __shared__ float zt[32][33];
    const float* plane = in + (size_t)d*NTOT + b*NPIX;
    int tid = threadIdx.x;
    if (tid < 49) wsm[tid] = wt[d*49 + tid];
    for (int i = tid; i < 38*38; i += 256) {
        int y = i/38, x = i - y*38;
        int yy = y - 3, xx = x - 3;
        sm[y][x] = (yy>=0 && yy<32 && xx>=0 && xx<32) ? plane[yy*32+xx] : 0.f;
    }
    __syncthreads();
    float bv = bias[d];
    int y  = tid >> 3;
    int x0 = (tid & 7) << 2;
    float a0 = bv, a1 = bv, a2 = bv, a3 = bv;
    #pragma unroll
    for (int ky = 0; ky < 7; ky++) {
        float r[10];
        #pragma unroll
        for (int i = 0; i < 10; i++) r[i] = sm[y+ky][x0+i];
        #pragma unroll
        for (int kx = 0; kx < 7; kx++) {
            float wv = wsm[ky*7+kx];
            a0 = fmaf(r[kx],   wv, a0);
            a1 = fmaf(r[kx+1], wv, a1);
            a2 = fmaf(r[kx+2], wv, a2);
            a3 = fmaf(r[kx+3], wv, a3);
        }
    }
    size_t base = (size_t)d*NTOT + b*NPIX;
    *(float4*)(out + base + (y << 5) + x0) = make_float4(a0, a1, a2, a3);
    zt[y][x0] = a0; zt[y][x0+1] = a1; zt[y][x0+2] = a2; zt[y][x0+3] = a3;
    __syncthreads();
    float4 vt = make_float4(zt[x0][y], zt[x0+1][y], zt[x0+2][y], zt[x0+3][y]);
    *(float4*)(outT + base + (y << 5) + x0) = vt;
}

// ------------------------------ dw3 + y*relu(y): 1x4 strips ----------------
__global__ void dw3act_kernel(const float* __restrict__ in, const float* __restrict__ wt,
                              float* __restrict__ out) {
    int d = blockIdx.x, b = blockIdx.y;
    __shared__ float sm[34][35];
    __shared__ float wsm[9];
    const float* plane = in + (size_t)d*NTOT + b*NPIX;
    int tid = threadIdx.x;
    if (tid < 9) wsm[tid] = wt[d*9 + tid];
    for (int i = tid; i < 34*34; i += 256) {
        int y = i/34, x = i - y*34;
        int yy = y - 1, xx = x - 1;
        sm[y][x] = (yy>=0 && yy<32 && xx>=0 && xx<32) ? plane[yy*32+xx] : 0.f;
    }
    __syncthreads();
    int y  = tid >> 3;
    int x0 = (tid & 7) << 2;
    float a0 = 0.f, a1 = 0.f, a2 = 0.f, a3 = 0.f;
    #pragma unroll
    for (int ky = 0; ky < 3; ky++) {
        float r[6];
        #pragma unroll
        for (int i = 0; i < 6; i++) r[i] = sm[y+ky][x0+i];
        #pragma unroll
        for (int kx = 0; kx < 3; kx++) {
            float wv = wsm[ky*3+kx];
            a0 = fmaf(r[kx],   wv, a0);
            a1 = fmaf(r[kx+1], wv, a1);
            a2 = fmaf(r[kx+2], wv, a2);
            a3 = fmaf(r[kx+3], wv, a3);
        }
    }
    float z0 = (a0 > 0.f) ? a0*a0 : 0.f;
    float z1 = (a1 > 0.f) ? a1*a1 : 0.f;
    float z2 = (a2 > 0.f) ? a2*a2 : 0.f;
    float z3 = (a3 > 0.f) ? a3*a3 : 0.f;
    *(float4*)(out + (size_t)d*NTOT + b*NPIX + (y << 5) + x0) =
        make_float4(z0, z1, z2, z3);
}

// ------------------------------ scan ---------------------------------------
__global__ void scan_kernel(const __nv_bfloat16* __restrict__ gsig,
                            const float* __restrict__ glud,
                            const float* __restrict__ x2,
                            const float* __restrict__ x2t,
                            const float* __restrict__ mw,
                            float* __restrict__ s4) {
    int c4 = blockIdx.x, b = blockIdx.y;
    int k = c4 / Dch, d = c4 - k*Dch;
    int tid = threadIdx.x;
    int chunk = tid >> 5, h = tid & 31;
    const size_t PS = (size_t)C4 * NTOT;
    const __nv_bfloat16* Gl = gsig + (size_t)c4*NTOT + (size_t)b*NPIX;
    const __nv_bfloat16* Gm = Gl + PS;
    const __nv_bfloat16* Gr = Gl + 2*PS;
    const float* Lp = glud + (size_t)c4*NTOT + (size_t)b*NPIX;
    const float* Up = Lp + PS;
    const float* Dp = Lp + 2*PS;
    const float* xsrc = ((k & 1) ? x2 : x2t) + (size_t)d*NTOT + b*NPIX;
    float mk = mw[k];
    float* outp = s4 + (size_t)c4*NTOT + b*NPIX;
    float hs = 0.f;
    const unsigned mask = 0xFFFFFFFFu;
    #pragma unroll
    for (int pos = 0; pos < 8; pos++) {
        int w  = chunk*8 + pos;
        int q  = w*32 + h;
        int wq = (k >= 2) ? (31 - w) : w;
        float xv = xsrc[wq*32 + h];
        float a  = __bfloat162float(Gl[q]);
        float bb = __bfloat162float(Gm[q]);
        float cc = __bfloat162float(Gr[q]);
        float l  = Lp[q];
        float ea = fast_exp(a), eb = fast_exp(bb), ec = fast_exp(cc);
        float qa = 1.f + ea, qb = 1.f + eb, qc = 1.f + ec;
        float pl = ea*qb*qc, pm = eb*qa*qc, pr = ec*qa*qb;
        float den = pl + pm + pr;
        if (h == 0)  den = pm + pr;
        if (h == 31) den = pl + pm;
        float rd = fast_rcp(den);
        float gl = pl*rd, gm = pm*rd, gr = pr*rd;
        float up = __shfl_up_sync(mask, hs, 1);
        float dn = __shfl_down_sync(mask, hs, 1);
        if (h == 0)  up = 0.f;
        if (h == 31) dn = 0.f;
        hs = fmaf(l, xv, fmaf(gl, up, fmaf(gm, hs, gr*dn)));
        outp[q] = mk * fmaf(hs, Up[q], xv*Dp[q]);
    }
}

// ------------------------------ merge + transpose + bf16 split -------------
__global__ void merge_split_kernel(const float* __restrict__ s4,
                                   __nv_bfloat16* __restrict__ dh,
                                   __nv_bfloat16* __restrict__ dl) {
    __shared__ float sm[32][33];
    int d0 = blockIdx.x << 5, b = blockIdx.y;
    int tx = threadIdx.x, ty = threadIdx.y;
    for (int pg = blockIdx.z * 8; pg < blockIdx.z * 8 + 8; pg++) {
        int q = (pg << 5) + tx;
        float v = 0.f;
        #pragma unroll
        for (int k = 0; k < 4; k++)
            v += s4[(size_t)(k*Dch + d0 + ty)*NTOT + b*NPIX + q];
        sm[ty][tx] = v;
        __syncthreads();
        float y = sm[tx][ty];
        __nv_bfloat16 hh = __float2bfloat16(y);
        size_t o = (size_t)(b*NPIX + (ty << 5) + pg) * Dch + d0 + tx;
        dh[o] = hh;
        dl[o] = __float2bfloat16(y - __bfloat162float(hh));
        __syncthreads();
    }
}

// ------------------------------ launch -------------------------------------
extern "C" void kernel_launch(void* const* d_in, const int* in_sizes, int n_in,
                              void* d_out, int out_size) {
    const float* hidden   = (const float*)d_in[0];
    const float* norm_w   = (const float*)d_in[1];
    const float* norm_b   = (const float*)d_in[2];
    const float* in_proj  = (const float*)d_in[3];
    const float* conv7_w  = (const float*)d_in[4];
    const float* conv7_b  = (const float*)d_in[5];
    const float* xdown_w  = (const float*)d_in[6];
    const float* wup_w    = (const float*)d_in[7];
    const float* lup_w    = (const float*)d_in[8];
    const float* uup_w    = (const float*)d_in[9];
    const float* dcoef_w  = (const float*)d_in[10];
    const float* m_w      = (const float*)d_in[11];
    const float* outconv_w  = (const float*)d_in[12];
    const float* outdconv_w = (const float*)d_in[13];
    const float* outproj_w  = (const float*)d_in[14];
    float* outp = (float*)d_out;

    float *x1,*x2,*x2t,*glud,*s4,*oc,*act;
    __nv_bfloat16 *gsig,*xlnh,*xlnl,*wih,*wil,*woh,*wol,*wph,*wpl,*gwh,*gwl,
                  *xpnh,*xpnl,*mnh,*mnl,*anh,*anl;
    cudaGetSymbolAddress((void**)&x1, g_x1);   cudaGetSymbolAddress((void**)&x2, g_x2);
    cudaGetSymbolAddress((void**)&x2t,g_x2t);
    cudaGetSymbolAddress((void**)&gsig,g_gsig);cudaGetSymbolAddress((void**)&glud,g_glud);
    cudaGetSymbolAddress((void**)&s4, g_s4);   cudaGetSymbolAddress((void**)&oc, g_oc);
    cudaGetSymbolAddress((void**)&act,g_act);
    cudaGetSymbolAddress((void**)&xlnh,g_xlnh);cudaGetSymbolAddress((void**)&xlnl,g_xlnl);
    cudaGetSymbolAddress((void**)&wih,g_wih);  cudaGetSymbolAddress((void**)&wil,g_wil);
    cudaGetSymbolAddress((void**)&woh,g_woh);  cudaGetSymbolAddress((void**)&wol,g_wol);
    cudaGetSymbolAddress((void**)&wph,g_wph);  cudaGetSymbolAddress((void**)&wpl,g_wpl);
    cudaGetSymbolAddress((void**)&gwh,g_gwh);  cudaGetSymbolAddress((void**)&gwl,g_gwl);
    cudaGetSymbolAddress((void**)&xpnh,g_xpnh);cudaGetSymbolAddress((void**)&xpnl,g_xpnl);
    cudaGetSymbolAddress((void**)&mnh,g_mnh);  cudaGetSymbolAddress((void**)&mnl,g_mnl);
    cudaGetSymbolAddress((void**)&anh,g_anh);  cudaGetSymbolAddress((void**)&anl,g_anl);

    const int SMEM_TM64_3  = 3 * 24576;   // 72KB  (3 CTA/SM)
    const int SMEM_TM128_3 = 3 * 32768;   // 96KB  (2 CTA/SM)
    const int SMEM_TM128_1 = 3 * 16384;   // 48KB
    cudaFuncSetAttribute(mma_gemm<3,0,64,3>,  cudaFuncAttributeMaxDynamicSharedMemorySize, SMEM_TM64_3);
    cudaFuncSetAttribute(mma_gemm<3,0,128,2>, cudaFuncAttributeMaxDynamicSharedMemorySize, SMEM_TM128_3);
    cudaFuncSetAttribute(mma_gemm<1,1,128,2>, cudaFuncAttributeMaxDynamicSharedMemorySize, SMEM_TM128_1);
    dim3 b3232(32, 32);

    // 1) batched weight splits
    wsplit_all_kernel<<<(4*WSEG_BIG + 3*WSEG_SMALL)/256, 256>>>(
        in_proj, outconv_w, outproj_w, wup_w, lup_w, uup_w, dcoef_w,
        wih, wil, woh, wol, wph, wpl, gwh, gwl);

    // 2) LN -> bf16 hi/lo
    ln_split_kernel<<<NTOT/8, 256>>>(hidden, norm_w, norm_b, xlnh, xlnl);

    // 3) shortcut copy (keeps in_proj as profiled launch #4)
    copy_kernel<<<BTD/1024, 256>>>((const float4*)hidden, (float4*)(outp + BTD));

    // 4) in_proj (TM=64, grid 384)   <-- profiled launch
    mma_gemm<3,0,64,3><<<dim3(NTOT/128, Dch/64), 256, SMEM_TM64_3>>>(
        wih, wil, xlnh, xlnl, x1, nullptr, Dch, NTOT);

    // 5) dw 7x7 (+ fused w-major transpose)
    dw7_kernel<<<dim3(Dch, Bsz), 256>>>(x1, conv7_w, conv7_b, x2, x2t);

    // 6) xdown + fused remap/split -> xpn hi/lo
    xdown_kernel<<<dim3(NTOT/64, 1), 256>>>(xdown_w, x2, xpnh, xpnl);

    // 7) sigmoid gates: 1-pass bf16 out (TM=128, grid 2304)
    mma_gemm<1,1,128,2><<<dim3(NTOT/128, (3*C4)/128), 256, SMEM_TM128_1>>>(
        gwh, nullptr, xpnh, nullptr, nullptr, gsig, 64, NTOT);

    // 8) L|U|D: 3-pass fp32 out (TM=128, grid 2304)
    mma_gemm<3,0,128,2><<<dim3(NTOT/128, (3*C4)/128), 256, SMEM_TM128_3>>>(
        gwh + (size_t)3*C4*64, gwl + (size_t)3*C4*64, xpnh, xpnl,
        glud, nullptr, 64, NTOT);

    // 9) scan
    scan_kernel<<<dim3(C4, Bsz), 128>>>(gsig, glud, x2, x2t, m_w, s4);

    // 10) merge + transpose + split -> mn hi/lo
    merge_split_kernel<<<dim3(Dch/32, Bsz, 4), b3232>>>(s4, mnh, mnl);

    // 11) outconv (TM=64, grid 384)
    mma_gemm<3,0,64,3><<<dim3(NTOT/128, Dch/64), 256, SMEM_TM64_3>>>(
        woh, wol, mnh, mnl, oc, nullptr, Dch, NTOT);

    // 12) dw 3x3 + y*relu(y)
    dw3act_kernel<<<dim3(Dch, Bsz), 256>>>(oc, outdconv_w, act);

    // 13) act -> (4096x768) hi/lo
    tconv_kernel<<<dim3(NTOT/32, Dch/32), b3232>>>(act, anh, anl);

    // 14) outproj -> d_out (TM=64, grid 384)
    mma_gemm<3,0,64,3><<<dim3(Dch/128, NTOT/64), 256, SMEM_TM64_3>>>(
        anh, anl, wph, wpl, outp, nullptr, Dch, Dch);
}